// round 9
// baseline (speedup 1.0000x reference)
#include <cuda_runtime.h>
#include <cuda_bf16.h>
#include <math.h>
#include <stdint.h>

// ---------------- problem constants ----------------
#define BATCH   2
#define NQ      4096
#define NCTX    4096
#define DIMC    512
#define HEADS   8
#define DH      64
#define INNER   512
#define MK      4097         // keys incl. null
#define MKP     4160         // padded V^T stride (covers 65*64 tail, zeros in pad)
#define SQSCALE 0.35355339059327373f   // sqrt(64^-0.5)
#define SPIT    72           // smem pitch (bf16 elems) = 144B

// ---------------- scratch ----------------------------------------------------
__device__ float g_pj[(size_t)BATCH * NQ * DIMC];

// pre-split activations (bf16 hi/lo), row-major [8192][512]
__device__ __nv_bfloat16 g_xnh[(size_t)BATCH * NQ * DIMC], g_xnl[(size_t)BATCH * NQ * DIMC];
__device__ __nv_bfloat16 g_cxh[(size_t)BATCH * NCTX * DIMC], g_cxl[(size_t)BATCH * NCTX * DIMC];
__device__ __nv_bfloat16 g_aoh[(size_t)BATCH * NQ * INNER], g_aol[(size_t)BATCH * NQ * INNER];

__device__ __nv_bfloat16 g_qh[(size_t)BATCH * HEADS * NQ * DH];
__device__ __nv_bfloat16 g_ql[(size_t)BATCH * HEADS * NQ * DH];
__device__ __nv_bfloat16 g_kh[(size_t)BATCH * HEADS * MK * DH];
__device__ __nv_bfloat16 g_kl[(size_t)BATCH * HEADS * MK * DH];
__device__ __nv_bfloat16 g_vth[(size_t)BATCH * HEADS * DH * MKP];  // [bh][d][key]
__device__ __nv_bfloat16 g_vtl[(size_t)BATCH * HEADS * DH * MKP];

// transposed/split weights: Wt[n][k], k = 512
__device__ __nv_bfloat16 g_wqh[512 * 512],  g_wql[512 * 512];
__device__ __nv_bfloat16 g_wkvh[1024 * 512], g_wkvl[1024 * 512];
__device__ __nv_bfloat16 g_woh[512 * 512],  g_wol[512 * 512];

// ---------------- helpers -----------------------------------------------------
__device__ __forceinline__ void bsplit(float v, __nv_bfloat16* hi, __nv_bfloat16* lo) {
    __nv_bfloat16 h = __float2bfloat16(v);
    *hi = h;
    *lo = __float2bfloat16(v - __bfloat162float(h));
}
__device__ __forceinline__ uint32_t pack_bf16x2(float lo_elem, float hi_elem) {
    uint32_t r;
    asm("cvt.rn.bf16x2.f32 %0, %1, %2;" : "=r"(r) : "f"(hi_elem), "f"(lo_elem));
    return r;
}
__device__ __forceinline__ void mma16816(float* d, const uint32_t* a, uint32_t b0, uint32_t b1) {
    asm volatile("mma.sync.aligned.m16n8k16.row.col.f32.bf16.bf16.f32 "
        "{%0,%1,%2,%3}, {%4,%5,%6,%7}, {%8,%9}, {%0,%1,%2,%3};"
        : "+f"(d[0]), "+f"(d[1]), "+f"(d[2]), "+f"(d[3])
        : "r"(a[0]), "r"(a[1]), "r"(a[2]), "r"(a[3]), "r"(b0), "r"(b1));
}
__device__ __forceinline__ void ldsm_x4(uint32_t* r, uint32_t addr) {
    asm volatile("ldmatrix.sync.aligned.m8n8.x4.shared.b16 {%0,%1,%2,%3}, [%4];"
        : "=r"(r[0]), "=r"(r[1]), "=r"(r[2]), "=r"(r[3]) : "r"(addr));
}
__device__ __forceinline__ void cp16(uint32_t dst, const void* src) {
    asm volatile("cp.async.cg.shared.global [%0], [%1], 16;"
        :: "r"(dst), "l"(src) : "memory");
}
__device__ __forceinline__ void cp16z(uint32_t dst, const void* src, int ok) {
    int sz = ok ? 16 : 0;
    asm volatile("cp.async.cg.shared.global [%0], [%1], 16, %2;"
        :: "r"(dst), "l"(src), "r"(sz) : "memory");
}
#define CP_COMMIT() asm volatile("cp.async.commit_group;" ::: "memory")
#define CP_WAIT0()  asm volatile("cp.async.wait_group 0;" ::: "memory")

// ---------------- layernorm --------------------------------------------------
// WHICH==0: reads inp, writes split bf16 to g_xnh/g_xnl
// WHICH==1: reads g_pj, writes fp32 outp
template <int WHICH>
__global__ void __launch_bounds__(128) ln_kernel(const float* __restrict__ inp,
                                                 const float* __restrict__ g,
                                                 float* __restrict__ outp)
{
    const float* in = (WHICH == 0) ? inp : g_pj;
    int row = blockIdx.x;
    int tid = threadIdx.x;
    const float* rptr = in + (size_t)row * DIMC;

    float4 v = reinterpret_cast<const float4*>(rptr)[tid];
    float s  = v.x + v.y + v.z + v.w;
    float ss = v.x * v.x + v.y * v.y + v.z * v.z + v.w * v.w;
    #pragma unroll
    for (int o = 16; o > 0; o >>= 1) {
        s  += __shfl_down_sync(0xffffffffu, s,  o);
        ss += __shfl_down_sync(0xffffffffu, ss, o);
    }
    __shared__ float sb[8];
    int wid = tid >> 5, lane = tid & 31;
    if (lane == 0) { sb[wid] = s; sb[4 + wid] = ss; }
    __syncthreads();
    float S  = sb[0] + sb[1] + sb[2] + sb[3];
    float SS = sb[4] + sb[5] + sb[6] + sb[7];
    float mean = S * (1.0f / DIMC);
    float var  = SS * (1.0f / DIMC) - mean * mean;
    float rstd = rsqrtf(var + 1e-5f);
    float4 gv = reinterpret_cast<const float4*>(g)[tid];
    float o0 = (v.x - mean) * rstd * gv.x;
    float o1 = (v.y - mean) * rstd * gv.y;
    float o2 = (v.z - mean) * rstd * gv.z;
    float o3 = (v.w - mean) * rstd * gv.w;
    if (WHICH == 0) {
        size_t base = (size_t)row * DIMC + tid * 4;
        bsplit(o0, &g_xnh[base],     &g_xnl[base]);
        bsplit(o1, &g_xnh[base + 1], &g_xnl[base + 1]);
        bsplit(o2, &g_xnh[base + 2], &g_xnl[base + 2]);
        bsplit(o3, &g_xnh[base + 3], &g_xnl[base + 3]);
    } else {
        float4 o4 = make_float4(o0, o1, o2, o3);
        reinterpret_cast<float4*>(outp + (size_t)row * DIMC)[tid] = o4;
    }
}

// ---------------- context split (fp32 -> bf16 hi/lo) -------------------------
__global__ void __launch_bounds__(256) csplit_kernel(const float* __restrict__ src)
{
    size_t i4 = ((size_t)blockIdx.x * 256 + threadIdx.x);
    float4 v = reinterpret_cast<const float4*>(src)[i4];
    size_t base = i4 * 4;
    bsplit(v.x, &g_cxh[base],     &g_cxl[base]);
    bsplit(v.y, &g_cxh[base + 1], &g_cxl[base + 1]);
    bsplit(v.z, &g_cxh[base + 2], &g_cxl[base + 2]);
    bsplit(v.w, &g_cxh[base + 3], &g_cxl[base + 3]);
}

// ---------------- null kv fill -----------------------------------------------
__global__ void null_fill_kernel(const float* __restrict__ null_kv)
{
    int bh = blockIdx.x;
    int d  = threadIdx.x;
    size_t kidx = (size_t)bh * MK * DH + d;
    bsplit(null_kv[d] * SQSCALE, &g_kh[kidx], &g_kl[kidx]);
    size_t vidx = ((size_t)bh * DH + d) * MKP + 0;
    bsplit(null_kv[DH + d], &g_vth[vidx], &g_vtl[vidx]);
}

// ---------------- weight transpose + split: Wt[n][k] -------------------------
__global__ void __launch_bounds__(256) wsplit_kernel(const float* __restrict__ W,
                                                     __nv_bfloat16* __restrict__ Th,
                                                     __nv_bfloat16* __restrict__ Tl,
                                                     int N)
{
    __shared__ float s[64][65];
    int tid = threadIdx.x;
    int n0 = blockIdx.x * 64;
    int k0 = blockIdx.y * 64;
    #pragma unroll
    for (int i = 0; i < 16; i++) {
        int idx = tid + i * 256;
        int k = idx >> 6, n = idx & 63;
        s[k][n] = W[(size_t)(k0 + k) * N + n0 + n];
    }
    __syncthreads();
    #pragma unroll
    for (int i = 0; i < 16; i++) {
        int idx = tid + i * 256;
        int n = idx >> 6, k = idx & 63;
        size_t o = (size_t)(n0 + n) * 512 + k0 + k;
        bsplit(s[k][n], &Th[o], &Tl[o]);
    }
}

// ---------------- tensor-core projection GEMM: bf16 A, cp.async 2-buffer -----
// buffer parts: 0=Ah 1=Al 2=Bh 3=Bl, each 9216B; BUFSZ 36864, x2 = 73728B dyn smem
#define PBUF 36864
template <int MODE>
__global__ void __launch_bounds__(128) proj_mma_kernel(const __nv_bfloat16* __restrict__ Ath,
                                                       const __nv_bfloat16* __restrict__ Atl,
                                                       const __nv_bfloat16* __restrict__ Wth,
                                                       const __nv_bfloat16* __restrict__ Wtl)
{
    extern __shared__ char smc[];
    uint32_t sbase = (uint32_t)__cvta_generic_to_shared(smc);

    int tid  = threadIdx.x;
    int wid  = tid >> 5;
    int lane = tid & 31;
    int g    = lane >> 2;
    int qoff = (lane & 3) << 1;
    int row0 = blockIdx.y * 64;
    int col0 = blockIdx.x * 64;

    int lm = lane >> 3, li = lane & 7;
    uint32_t aoff = (uint32_t)(((wid * 16 + (lm & 1) * 8 + li) * SPIT + (lm >> 1) * 8) * 2);
    uint32_t boff = (uint32_t)((((lm >> 1) * 8 + li) * SPIT + (lm & 1) * 8) * 2);

    auto stage = [&](int k0, int buf) {
        #pragma unroll
        for (int i = 0; i < 16; i++) {
            int idx = tid + i * 128;          // 0..2047
            int part = idx >> 9;              // 0=Ah 1=Al 2=Bh 3=Bl
            int rem = idx & 511;
            int r = rem >> 3, cc = (rem & 7) << 3;
            uint32_t dst = sbase + (uint32_t)(buf * PBUF + part * 9216 + (r * SPIT + cc) * 2);
            const __nv_bfloat16* src;
            if (part == 0)      src = Ath + (size_t)(row0 + r) * 512 + k0 + cc;
            else if (part == 1) src = Atl + (size_t)(row0 + r) * 512 + k0 + cc;
            else if (part == 2) src = Wth + (size_t)(col0 + r) * 512 + k0 + cc;
            else                src = Wtl + (size_t)(col0 + r) * 512 + k0 + cc;
            cp16(dst, src);
        }
    };

    stage(0, 0);
    CP_COMMIT();

    float oacc[8][4] = {};

    for (int kc = 0; kc < 8; kc++) {
        CP_WAIT0();
        __syncthreads();
        if (kc + 1 < 8) { stage((kc + 1) << 6, (kc + 1) & 1); CP_COMMIT(); }

        uint32_t uAh = sbase + (uint32_t)((kc & 1) * PBUF);
        uint32_t uAl = uAh + 9216;
        uint32_t uBh = uAh + 18432;
        uint32_t uBl = uAh + 27648;

        uint32_t afh[4][4], afl[4][4];
        #pragma unroll
        for (int kt = 0; kt < 4; kt++) {
            ldsm_x4(afh[kt], uAh + (uint32_t)(kt * 32) + aoff);
            ldsm_x4(afl[kt], uAl + (uint32_t)(kt * 32) + aoff);
        }

        #pragma unroll
        for (int kt = 0; kt < 4; kt++) {
            #pragma unroll
            for (int ntp = 0; ntp < 4; ntp++) {
                uint32_t off = (uint32_t)(ntp * 16 * SPIT * 2 + kt * 32) + boff;
                uint32_t bhf[4], blf[4];
                ldsm_x4(bhf, uBh + off);
                ldsm_x4(blf, uBl + off);
                mma16816(oacc[2 * ntp],     afh[kt], bhf[0], bhf[1]);
                mma16816(oacc[2 * ntp + 1], afh[kt], bhf[2], bhf[3]);
                mma16816(oacc[2 * ntp],     afl[kt], bhf[0], bhf[1]);
                mma16816(oacc[2 * ntp + 1], afl[kt], bhf[2], bhf[3]);
                mma16816(oacc[2 * ntp],     afh[kt], blf[0], blf[1]);
                mma16816(oacc[2 * ntp + 1], afh[kt], blf[2], blf[3]);
            }
        }
    }

    #pragma unroll
    for (int nt = 0; nt < 8; nt++) {
        #pragma unroll
        for (int half = 0; half < 2; half++) {
            int row = row0 + wid * 16 + g + half * 8;
            float v0 = oacc[nt][half * 2 + 0];
            float v1 = oacc[nt][half * 2 + 1];
            int c = col0 + nt * 8 + qoff;
            if (MODE == 0) {
                int b = row >> 12, n = row & 4095;
                int h = c >> 6, dd = c & 63;
                size_t idx = (((size_t)(b * HEADS + h)) * NQ + n) * DH + dd;
                bsplit(v0 * SQSCALE, &g_qh[idx],     &g_ql[idx]);
                bsplit(v1 * SQSCALE, &g_qh[idx + 1], &g_ql[idx + 1]);
            } else if (MODE == 1) {
                int b = row >> 12, mr = row & 4095;
                if (c < 512) {
                    int h = c >> 6, dd = c & 63;
                    size_t idx = (((size_t)(b * HEADS + h)) * MK + mr + 1) * DH + dd;
                    bsplit(v0 * SQSCALE, &g_kh[idx],     &g_kl[idx]);
                    bsplit(v1 * SQSCALE, &g_kh[idx + 1], &g_kl[idx + 1]);
                } else {
                    int c2 = c - 512;
                    int h = c2 >> 6, dd = c2 & 63;
                    size_t idx = (((size_t)(b * HEADS + h)) * DH + dd) * MKP + (mr + 1);
                    bsplit(v0, &g_vth[idx],       &g_vtl[idx]);
                    bsplit(v1, &g_vth[idx + MKP], &g_vtl[idx + MKP]);
                }
            } else {
                *(float2*)(g_pj + (size_t)row * 512 + c) = make_float2(v0, v1);
            }
        }
    }
}

// ---------------- FA2 attention: 128-row Q tiles, 256 threads -----------------
// buffer parts: Kh(0) Kl(9216) Vh(18432) Vl(27648); BUFSZ 36864, x2; bitmap 544B
#define BUFSZ   36864
#define OFF_BM  73728
#define ATTN_SMEM 74272
#define NCH     65

__global__ void __launch_bounds__(256) attn_mma_kernel(const int* __restrict__ mask)
{
    extern __shared__ char smc[];
    const int tid  = threadIdx.x;
    const int wid  = tid >> 5;          // 0..7
    const int lane = tid & 31;
    const int g    = lane >> 2;
    const int qoff = (lane & 3) << 1;
    const int bh = blockIdx.y;
    const int b = bh >> 3, h = bh & 7;
    const int n0 = blockIdx.x << 7;     // 128-row tiles

    uint32_t sbase = (uint32_t)__cvta_generic_to_shared(smc);
    uint32_t* bmap = (uint32_t*)(smc + OFF_BM);

    for (int w = tid; w < 130; w += 256) {
        uint32_t wv = 0;
        int jb = w * 32;
        #pragma unroll 8
        for (int i = 0; i < 32; i++) {
            int j = jb + i;
            int ok = (j == 0) ? 1 : ((j < MK) ? (mask[b * NCTX + j - 1] != 0) : 0);
            wv |= (uint32_t)ok << i;
        }
        bmap[w] = wv;
    }

    // Q fragments (hi/lo) from gmem — this warp's 16 rows
    uint32_t qfh[4][4], qfl[4][4];
    {
        const __nv_bfloat16* q0h = g_qh + ((size_t)bh * NQ + n0 + wid * 16 + g) * DH;
        const __nv_bfloat16* q0l = g_ql + ((size_t)bh * NQ + n0 + wid * 16 + g) * DH;
        #pragma unroll
        for (int kt = 0; kt < 4; kt++) {
            int d0 = kt * 16 + qoff;
            qfh[kt][0] = *(const uint32_t*)(q0h + d0);
            qfh[kt][1] = *(const uint32_t*)(q0h + 8 * DH + d0);
            qfh[kt][2] = *(const uint32_t*)(q0h + d0 + 8);
            qfh[kt][3] = *(const uint32_t*)(q0h + 8 * DH + d0 + 8);
            qfl[kt][0] = *(const uint32_t*)(q0l + d0);
            qfl[kt][1] = *(const uint32_t*)(q0l + 8 * DH + d0);
            qfl[kt][2] = *(const uint32_t*)(q0l + d0 + 8);
            qfl[kt][3] = *(const uint32_t*)(q0l + 8 * DH + d0 + 8);
        }
    }

    const int lm = lane >> 3, li = lane & 7;
    const uint32_t boff = (uint32_t)((((lm >> 1) * 8 + li) * SPIT + (lm & 1) * 8) * 2);

    auto stage = [&](int c0s, int buf) {
        #pragma unroll
        for (int i = 0; i < 8; i++) {
            int idx = tid + i * 256;          // 0..2047
            int part = idx >> 9;              // 0=Kh 1=Kl 2=Vh 3=Vl
            int rem = idx & 511;
            int r = rem >> 3, cc = (rem & 7) << 3;
            uint32_t dst = sbase + (uint32_t)(buf * BUFSZ + part * 9216 + (r * SPIT + cc) * 2);
            if (part < 2) {
                int j = c0s + r;
                const __nv_bfloat16* ks = ((part & 1) ? g_kl : g_kh)
                    + ((size_t)bh * MK + min(j, MK - 1)) * DH + cc;
                cp16z(dst, ks, j < MK);
            } else {
                const __nv_bfloat16* vs = ((part & 1) ? g_vtl : g_vth)
                    + ((size_t)bh * DH + r) * MKP + c0s + cc;
                cp16(dst, vs);
            }
        }
    };

    stage(0, 0);
    CP_COMMIT();

    float oacc[8][4] = {};
    float sum0 = 0.0f, sum1 = 0.0f;

    for (int ch = 0; ch < NCH; ch++) {
        int c0 = ch << 6;
        CP_WAIT0();
        __syncthreads();
        if (ch + 1 < NCH) { stage((ch + 1) << 6, (ch + 1) & 1); CP_COMMIT(); }

        uint32_t uKh = sbase + (uint32_t)((ch & 1) * BUFSZ);
        uint32_t uKl = uKh + 9216;
        uint32_t uVh = uKh + 18432;
        uint32_t uVl = uKh + 27648;

        float sacc[8][4] = {};
        #pragma unroll
        for (int kt = 0; kt < 4; kt++) {
            #pragma unroll
            for (int ntp = 0; ntp < 4; ntp++) {
                uint32_t off = (uint32_t)(ntp * 16 * SPIT * 2 + kt * 32) + boff;
                uint32_t bhf[4], blf[4];
                ldsm_x4(bhf, uKh + off);
                ldsm_x4(blf, uKl + off);
                mma16816(sacc[2 * ntp],     qfh[kt], bhf[0], bhf[1]);
                mma16816(sacc[2 * ntp + 1], qfh[kt], bhf[2], bhf[3]);
                mma16816(sacc[2 * ntp],     qfl[kt], bhf[0], bhf[1]);
                mma16816(sacc[2 * ntp + 1], qfl[kt], bhf[2], bhf[3]);
                mma16816(sacc[2 * ntp],     qfh[kt], blf[0], blf[1]);
                mma16816(sacc[2 * ntp + 1], qfh[kt], blf[2], blf[3]);
            }
        }

        uint32_t pfh[4][4], pfl[4][4];
        #pragma unroll
        for (int nt = 0; nt < 8; nt++) {
            int j0 = c0 + nt * 8 + qoff;
            uint32_t wb = bmap[j0 >> 5];
            int bi = j0 & 31;
            float m0 = (float)((wb >> bi) & 1u);
            float m1 = (float)((wb >> (bi + 1)) & 1u);
            float p0 = m0 * __expf(fminf(sacc[nt][0], 30.0f));
            float p1 = m1 * __expf(fminf(sacc[nt][1], 30.0f));
            float p2 = m0 * __expf(fminf(sacc[nt][2], 30.0f));
            float p3 = m1 * __expf(fminf(sacc[nt][3], 30.0f));
            sum0 += p0 + p1;
            sum1 += p2 + p3;
            float h0 = __bfloat162float(__float2bfloat16(p0));
            float h1 = __bfloat162float(__float2bfloat16(p1));
            float h2 = __bfloat162float(__float2bfloat16(p2));
            float h3 = __bfloat162float(__float2bfloat16(p3));
            int kt = nt >> 1, hf = (nt & 1) << 1;
            pfh[kt][hf + 0] = pack_bf16x2(h0, h1);
            pfh[kt][hf + 1] = pack_bf16x2(h2, h3);
            pfl[kt][hf + 0] = pack_bf16x2(p0 - h0, p1 - h1);
            pfl[kt][hf + 1] = pack_bf16x2(p2 - h2, p3 - h3);
        }

        #pragma unroll
        for (int kt = 0; kt < 4; kt++) {
            #pragma unroll
            for (int ntp = 0; ntp < 4; ntp++) {
                uint32_t off = (uint32_t)(ntp * 16 * SPIT * 2 + kt * 32) + boff;
                uint32_t vhf[4], vlf[4];
                ldsm_x4(vhf, uVh + off);
                ldsm_x4(vlf, uVl + off);
                mma16816(oacc[2 * ntp],     pfh[kt], vhf[0], vhf[1]);
                mma16816(oacc[2 * ntp + 1], pfh[kt], vhf[2], vhf[3]);
                mma16816(oacc[2 * ntp],     pfl[kt], vhf[0], vhf[1]);
                mma16816(oacc[2 * ntp + 1], pfl[kt], vhf[2], vhf[3]);
                mma16816(oacc[2 * ntp],     pfh[kt], vlf[0], vlf[1]);
                mma16816(oacc[2 * ntp + 1], pfh[kt], vlf[2], vlf[3]);
            }
        }
    }

    sum0 += __shfl_xor_sync(0xffffffffu, sum0, 1);
    sum0 += __shfl_xor_sync(0xffffffffu, sum0, 2);
    sum1 += __shfl_xor_sync(0xffffffffu, sum1, 1);
    sum1 += __shfl_xor_sync(0xffffffffu, sum1, 2);
    float inv0 = 1.0f / sum0;
    float inv1 = 1.0f / sum1;

    // write attention out pre-split (bf16 hi/lo) for the Wo projection
    size_t base0 = ((size_t)(b * NQ) + n0 + wid * 16 + g) * INNER + h * DH;
    size_t base1 = base0 + 8 * INNER;
    #pragma unroll
    for (int nt = 0; nt < 8; nt++) {
        int c = nt * 8 + qoff;
        float v0 = oacc[nt][0] * inv0;
        float v1 = oacc[nt][1] * inv0;
        float v2 = oacc[nt][2] * inv1;
        float v3 = oacc[nt][3] * inv1;
        bsplit(v0, &g_aoh[base0 + c],     &g_aol[base0 + c]);
        bsplit(v1, &g_aoh[base0 + c + 1], &g_aol[base0 + c + 1]);
        bsplit(v2, &g_aoh[base1 + c],     &g_aol[base1 + c]);
        bsplit(v3, &g_aoh[base1 + c + 1], &g_aol[base1 + c + 1]);
    }
}

// ---------------- launch ------------------------------------------------------
extern "C" void kernel_launch(void* const* d_in, const int* in_sizes, int n_in,
                              void* d_out, int out_size)
{
    const float* x       = (const float*)d_in[0];
    const float* context = (const float*)d_in[1];
    const int*   mask    = (const int*)  d_in[2];
    const float* g_x     = (const float*)d_in[3];
    const float* null_kv = (const float*)d_in[4];
    const float* Wq      = (const float*)d_in[5];
    const float* Wkv     = (const float*)d_in[6];
    const float* Wo      = (const float*)d_in[7];
    const float* g_outp  = (const float*)d_in[8];
    float* out = (float*)d_out;
    (void)in_sizes; (void)n_in; (void)out_size;

    __nv_bfloat16 *wqh, *wql, *wkvh, *wkvl, *woh, *wol;
    __nv_bfloat16 *xnh, *xnl, *cxh, *cxl, *aoh, *aol;
    cudaGetSymbolAddress((void**)&wqh,  g_wqh);
    cudaGetSymbolAddress((void**)&wql,  g_wql);
    cudaGetSymbolAddress((void**)&wkvh, g_wkvh);
    cudaGetSymbolAddress((void**)&wkvl, g_wkvl);
    cudaGetSymbolAddress((void**)&woh,  g_woh);
    cudaGetSymbolAddress((void**)&wol,  g_wol);
    cudaGetSymbolAddress((void**)&xnh,  g_xnh);
    cudaGetSymbolAddress((void**)&xnl,  g_xnl);
    cudaGetSymbolAddress((void**)&cxh,  g_cxh);
    cudaGetSymbolAddress((void**)&cxl,  g_cxl);
    cudaGetSymbolAddress((void**)&aoh,  g_aoh);
    cudaGetSymbolAddress((void**)&aol,  g_aol);

    wsplit_kernel<<<dim3(8, 8),  256>>>(Wq,  wqh,  wql,  512);
    wsplit_kernel<<<dim3(16, 8), 256>>>(Wkv, wkvh, wkvl, 1024);
    wsplit_kernel<<<dim3(8, 8),  256>>>(Wo,  woh,  wol,  512);

    csplit_kernel<<<(BATCH * NCTX * DIMC) / 1024, 256>>>(context);
    ln_kernel<0><<<BATCH * NQ, 128>>>(x, g_x, nullptr);

    cudaFuncSetAttribute(proj_mma_kernel<0>, cudaFuncAttributeMaxDynamicSharedMemorySize, 2 * PBUF);
    cudaFuncSetAttribute(proj_mma_kernel<1>, cudaFuncAttributeMaxDynamicSharedMemorySize, 2 * PBUF);
    cudaFuncSetAttribute(proj_mma_kernel<2>, cudaFuncAttributeMaxDynamicSharedMemorySize, 2 * PBUF);

    proj_mma_kernel<0><<<dim3(8, 128),  128, 2 * PBUF>>>(xnh, xnl, wqh, wql);
    proj_mma_kernel<1><<<dim3(16, 128), 128, 2 * PBUF>>>(cxh, cxl, wkvh, wkvl);
    null_fill_kernel<<<BATCH * HEADS, DH>>>(null_kv);

    cudaFuncSetAttribute(attn_mma_kernel, cudaFuncAttributeMaxDynamicSharedMemorySize, ATTN_SMEM);
    attn_mma_kernel<<<dim3(NQ / 128, BATCH * HEADS), 256, ATTN_SMEM>>>(mask);

    proj_mma_kernel<2><<<dim3(8, 128), 128, 2 * PBUF>>>(aoh, aol, woh, wol);
    ln_kernel<1><<<BATCH * NQ, 128>>>(nullptr, g_outp, out);
}

// round 10
// speedup vs baseline: 1.0375x; 1.0375x over previous
#include <cuda_runtime.h>
#include <cuda_bf16.h>
#include <math.h>
#include <stdint.h>

// ---------------- problem constants ----------------
#define BATCH   2
#define NQ      4096
#define NCTX    4096
#define DIMC    512
#define HEADS   8
#define DH      64
#define INNER   512
#define MK      4097         // keys incl. null
#define MKP     4160         // padded V^T stride (covers 65*64 tail, zeros in pad)
#define SQSCALE 0.35355339059327373f   // sqrt(64^-0.5)
#define SPIT    72           // smem pitch (bf16 elems) = 144B

// ---------------- scratch ----------------------------------------------------
__device__ float g_pj[(size_t)BATCH * NQ * DIMC];

// pre-split activations (bf16 hi/lo), row-major [8192][512]
__device__ __nv_bfloat16 g_xnh[(size_t)BATCH * NQ * DIMC], g_xnl[(size_t)BATCH * NQ * DIMC];
__device__ __nv_bfloat16 g_cxh[(size_t)BATCH * NCTX * DIMC], g_cxl[(size_t)BATCH * NCTX * DIMC];
__device__ __nv_bfloat16 g_aoh[(size_t)BATCH * NQ * INNER], g_aol[(size_t)BATCH * NQ * INNER];

__device__ __nv_bfloat16 g_qh[(size_t)BATCH * HEADS * NQ * DH];
__device__ __nv_bfloat16 g_ql[(size_t)BATCH * HEADS * NQ * DH];
__device__ __nv_bfloat16 g_kh[(size_t)BATCH * HEADS * MK * DH];
__device__ __nv_bfloat16 g_kl[(size_t)BATCH * HEADS * MK * DH];
__device__ __nv_bfloat16 g_vth[(size_t)BATCH * HEADS * DH * MKP];  // [bh][d][key]
__device__ __nv_bfloat16 g_vtl[(size_t)BATCH * HEADS * DH * MKP];

// transposed/split weights: Wt[n][k], k = 512
__device__ __nv_bfloat16 g_wqh[512 * 512],  g_wql[512 * 512];
__device__ __nv_bfloat16 g_wkvh[1024 * 512], g_wkvl[1024 * 512];
__device__ __nv_bfloat16 g_woh[512 * 512],  g_wol[512 * 512];

// ---------------- helpers -----------------------------------------------------
__device__ __forceinline__ void bsplit(float v, __nv_bfloat16* hi, __nv_bfloat16* lo) {
    __nv_bfloat16 h = __float2bfloat16(v);
    *hi = h;
    *lo = __float2bfloat16(v - __bfloat162float(h));
}
__device__ __forceinline__ uint32_t pack_bf16x2(float lo_elem, float hi_elem) {
    uint32_t r;
    asm("cvt.rn.bf16x2.f32 %0, %1, %2;" : "=r"(r) : "f"(hi_elem), "f"(lo_elem));
    return r;
}
__device__ __forceinline__ void mma16816(float* d, const uint32_t* a, uint32_t b0, uint32_t b1) {
    asm volatile("mma.sync.aligned.m16n8k16.row.col.f32.bf16.bf16.f32 "
        "{%0,%1,%2,%3}, {%4,%5,%6,%7}, {%8,%9}, {%0,%1,%2,%3};"
        : "+f"(d[0]), "+f"(d[1]), "+f"(d[2]), "+f"(d[3])
        : "r"(a[0]), "r"(a[1]), "r"(a[2]), "r"(a[3]), "r"(b0), "r"(b1));
}
__device__ __forceinline__ void ldsm_x4(uint32_t* r, uint32_t addr) {
    asm volatile("ldmatrix.sync.aligned.m8n8.x4.shared.b16 {%0,%1,%2,%3}, [%4];"
        : "=r"(r[0]), "=r"(r[1]), "=r"(r[2]), "=r"(r[3]) : "r"(addr));
}
__device__ __forceinline__ void cp16(uint32_t dst, const void* src) {
    asm volatile("cp.async.cg.shared.global [%0], [%1], 16;"
        :: "r"(dst), "l"(src) : "memory");
}
__device__ __forceinline__ void cp16z(uint32_t dst, const void* src, int ok) {
    int sz = ok ? 16 : 0;
    asm volatile("cp.async.cg.shared.global [%0], [%1], 16, %2;"
        :: "r"(dst), "l"(src), "r"(sz) : "memory");
}
#define CP_COMMIT() asm volatile("cp.async.commit_group;" ::: "memory")
#define CP_WAIT0()  asm volatile("cp.async.wait_group 0;" ::: "memory")

// ---------------- layernorm --------------------------------------------------
template <int WHICH>
__global__ void __launch_bounds__(128) ln_kernel(const float* __restrict__ inp,
                                                 const float* __restrict__ g,
                                                 float* __restrict__ outp)
{
    const float* in = (WHICH == 0) ? inp : g_pj;
    int row = blockIdx.x;
    int tid = threadIdx.x;
    const float* rptr = in + (size_t)row * DIMC;

    float4 v = reinterpret_cast<const float4*>(rptr)[tid];
    float s  = v.x + v.y + v.z + v.w;
    float ss = v.x * v.x + v.y * v.y + v.z * v.z + v.w * v.w;
    #pragma unroll
    for (int o = 16; o > 0; o >>= 1) {
        s  += __shfl_down_sync(0xffffffffu, s,  o);
        ss += __shfl_down_sync(0xffffffffu, ss, o);
    }
    __shared__ float sb[8];
    int wid = tid >> 5, lane = tid & 31;
    if (lane == 0) { sb[wid] = s; sb[4 + wid] = ss; }
    __syncthreads();
    float S  = sb[0] + sb[1] + sb[2] + sb[3];
    float SS = sb[4] + sb[5] + sb[6] + sb[7];
    float mean = S * (1.0f / DIMC);
    float var  = SS * (1.0f / DIMC) - mean * mean;
    float rstd = rsqrtf(var + 1e-5f);
    float4 gv = reinterpret_cast<const float4*>(g)[tid];
    float o0 = (v.x - mean) * rstd * gv.x;
    float o1 = (v.y - mean) * rstd * gv.y;
    float o2 = (v.z - mean) * rstd * gv.z;
    float o3 = (v.w - mean) * rstd * gv.w;
    if (WHICH == 0) {
        size_t base = (size_t)row * DIMC + tid * 4;
        bsplit(o0, &g_xnh[base],     &g_xnl[base]);
        bsplit(o1, &g_xnh[base + 1], &g_xnl[base + 1]);
        bsplit(o2, &g_xnh[base + 2], &g_xnl[base + 2]);
        bsplit(o3, &g_xnh[base + 3], &g_xnl[base + 3]);
    } else {
        float4 o4 = make_float4(o0, o1, o2, o3);
        reinterpret_cast<float4*>(outp + (size_t)row * DIMC)[tid] = o4;
    }
}

// ---------------- context split (fp32 -> bf16 hi/lo) -------------------------
__global__ void __launch_bounds__(256) csplit_kernel(const float* __restrict__ src)
{
    size_t i4 = ((size_t)blockIdx.x * 256 + threadIdx.x);
    float4 v = reinterpret_cast<const float4*>(src)[i4];
    size_t base = i4 * 4;
    bsplit(v.x, &g_cxh[base],     &g_cxl[base]);
    bsplit(v.y, &g_cxh[base + 1], &g_cxl[base + 1]);
    bsplit(v.z, &g_cxh[base + 2], &g_cxl[base + 2]);
    bsplit(v.w, &g_cxh[base + 3], &g_cxl[base + 3]);
}

// ---------------- null kv fill -----------------------------------------------
__global__ void null_fill_kernel(const float* __restrict__ null_kv)
{
    int bh = blockIdx.x;
    int d  = threadIdx.x;
    size_t kidx = (size_t)bh * MK * DH + d;
    bsplit(null_kv[d] * SQSCALE, &g_kh[kidx], &g_kl[kidx]);
    size_t vidx = ((size_t)bh * DH + d) * MKP + 0;
    bsplit(null_kv[DH + d], &g_vth[vidx], &g_vtl[vidx]);
}

// ---------------- weight transpose + split: Wt[n][k] -------------------------
__global__ void __launch_bounds__(256) wsplit_kernel(const float* __restrict__ W,
                                                     __nv_bfloat16* __restrict__ Th,
                                                     __nv_bfloat16* __restrict__ Tl,
                                                     int N)
{
    __shared__ float s[64][65];
    int tid = threadIdx.x;
    int n0 = blockIdx.x * 64;
    int k0 = blockIdx.y * 64;
    #pragma unroll
    for (int i = 0; i < 16; i++) {
        int idx = tid + i * 256;
        int k = idx >> 6, n = idx & 63;
        s[k][n] = W[(size_t)(k0 + k) * N + n0 + n];
    }
    __syncthreads();
    #pragma unroll
    for (int i = 0; i < 16; i++) {
        int idx = tid + i * 256;
        int n = idx >> 6, k = idx & 63;
        size_t o = (size_t)(n0 + n) * 512 + k0 + k;
        bsplit(s[k][n], &Th[o], &Tl[o]);
    }
}

// ---------------- tensor-core projection GEMM: bf16 A, cp.async 2-buffer -----
#define PBUF 36864
template <int MODE>
__global__ void __launch_bounds__(128) proj_mma_kernel(const __nv_bfloat16* __restrict__ Ath,
                                                       const __nv_bfloat16* __restrict__ Atl,
                                                       const __nv_bfloat16* __restrict__ Wth,
                                                       const __nv_bfloat16* __restrict__ Wtl)
{
    extern __shared__ char smc[];
    uint32_t sbase = (uint32_t)__cvta_generic_to_shared(smc);

    int tid  = threadIdx.x;
    int wid  = tid >> 5;
    int lane = tid & 31;
    int g    = lane >> 2;
    int qoff = (lane & 3) << 1;
    int row0 = blockIdx.y * 64;
    int col0 = blockIdx.x * 64;

    int lm = lane >> 3, li = lane & 7;
    uint32_t aoff = (uint32_t)(((wid * 16 + (lm & 1) * 8 + li) * SPIT + (lm >> 1) * 8) * 2);
    uint32_t boff = (uint32_t)((((lm >> 1) * 8 + li) * SPIT + (lm & 1) * 8) * 2);

    auto stage = [&](int k0, int buf) {
        #pragma unroll
        for (int i = 0; i < 16; i++) {
            int idx = tid + i * 128;          // 0..2047
            int part = idx >> 9;              // 0=Ah 1=Al 2=Bh 3=Bl
            int rem = idx & 511;
            int r = rem >> 3, cc = (rem & 7) << 3;
            uint32_t dst = sbase + (uint32_t)(buf * PBUF + part * 9216 + (r * SPIT + cc) * 2);
            const __nv_bfloat16* src;
            if (part == 0)      src = Ath + (size_t)(row0 + r) * 512 + k0 + cc;
            else if (part == 1) src = Atl + (size_t)(row0 + r) * 512 + k0 + cc;
            else if (part == 2) src = Wth + (size_t)(col0 + r) * 512 + k0 + cc;
            else                src = Wtl + (size_t)(col0 + r) * 512 + k0 + cc;
            cp16(dst, src);
        }
    };

    stage(0, 0);
    CP_COMMIT();

    float oacc[8][4] = {};

    for (int kc = 0; kc < 8; kc++) {
        CP_WAIT0();
        __syncthreads();
        if (kc + 1 < 8) { stage((kc + 1) << 6, (kc + 1) & 1); CP_COMMIT(); }

        uint32_t uAh = sbase + (uint32_t)((kc & 1) * PBUF);
        uint32_t uAl = uAh + 9216;
        uint32_t uBh = uAh + 18432;
        uint32_t uBl = uAh + 27648;

        uint32_t afh[4][4], afl[4][4];
        #pragma unroll
        for (int kt = 0; kt < 4; kt++) {
            ldsm_x4(afh[kt], uAh + (uint32_t)(kt * 32) + aoff);
            ldsm_x4(afl[kt], uAl + (uint32_t)(kt * 32) + aoff);
        }

        #pragma unroll
        for (int kt = 0; kt < 4; kt++) {
            #pragma unroll
            for (int ntp = 0; ntp < 4; ntp++) {
                uint32_t off = (uint32_t)(ntp * 16 * SPIT * 2 + kt * 32) + boff;
                uint32_t bhf[4], blf[4];
                ldsm_x4(bhf, uBh + off);
                ldsm_x4(blf, uBl + off);
                mma16816(oacc[2 * ntp],     afh[kt], bhf[0], bhf[1]);
                mma16816(oacc[2 * ntp + 1], afh[kt], bhf[2], bhf[3]);
                mma16816(oacc[2 * ntp],     afl[kt], bhf[0], bhf[1]);
                mma16816(oacc[2 * ntp + 1], afl[kt], bhf[2], bhf[3]);
                mma16816(oacc[2 * ntp],     afh[kt], blf[0], blf[1]);
                mma16816(oacc[2 * ntp + 1], afh[kt], blf[2], blf[3]);
            }
        }
    }

    #pragma unroll
    for (int nt = 0; nt < 8; nt++) {
        #pragma unroll
        for (int half = 0; half < 2; half++) {
            int row = row0 + wid * 16 + g + half * 8;
            float v0 = oacc[nt][half * 2 + 0];
            float v1 = oacc[nt][half * 2 + 1];
            int c = col0 + nt * 8 + qoff;
            if (MODE == 0) {
                int b = row >> 12, n = row & 4095;
                int h = c >> 6, dd = c & 63;
                size_t idx = (((size_t)(b * HEADS + h)) * NQ + n) * DH + dd;
                bsplit(v0 * SQSCALE, &g_qh[idx],     &g_ql[idx]);
                bsplit(v1 * SQSCALE, &g_qh[idx + 1], &g_ql[idx + 1]);
            } else if (MODE == 1) {
                int b = row >> 12, mr = row & 4095;
                if (c < 512) {
                    int h = c >> 6, dd = c & 63;
                    size_t idx = (((size_t)(b * HEADS + h)) * MK + mr + 1) * DH + dd;
                    bsplit(v0 * SQSCALE, &g_kh[idx],     &g_kl[idx]);
                    bsplit(v1 * SQSCALE, &g_kh[idx + 1], &g_kl[idx + 1]);
                } else {
                    int c2 = c - 512;
                    int h = c2 >> 6, dd = c2 & 63;
                    size_t idx = (((size_t)(b * HEADS + h)) * DH + dd) * MKP + (mr + 1);
                    bsplit(v0, &g_vth[idx],       &g_vtl[idx]);
                    bsplit(v1, &g_vth[idx + MKP], &g_vtl[idx + MKP]);
                }
            } else {
                *(float2*)(g_pj + (size_t)row * 512 + c) = make_float2(v0, v1);
            }
        }
    }
}

// ---------------- FA2 attention: 64-row Q tiles, 128 threads (R8 config) ------
#define BUFSZ   36864
#define OFF_BM  73728
#define ATTN_SMEM 74272
#define NCH     65

__global__ void __launch_bounds__(128) attn_mma_kernel(const int* __restrict__ mask)
{
    extern __shared__ char smc[];
    const int tid  = threadIdx.x;
    const int wid  = tid >> 5;          // 0..3
    const int lane = tid & 31;
    const int g    = lane >> 2;
    const int qoff = (lane & 3) << 1;
    const int bh = blockIdx.y;
    const int b = bh >> 3, h = bh & 7;
    const int n0 = blockIdx.x << 6;     // 64-row tiles

    uint32_t sbase = (uint32_t)__cvta_generic_to_shared(smc);
    uint32_t* bmap = (uint32_t*)(smc + OFF_BM);

    for (int w = tid; w < 130; w += 128) {
        uint32_t wv = 0;
        int jb = w * 32;
        #pragma unroll 8
        for (int i = 0; i < 32; i++) {
            int j = jb + i;
            int ok = (j == 0) ? 1 : ((j < MK) ? (mask[b * NCTX + j - 1] != 0) : 0);
            wv |= (uint32_t)ok << i;
        }
        bmap[w] = wv;
    }

    // Q fragments (hi/lo) from gmem — this warp's 16 rows
    uint32_t qfh[4][4], qfl[4][4];
    {
        const __nv_bfloat16* q0h = g_qh + ((size_t)bh * NQ + n0 + wid * 16 + g) * DH;
        const __nv_bfloat16* q0l = g_ql + ((size_t)bh * NQ + n0 + wid * 16 + g) * DH;
        #pragma unroll
        for (int kt = 0; kt < 4; kt++) {
            int d0 = kt * 16 + qoff;
            qfh[kt][0] = *(const uint32_t*)(q0h + d0);
            qfh[kt][1] = *(const uint32_t*)(q0h + 8 * DH + d0);
            qfh[kt][2] = *(const uint32_t*)(q0h + d0 + 8);
            qfh[kt][3] = *(const uint32_t*)(q0h + 8 * DH + d0 + 8);
            qfl[kt][0] = *(const uint32_t*)(q0l + d0);
            qfl[kt][1] = *(const uint32_t*)(q0l + 8 * DH + d0);
            qfl[kt][2] = *(const uint32_t*)(q0l + d0 + 8);
            qfl[kt][3] = *(const uint32_t*)(q0l + 8 * DH + d0 + 8);
        }
    }

    const int lm = lane >> 3, li = lane & 7;
    const uint32_t boff = (uint32_t)((((lm >> 1) * 8 + li) * SPIT + (lm & 1) * 8) * 2);

    auto stage = [&](int c0s, int buf) {
        #pragma unroll
        for (int i = 0; i < 16; i++) {
            int idx = tid + i * 128;          // 0..2047
            int part = idx >> 9;              // 0=Kh 1=Kl 2=Vh 3=Vl
            int rem = idx & 511;
            int r = rem >> 3, cc = (rem & 7) << 3;
            uint32_t dst = sbase + (uint32_t)(buf * BUFSZ + part * 9216 + (r * SPIT + cc) * 2);
            if (part < 2) {
                int j = c0s + r;
                const __nv_bfloat16* ks = ((part & 1) ? g_kl : g_kh)
                    + ((size_t)bh * MK + min(j, MK - 1)) * DH + cc;
                cp16z(dst, ks, j < MK);
            } else {
                const __nv_bfloat16* vs = ((part & 1) ? g_vtl : g_vth)
                    + ((size_t)bh * DH + r) * MKP + c0s + cc;
                cp16(dst, vs);
            }
        }
    };

    stage(0, 0);
    CP_COMMIT();

    float oacc[8][4] = {};
    float sum0 = 0.0f, sum1 = 0.0f;

    for (int ch = 0; ch < NCH; ch++) {
        int c0 = ch << 6;
        CP_WAIT0();
        __syncthreads();
        if (ch + 1 < NCH) { stage((ch + 1) << 6, (ch + 1) & 1); CP_COMMIT(); }

        uint32_t uKh = sbase + (uint32_t)((ch & 1) * BUFSZ);
        uint32_t uKl = uKh + 9216;
        uint32_t uVh = uKh + 18432;
        uint32_t uVl = uKh + 27648;

        float sacc[8][4] = {};
        #pragma unroll
        for (int kt = 0; kt < 4; kt++) {
            #pragma unroll
            for (int ntp = 0; ntp < 4; ntp++) {
                uint32_t off = (uint32_t)(ntp * 16 * SPIT * 2 + kt * 32) + boff;
                uint32_t bhf[4], blf[4];
                ldsm_x4(bhf, uKh + off);
                ldsm_x4(blf, uKl + off);
                mma16816(sacc[2 * ntp],     qfh[kt], bhf[0], bhf[1]);
                mma16816(sacc[2 * ntp + 1], qfh[kt], bhf[2], bhf[3]);
                mma16816(sacc[2 * ntp],     qfl[kt], bhf[0], bhf[1]);
                mma16816(sacc[2 * ntp + 1], qfl[kt], bhf[2], bhf[3]);
                mma16816(sacc[2 * ntp],     qfh[kt], blf[0], blf[1]);
                mma16816(sacc[2 * ntp + 1], qfh[kt], blf[2], blf[3]);
            }
        }

        uint32_t pfh[4][4], pfl[4][4];
        #pragma unroll
        for (int nt = 0; nt < 8; nt++) {
            int j0 = c0 + nt * 8 + qoff;
            uint32_t wb = bmap[j0 >> 5];
            int bi = j0 & 31;
            float m0 = (float)((wb >> bi) & 1u);
            float m1 = (float)((wb >> (bi + 1)) & 1u);
            float p0 = m0 * __expf(fminf(sacc[nt][0], 30.0f));
            float p1 = m1 * __expf(fminf(sacc[nt][1], 30.0f));
            float p2 = m0 * __expf(fminf(sacc[nt][2], 30.0f));
            float p3 = m1 * __expf(fminf(sacc[nt][3], 30.0f));
            sum0 += p0 + p1;
            sum1 += p2 + p3;
            float h0 = __bfloat162float(__float2bfloat16(p0));
            float h1 = __bfloat162float(__float2bfloat16(p1));
            float h2 = __bfloat162float(__float2bfloat16(p2));
            float h3 = __bfloat162float(__float2bfloat16(p3));
            int kt = nt >> 1, hf = (nt & 1) << 1;
            pfh[kt][hf + 0] = pack_bf16x2(h0, h1);
            pfh[kt][hf + 1] = pack_bf16x2(h2, h3);
            pfl[kt][hf + 0] = pack_bf16x2(p0 - h0, p1 - h1);
            pfl[kt][hf + 1] = pack_bf16x2(p2 - h2, p3 - h3);
        }

        #pragma unroll
        for (int kt = 0; kt < 4; kt++) {
            #pragma unroll
            for (int ntp = 0; ntp < 4; ntp++) {
                uint32_t off = (uint32_t)(ntp * 16 * SPIT * 2 + kt * 32) + boff;
                uint32_t vhf[4], vlf[4];
                ldsm_x4(vhf, uVh + off);
                ldsm_x4(vlf, uVl + off);
                mma16816(oacc[2 * ntp],     pfh[kt], vhf[0], vhf[1]);
                mma16816(oacc[2 * ntp + 1], pfh[kt], vhf[2], vhf[3]);
                mma16816(oacc[2 * ntp],     pfl[kt], vhf[0], vhf[1]);
                mma16816(oacc[2 * ntp + 1], pfl[kt], vhf[2], vhf[3]);
                mma16816(oacc[2 * ntp],     pfh[kt], vlf[0], vlf[1]);
                mma16816(oacc[2 * ntp + 1], pfh[kt], vlf[2], vlf[3]);
            }
        }
    }

    sum0 += __shfl_xor_sync(0xffffffffu, sum0, 1);
    sum0 += __shfl_xor_sync(0xffffffffu, sum0, 2);
    sum1 += __shfl_xor_sync(0xffffffffu, sum1, 1);
    sum1 += __shfl_xor_sync(0xffffffffu, sum1, 2);
    float inv0 = 1.0f / sum0;
    float inv1 = 1.0f / sum1;

    // write attention out pre-split (bf16 hi/lo) for the Wo projection
    size_t base0 = ((size_t)(b * NQ) + n0 + wid * 16 + g) * INNER + h * DH;
    size_t base1 = base0 + 8 * INNER;
    #pragma unroll
    for (int nt = 0; nt < 8; nt++) {
        int c = nt * 8 + qoff;
        float v0 = oacc[nt][0] * inv0;
        float v1 = oacc[nt][1] * inv0;
        float v2 = oacc[nt][2] * inv1;
        float v3 = oacc[nt][3] * inv1;
        bsplit(v0, &g_aoh[base0 + c],     &g_aol[base0 + c]);
        bsplit(v1, &g_aoh[base0 + c + 1], &g_aol[base0 + c + 1]);
        bsplit(v2, &g_aoh[base1 + c],     &g_aol[base1 + c]);
        bsplit(v3, &g_aoh[base1 + c + 1], &g_aol[base1 + c + 1]);
    }
}

// ---------------- launch ------------------------------------------------------
extern "C" void kernel_launch(void* const* d_in, const int* in_sizes, int n_in,
                              void* d_out, int out_size)
{
    const float* x       = (const float*)d_in[0];
    const float* context = (const float*)d_in[1];
    const int*   mask    = (const int*)  d_in[2];
    const float* g_x     = (const float*)d_in[3];
    const float* null_kv = (const float*)d_in[4];
    const float* Wq      = (const float*)d_in[5];
    const float* Wkv     = (const float*)d_in[6];
    const float* Wo      = (const float*)d_in[7];
    const float* g_outp  = (const float*)d_in[8];
    float* out = (float*)d_out;
    (void)in_sizes; (void)n_in; (void)out_size;

    __nv_bfloat16 *wqh, *wql, *wkvh, *wkvl, *woh, *wol;
    __nv_bfloat16 *xnh, *xnl, *cxh, *cxl, *aoh, *aol;
    cudaGetSymbolAddress((void**)&wqh,  g_wqh);
    cudaGetSymbolAddress((void**)&wql,  g_wql);
    cudaGetSymbolAddress((void**)&wkvh, g_wkvh);
    cudaGetSymbolAddress((void**)&wkvl, g_wkvl);
    cudaGetSymbolAddress((void**)&woh,  g_woh);
    cudaGetSymbolAddress((void**)&wol,  g_wol);
    cudaGetSymbolAddress((void**)&xnh,  g_xnh);
    cudaGetSymbolAddress((void**)&xnl,  g_xnl);
    cudaGetSymbolAddress((void**)&cxh,  g_cxh);
    cudaGetSymbolAddress((void**)&cxl,  g_cxl);
    cudaGetSymbolAddress((void**)&aoh,  g_aoh);
    cudaGetSymbolAddress((void**)&aol,  g_aol);

    wsplit_kernel<<<dim3(8, 8),  256>>>(Wq,  wqh,  wql,  512);
    wsplit_kernel<<<dim3(16, 8), 256>>>(Wkv, wkvh, wkvl, 1024);
    wsplit_kernel<<<dim3(8, 8),  256>>>(Wo,  woh,  wol,  512);

    csplit_kernel<<<(BATCH * NCTX * DIMC) / 1024, 256>>>(context);
    ln_kernel<0><<<BATCH * NQ, 128>>>(x, g_x, nullptr);

    cudaFuncSetAttribute(proj_mma_kernel<0>, cudaFuncAttributeMaxDynamicSharedMemorySize, 2 * PBUF);
    cudaFuncSetAttribute(proj_mma_kernel<1>, cudaFuncAttributeMaxDynamicSharedMemorySize, 2 * PBUF);
    cudaFuncSetAttribute(proj_mma_kernel<2>, cudaFuncAttributeMaxDynamicSharedMemorySize, 2 * PBUF);

    proj_mma_kernel<0><<<dim3(8, 128),  128, 2 * PBUF>>>(xnh, xnl, wqh, wql);
    proj_mma_kernel<1><<<dim3(16, 128), 128, 2 * PBUF>>>(cxh, cxl, wkvh, wkvl);
    null_fill_kernel<<<BATCH * HEADS, DH>>>(null_kv);

    cudaFuncSetAttribute(attn_mma_kernel, cudaFuncAttributeMaxDynamicSharedMemorySize, ATTN_SMEM);
    attn_mma_kernel<<<dim3(NQ / 64, BATCH * HEADS), 128, ATTN_SMEM>>>(mask);

    proj_mma_kernel<2><<<dim3(8, 128), 128, 2 * PBUF>>>(aoh, aol, woh, wol);
    ln_kernel<1><<<BATCH * NQ, 128>>>(nullptr, g_outp, out);
}

// round 11
// speedup vs baseline: 1.2462x; 1.2012x over previous
#include <cuda_runtime.h>
#include <cuda_bf16.h>
#include <cuda_fp16.h>
#include <math.h>
#include <stdint.h>

// ---------------- problem constants ----------------
#define BATCH   2
#define NQ      4096
#define NCTX    4096
#define DIMC    512
#define HEADS   8
#define DH      64
#define INNER   512
#define MK      4097         // keys incl. null
#define MKP     4160         // padded V^T stride (covers 65*64 tail, zeros in pad)
#define SQSCALE 0.35355339059327373f   // sqrt(64^-0.5)
#define SPIT    72           // smem pitch (16-bit elems) = 144B

// ---------------- scratch ----------------------------------------------------
__device__ float g_pj[(size_t)BATCH * NQ * DIMC];

// pre-split activations (bf16 hi/lo) for projections
__device__ __nv_bfloat16 g_xnh[(size_t)BATCH * NQ * DIMC], g_xnl[(size_t)BATCH * NQ * DIMC];
__device__ __nv_bfloat16 g_cxh[(size_t)BATCH * NCTX * DIMC], g_cxl[(size_t)BATCH * NCTX * DIMC];
__device__ __nv_bfloat16 g_aoh[(size_t)BATCH * NQ * INNER], g_aol[(size_t)BATCH * NQ * INNER];

// attention operands: fp16. Q single; K,V split-2.
__device__ __half g_qh[(size_t)BATCH * HEADS * NQ * DH];
__device__ __half g_kh[(size_t)BATCH * HEADS * MK * DH];
__device__ __half g_kl[(size_t)BATCH * HEADS * MK * DH];
__device__ __half g_vth[(size_t)BATCH * HEADS * DH * MKP];  // [bh][d][key]
__device__ __half g_vtl[(size_t)BATCH * HEADS * DH * MKP];

// transposed/split weights: Wt[n][k], k = 512 (bf16 hi/lo)
__device__ __nv_bfloat16 g_wqh[512 * 512],  g_wql[512 * 512];
__device__ __nv_bfloat16 g_wkvh[1024 * 512], g_wkvl[1024 * 512];
__device__ __nv_bfloat16 g_woh[512 * 512],  g_wol[512 * 512];

// ---------------- helpers -----------------------------------------------------
__device__ __forceinline__ void bsplit(float v, __nv_bfloat16* hi, __nv_bfloat16* lo) {
    __nv_bfloat16 h = __float2bfloat16(v);
    *hi = h;
    *lo = __float2bfloat16(v - __bfloat162float(h));
}
__device__ __forceinline__ void hsplit(float v, __half* hi, __half* lo) {
    __half h = __float2half(v);
    *hi = h;
    *lo = __float2half(v - __half2float(h));
}
__device__ __forceinline__ uint32_t pack_f16x2(float lo_elem, float hi_elem) {
    uint32_t r;
    asm("cvt.rn.f16x2.f32 %0, %1, %2;" : "=r"(r) : "f"(hi_elem), "f"(lo_elem));
    return r;
}
// bf16 mma (projections)
__device__ __forceinline__ void mma16816(float* d, const uint32_t* a, uint32_t b0, uint32_t b1) {
    asm volatile("mma.sync.aligned.m16n8k16.row.col.f32.bf16.bf16.f32 "
        "{%0,%1,%2,%3}, {%4,%5,%6,%7}, {%8,%9}, {%0,%1,%2,%3};"
        : "+f"(d[0]), "+f"(d[1]), "+f"(d[2]), "+f"(d[3])
        : "r"(a[0]), "r"(a[1]), "r"(a[2]), "r"(a[3]), "r"(b0), "r"(b1));
}
// fp16 mma (attention)
__device__ __forceinline__ void mma16816f(float* d, const uint32_t* a, uint32_t b0, uint32_t b1) {
    asm volatile("mma.sync.aligned.m16n8k16.row.col.f32.f16.f16.f32 "
        "{%0,%1,%2,%3}, {%4,%5,%6,%7}, {%8,%9}, {%0,%1,%2,%3};"
        : "+f"(d[0]), "+f"(d[1]), "+f"(d[2]), "+f"(d[3])
        : "r"(a[0]), "r"(a[1]), "r"(a[2]), "r"(a[3]), "r"(b0), "r"(b1));
}
__device__ __forceinline__ void ldsm_x4(uint32_t* r, uint32_t addr) {
    asm volatile("ldmatrix.sync.aligned.m8n8.x4.shared.b16 {%0,%1,%2,%3}, [%4];"
        : "=r"(r[0]), "=r"(r[1]), "=r"(r[2]), "=r"(r[3]) : "r"(addr));
}
__device__ __forceinline__ void cp16(uint32_t dst, const void* src) {
    asm volatile("cp.async.cg.shared.global [%0], [%1], 16;"
        :: "r"(dst), "l"(src) : "memory");
}
__device__ __forceinline__ void cp16z(uint32_t dst, const void* src, int ok) {
    int sz = ok ? 16 : 0;
    asm volatile("cp.async.cg.shared.global [%0], [%1], 16, %2;"
        :: "r"(dst), "l"(src), "r"(sz) : "memory");
}
#define CP_COMMIT() asm volatile("cp.async.commit_group;" ::: "memory")
#define CP_WAIT0()  asm volatile("cp.async.wait_group 0;" ::: "memory")

// ---------------- layernorm --------------------------------------------------
template <int WHICH>
__global__ void __launch_bounds__(128) ln_kernel(const float* __restrict__ inp,
                                                 const float* __restrict__ g,
                                                 float* __restrict__ outp)
{
    const float* in = (WHICH == 0) ? inp : g_pj;
    int row = blockIdx.x;
    int tid = threadIdx.x;
    const float* rptr = in + (size_t)row * DIMC;

    float4 v = reinterpret_cast<const float4*>(rptr)[tid];
    float s  = v.x + v.y + v.z + v.w;
    float ss = v.x * v.x + v.y * v.y + v.z * v.z + v.w * v.w;
    #pragma unroll
    for (int o = 16; o > 0; o >>= 1) {
        s  += __shfl_down_sync(0xffffffffu, s,  o);
        ss += __shfl_down_sync(0xffffffffu, ss, o);
    }
    __shared__ float sb[8];
    int wid = tid >> 5, lane = tid & 31;
    if (lane == 0) { sb[wid] = s; sb[4 + wid] = ss; }
    __syncthreads();
    float S  = sb[0] + sb[1] + sb[2] + sb[3];
    float SS = sb[4] + sb[5] + sb[6] + sb[7];
    float mean = S * (1.0f / DIMC);
    float var  = SS * (1.0f / DIMC) - mean * mean;
    float rstd = rsqrtf(var + 1e-5f);
    float4 gv = reinterpret_cast<const float4*>(g)[tid];
    float o0 = (v.x - mean) * rstd * gv.x;
    float o1 = (v.y - mean) * rstd * gv.y;
    float o2 = (v.z - mean) * rstd * gv.z;
    float o3 = (v.w - mean) * rstd * gv.w;
    if (WHICH == 0) {
        size_t base = (size_t)row * DIMC + tid * 4;
        bsplit(o0, &g_xnh[base],     &g_xnl[base]);
        bsplit(o1, &g_xnh[base + 1], &g_xnl[base + 1]);
        bsplit(o2, &g_xnh[base + 2], &g_xnl[base + 2]);
        bsplit(o3, &g_xnh[base + 3], &g_xnl[base + 3]);
    } else {
        float4 o4 = make_float4(o0, o1, o2, o3);
        reinterpret_cast<float4*>(outp + (size_t)row * DIMC)[tid] = o4;
    }
}

// ---------------- context split (fp32 -> bf16 hi/lo) -------------------------
__global__ void __launch_bounds__(256) csplit_kernel(const float* __restrict__ src)
{
    size_t i4 = ((size_t)blockIdx.x * 256 + threadIdx.x);
    float4 v = reinterpret_cast<const float4*>(src)[i4];
    size_t base = i4 * 4;
    bsplit(v.x, &g_cxh[base],     &g_cxl[base]);
    bsplit(v.y, &g_cxh[base + 1], &g_cxl[base + 1]);
    bsplit(v.z, &g_cxh[base + 2], &g_cxl[base + 2]);
    bsplit(v.w, &g_cxh[base + 3], &g_cxl[base + 3]);
}

// ---------------- null kv fill -----------------------------------------------
__global__ void null_fill_kernel(const float* __restrict__ null_kv)
{
    int bh = blockIdx.x;
    int d  = threadIdx.x;
    size_t kidx = (size_t)bh * MK * DH + d;
    hsplit(null_kv[d] * SQSCALE, &g_kh[kidx], &g_kl[kidx]);
    size_t vidx = ((size_t)bh * DH + d) * MKP + 0;
    hsplit(null_kv[DH + d], &g_vth[vidx], &g_vtl[vidx]);
}

// ---------------- weight transpose + split: Wt[n][k] -------------------------
__global__ void __launch_bounds__(256) wsplit_kernel(const float* __restrict__ W,
                                                     __nv_bfloat16* __restrict__ Th,
                                                     __nv_bfloat16* __restrict__ Tl,
                                                     int N)
{
    __shared__ float s[64][65];
    int tid = threadIdx.x;
    int n0 = blockIdx.x * 64;
    int k0 = blockIdx.y * 64;
    #pragma unroll
    for (int i = 0; i < 16; i++) {
        int idx = tid + i * 256;
        int k = idx >> 6, n = idx & 63;
        s[k][n] = W[(size_t)(k0 + k) * N + n0 + n];
    }
    __syncthreads();
    #pragma unroll
    for (int i = 0; i < 16; i++) {
        int idx = tid + i * 256;
        int n = idx >> 6, k = idx & 63;
        size_t o = (size_t)(n0 + n) * 512 + k0 + k;
        bsplit(s[k][n], &Th[o], &Tl[o]);
    }
}

// ---------------- tensor-core projection GEMM: bf16 A, cp.async 2-buffer -----
#define PBUF 36864
template <int MODE>
__global__ void __launch_bounds__(128) proj_mma_kernel(const __nv_bfloat16* __restrict__ Ath,
                                                       const __nv_bfloat16* __restrict__ Atl,
                                                       const __nv_bfloat16* __restrict__ Wth,
                                                       const __nv_bfloat16* __restrict__ Wtl)
{
    extern __shared__ char smc[];
    uint32_t sbase = (uint32_t)__cvta_generic_to_shared(smc);

    int tid  = threadIdx.x;
    int wid  = tid >> 5;
    int lane = tid & 31;
    int g    = lane >> 2;
    int qoff = (lane & 3) << 1;
    int row0 = blockIdx.y * 64;
    int col0 = blockIdx.x * 64;

    int lm = lane >> 3, li = lane & 7;
    uint32_t aoff = (uint32_t)(((wid * 16 + (lm & 1) * 8 + li) * SPIT + (lm >> 1) * 8) * 2);
    uint32_t boff = (uint32_t)((((lm >> 1) * 8 + li) * SPIT + (lm & 1) * 8) * 2);

    auto stage = [&](int k0, int buf) {
        #pragma unroll
        for (int i = 0; i < 16; i++) {
            int idx = tid + i * 128;
            int part = idx >> 9;              // 0=Ah 1=Al 2=Bh 3=Bl
            int rem = idx & 511;
            int r = rem >> 3, cc = (rem & 7) << 3;
            uint32_t dst = sbase + (uint32_t)(buf * PBUF + part * 9216 + (r * SPIT + cc) * 2);
            const __nv_bfloat16* src;
            if (part == 0)      src = Ath + (size_t)(row0 + r) * 512 + k0 + cc;
            else if (part == 1) src = Atl + (size_t)(row0 + r) * 512 + k0 + cc;
            else if (part == 2) src = Wth + (size_t)(col0 + r) * 512 + k0 + cc;
            else                src = Wtl + (size_t)(col0 + r) * 512 + k0 + cc;
            cp16(dst, src);
        }
    };

    stage(0, 0);
    CP_COMMIT();

    float oacc[8][4] = {};

    for (int kc = 0; kc < 8; kc++) {
        CP_WAIT0();
        __syncthreads();
        if (kc + 1 < 8) { stage((kc + 1) << 6, (kc + 1) & 1); CP_COMMIT(); }

        uint32_t uAh = sbase + (uint32_t)((kc & 1) * PBUF);
        uint32_t uAl = uAh + 9216;
        uint32_t uBh = uAh + 18432;
        uint32_t uBl = uAh + 27648;

        uint32_t afh[4][4], afl[4][4];
        #pragma unroll
        for (int kt = 0; kt < 4; kt++) {
            ldsm_x4(afh[kt], uAh + (uint32_t)(kt * 32) + aoff);
            ldsm_x4(afl[kt], uAl + (uint32_t)(kt * 32) + aoff);
        }

        #pragma unroll
        for (int kt = 0; kt < 4; kt++) {
            #pragma unroll
            for (int ntp = 0; ntp < 4; ntp++) {
                uint32_t off = (uint32_t)(ntp * 16 * SPIT * 2 + kt * 32) + boff;
                uint32_t bhf[4], blf[4];
                ldsm_x4(bhf, uBh + off);
                ldsm_x4(blf, uBl + off);
                mma16816(oacc[2 * ntp],     afh[kt], bhf[0], bhf[1]);
                mma16816(oacc[2 * ntp + 1], afh[kt], bhf[2], bhf[3]);
                mma16816(oacc[2 * ntp],     afl[kt], bhf[0], bhf[1]);
                mma16816(oacc[2 * ntp + 1], afl[kt], bhf[2], bhf[3]);
                mma16816(oacc[2 * ntp],     afh[kt], blf[0], blf[1]);
                mma16816(oacc[2 * ntp + 1], afh[kt], blf[2], blf[3]);
            }
        }
    }

    #pragma unroll
    for (int nt = 0; nt < 8; nt++) {
        #pragma unroll
        for (int half = 0; half < 2; half++) {
            int row = row0 + wid * 16 + g + half * 8;
            float v0 = oacc[nt][half * 2 + 0];
            float v1 = oacc[nt][half * 2 + 1];
            int c = col0 + nt * 8 + qoff;
            if (MODE == 0) {
                int b = row >> 12, n = row & 4095;
                int h = c >> 6, dd = c & 63;
                size_t idx = (((size_t)(b * HEADS + h)) * NQ + n) * DH + dd;
                g_qh[idx]     = __float2half(v0 * SQSCALE);
                g_qh[idx + 1] = __float2half(v1 * SQSCALE);
            } else if (MODE == 1) {
                int b = row >> 12, mr = row & 4095;
                if (c < 512) {
                    int h = c >> 6, dd = c & 63;
                    size_t idx = (((size_t)(b * HEADS + h)) * MK + mr + 1) * DH + dd;
                    hsplit(v0 * SQSCALE, &g_kh[idx],     &g_kl[idx]);
                    hsplit(v1 * SQSCALE, &g_kh[idx + 1], &g_kl[idx + 1]);
                } else {
                    int c2 = c - 512;
                    int h = c2 >> 6, dd = c2 & 63;
                    size_t idx = (((size_t)(b * HEADS + h)) * DH + dd) * MKP + (mr + 1);
                    hsplit(v0, &g_vth[idx],       &g_vtl[idx]);
                    hsplit(v1, &g_vth[idx + MKP], &g_vtl[idx + MKP]);
                }
            } else {
                *(float2*)(g_pj + (size_t)row * 512 + c) = make_float2(v0, v1);
            }
        }
    }
}

// ---------------- FA2 attention: fp16 2-term, 2 Q-subtiles, 128 threads -------
#define BUFSZ   36864
#define OFF_BM  73728
#define ATTN_SMEM 74272
#define NCH     65

__global__ void __launch_bounds__(128) attn_mma_kernel(const int* __restrict__ mask)
{
    extern __shared__ char smc[];
    const int tid  = threadIdx.x;
    const int wid  = tid >> 5;          // 0..3
    const int lane = tid & 31;
    const int g    = lane >> 2;
    const int qoff = (lane & 3) << 1;
    const int bh = blockIdx.y;
    const int b = bh >> 3, h = bh & 7;
    const int n0 = blockIdx.x << 7;     // 128 q-rows per CTA (2 subtiles of 64)

    uint32_t sbase = (uint32_t)__cvta_generic_to_shared(smc);
    uint32_t* bmap = (uint32_t*)(smc + OFF_BM);

    for (int w = tid; w < 130; w += 128) {
        uint32_t wv = 0;
        int jb = w * 32;
        #pragma unroll 8
        for (int i = 0; i < 32; i++) {
            int j = jb + i;
            int ok = (j == 0) ? 1 : ((j < MK) ? (mask[b * NCTX + j - 1] != 0) : 0);
            wv |= (uint32_t)ok << i;
        }
        bmap[w] = wv;
    }

    // Q fragments (fp16 single) for both subtiles
    uint32_t qf[2][4][4];
    #pragma unroll
    for (int t = 0; t < 2; t++) {
        const __half* q0 = g_qh + ((size_t)bh * NQ + n0 + t * 64 + wid * 16 + g) * DH;
        #pragma unroll
        for (int kt = 0; kt < 4; kt++) {
            int d0 = kt * 16 + qoff;
            qf[t][kt][0] = *(const uint32_t*)(q0 + d0);
            qf[t][kt][1] = *(const uint32_t*)(q0 + 8 * DH + d0);
            qf[t][kt][2] = *(const uint32_t*)(q0 + d0 + 8);
            qf[t][kt][3] = *(const uint32_t*)(q0 + 8 * DH + d0 + 8);
        }
    }

    const int lm = lane >> 3, li = lane & 7;
    const uint32_t boff = (uint32_t)((((lm >> 1) * 8 + li) * SPIT + (lm & 1) * 8) * 2);

    auto stage = [&](int c0s, int buf) {
        #pragma unroll
        for (int i = 0; i < 16; i++) {
            int idx = tid + i * 128;          // 0..2047
            int part = idx >> 9;              // 0=Kh 1=Kl 2=Vh 3=Vl
            int rem = idx & 511;
            int r = rem >> 3, cc = (rem & 7) << 3;
            uint32_t dst = sbase + (uint32_t)(buf * BUFSZ + part * 9216 + (r * SPIT + cc) * 2);
            if (part < 2) {
                int j = c0s + r;
                const __half* ks = ((part & 1) ? g_kl : g_kh)
                    + ((size_t)bh * MK + min(j, MK - 1)) * DH + cc;
                cp16z(dst, ks, j < MK);
            } else {
                const __half* vs = ((part & 1) ? g_vtl : g_vth)
                    + ((size_t)bh * DH + r) * MKP + c0s + cc;
                cp16(dst, vs);
            }
        }
    };

    stage(0, 0);
    CP_COMMIT();

    float oacc[2][8][4] = {};
    float sums[2][2] = {};

    for (int ch = 0; ch < NCH; ch++) {
        int c0 = ch << 6;
        CP_WAIT0();
        __syncthreads();
        if (ch + 1 < NCH) { stage((ch + 1) << 6, (ch + 1) & 1); CP_COMMIT(); }

        uint32_t uKh = sbase + (uint32_t)((ch & 1) * BUFSZ);
        uint32_t uKl = uKh + 9216;
        uint32_t uVh = uKh + 18432;
        uint32_t uVl = uKh + 27648;

        #pragma unroll
        for (int t = 0; t < 2; t++) {
            // ---- S = Q K^T : fp16, K split-2 → 4 MMAs per (kt,ntp) ----
            float sacc[8][4] = {};
            #pragma unroll
            for (int kt = 0; kt < 4; kt++) {
                #pragma unroll
                for (int ntp = 0; ntp < 4; ntp++) {
                    uint32_t off = (uint32_t)(ntp * 16 * SPIT * 2 + kt * 32) + boff;
                    uint32_t bhf[4], blf[4];
                    ldsm_x4(bhf, uKh + off);
                    ldsm_x4(blf, uKl + off);
                    mma16816f(sacc[2 * ntp],     qf[t][kt], bhf[0], bhf[1]);
                    mma16816f(sacc[2 * ntp + 1], qf[t][kt], bhf[2], bhf[3]);
                    mma16816f(sacc[2 * ntp],     qf[t][kt], blf[0], blf[1]);
                    mma16816f(sacc[2 * ntp + 1], qf[t][kt], blf[2], blf[3]);
                }
            }

            // ---- softmax (bitmap mask, no max-subtract) → P fp16 single ----
            uint32_t pf[4][4];
            #pragma unroll
            for (int nt = 0; nt < 8; nt++) {
                int j0 = c0 + nt * 8 + qoff;
                uint32_t wb = bmap[j0 >> 5];
                int bi = j0 & 31;
                float m0 = (float)((wb >> bi) & 1u);
                float m1 = (float)((wb >> (bi + 1)) & 1u);
                float p0 = m0 * __expf(fminf(sacc[nt][0], 10.0f));
                float p1 = m1 * __expf(fminf(sacc[nt][1], 10.0f));
                float p2 = m0 * __expf(fminf(sacc[nt][2], 10.0f));
                float p3 = m1 * __expf(fminf(sacc[nt][3], 10.0f));
                // round to fp16, sum the rounded values (match PV numerator)
                float r0 = __half2float(__float2half(p0));
                float r1 = __half2float(__float2half(p1));
                float r2 = __half2float(__float2half(p2));
                float r3 = __half2float(__float2half(p3));
                sums[t][0] += r0 + r1;
                sums[t][1] += r2 + r3;
                int kt = nt >> 1, hf = (nt & 1) << 1;
                pf[kt][hf + 0] = pack_f16x2(r0, r1);
                pf[kt][hf + 1] = pack_f16x2(r2, r3);
            }

            // ---- O += P V : fp16, V split-2 → 4 MMAs per (kt,ntp) ----
            #pragma unroll
            for (int kt = 0; kt < 4; kt++) {
                #pragma unroll
                for (int ntp = 0; ntp < 4; ntp++) {
                    uint32_t off = (uint32_t)(ntp * 16 * SPIT * 2 + kt * 32) + boff;
                    uint32_t vhf[4], vlf[4];
                    ldsm_x4(vhf, uVh + off);
                    ldsm_x4(vlf, uVl + off);
                    mma16816f(oacc[t][2 * ntp],     pf[kt], vhf[0], vhf[1]);
                    mma16816f(oacc[t][2 * ntp + 1], pf[kt], vhf[2], vhf[3]);
                    mma16816f(oacc[t][2 * ntp],     pf[kt], vlf[0], vlf[1]);
                    mma16816f(oacc[t][2 * ntp + 1], pf[kt], vlf[2], vlf[3]);
                }
            }
        }
    }

    #pragma unroll
    for (int t = 0; t < 2; t++) {
        float s0 = sums[t][0], s1 = sums[t][1];
        s0 += __shfl_xor_sync(0xffffffffu, s0, 1);
        s0 += __shfl_xor_sync(0xffffffffu, s0, 2);
        s1 += __shfl_xor_sync(0xffffffffu, s1, 1);
        s1 += __shfl_xor_sync(0xffffffffu, s1, 2);
        float inv0 = 1.0f / s0;
        float inv1 = 1.0f / s1;

        size_t base0 = ((size_t)(b * NQ) + n0 + t * 64 + wid * 16 + g) * INNER + h * DH;
        size_t base1 = base0 + 8 * INNER;
        #pragma unroll
        for (int nt = 0; nt < 8; nt++) {
            int c = nt * 8 + qoff;
            float v0 = oacc[t][nt][0] * inv0;
            float v1 = oacc[t][nt][1] * inv0;
            float v2 = oacc[t][nt][2] * inv1;
            float v3 = oacc[t][nt][3] * inv1;
            bsplit(v0, &g_aoh[base0 + c],     &g_aol[base0 + c]);
            bsplit(v1, &g_aoh[base0 + c + 1], &g_aol[base0 + c + 1]);
            bsplit(v2, &g_aoh[base1 + c],     &g_aol[base1 + c]);
            bsplit(v3, &g_aoh[base1 + c + 1], &g_aol[base1 + c + 1]);
        }
    }
}

// ---------------- launch ------------------------------------------------------
extern "C" void kernel_launch(void* const* d_in, const int* in_sizes, int n_in,
                              void* d_out, int out_size)
{
    const float* x       = (const float*)d_in[0];
    const float* context = (const float*)d_in[1];
    const int*   mask    = (const int*)  d_in[2];
    const float* g_x     = (const float*)d_in[3];
    const float* null_kv = (const float*)d_in[4];
    const float* Wq      = (const float*)d_in[5];
    const float* Wkv     = (const float*)d_in[6];
    const float* Wo      = (const float*)d_in[7];
    const float* g_outp  = (const float*)d_in[8];
    float* out = (float*)d_out;
    (void)in_sizes; (void)n_in; (void)out_size;

    __nv_bfloat16 *wqh, *wql, *wkvh, *wkvl, *woh, *wol;
    __nv_bfloat16 *xnh, *xnl, *cxh, *cxl, *aoh, *aol;
    cudaGetSymbolAddress((void**)&wqh,  g_wqh);
    cudaGetSymbolAddress((void**)&wql,  g_wql);
    cudaGetSymbolAddress((void**)&wkvh, g_wkvh);
    cudaGetSymbolAddress((void**)&wkvl, g_wkvl);
    cudaGetSymbolAddress((void**)&woh,  g_woh);
    cudaGetSymbolAddress((void**)&wol,  g_wol);
    cudaGetSymbolAddress((void**)&xnh,  g_xnh);
    cudaGetSymbolAddress((void**)&xnl,  g_xnl);
    cudaGetSymbolAddress((void**)&cxh,  g_cxh);
    cudaGetSymbolAddress((void**)&cxl,  g_cxl);
    cudaGetSymbolAddress((void**)&aoh,  g_aoh);
    cudaGetSymbolAddress((void**)&aol,  g_aol);

    wsplit_kernel<<<dim3(8, 8),  256>>>(Wq,  wqh,  wql,  512);
    wsplit_kernel<<<dim3(16, 8), 256>>>(Wkv, wkvh, wkvl, 1024);
    wsplit_kernel<<<dim3(8, 8),  256>>>(Wo,  woh,  wol,  512);

    csplit_kernel<<<(BATCH * NCTX * DIMC) / 1024, 256>>>(context);
    ln_kernel<0><<<BATCH * NQ, 128>>>(x, g_x, nullptr);

    cudaFuncSetAttribute(proj_mma_kernel<0>, cudaFuncAttributeMaxDynamicSharedMemorySize, 2 * PBUF);
    cudaFuncSetAttribute(proj_mma_kernel<1>, cudaFuncAttributeMaxDynamicSharedMemorySize, 2 * PBUF);
    cudaFuncSetAttribute(proj_mma_kernel<2>, cudaFuncAttributeMaxDynamicSharedMemorySize, 2 * PBUF);

    proj_mma_kernel<0><<<dim3(8, 128),  128, 2 * PBUF>>>(xnh, xnl, wqh, wql);
    proj_mma_kernel<1><<<dim3(16, 128), 128, 2 * PBUF>>>(cxh, cxl, wkvh, wkvl);
    null_fill_kernel<<<BATCH * HEADS, DH>>>(null_kv);

    cudaFuncSetAttribute(attn_mma_kernel, cudaFuncAttributeMaxDynamicSharedMemorySize, ATTN_SMEM);
    attn_mma_kernel<<<dim3(NQ / 128, BATCH * HEADS), 128, ATTN_SMEM>>>(mask);

    proj_mma_kernel<2><<<dim3(8, 128), 128, 2 * PBUF>>>(aoh, aol, woh, wol);
    ln_kernel<1><<<BATCH * NQ, 128>>>(nullptr, g_outp, out);
}

// round 12
// speedup vs baseline: 1.3835x; 1.1102x over previous
#include <cuda_runtime.h>
#include <cuda_bf16.h>
#include <cuda_fp16.h>
#include <math.h>
#include <stdint.h>

// ---------------- problem constants ----------------
#define BATCH   2
#define NQ      4096
#define NCTX    4096
#define DIMC    512
#define HEADS   8
#define DH      64
#define INNER   512
#define MK      4097         // keys incl. null
#define MKP     4160         // padded V^T stride (covers 65*64 tail, zeros in pad)
#define SQSCALE 0.35355339059327373f   // sqrt(64^-0.5)
#define SPIT    72           // smem pitch (16-bit elems) = 144B

// ---------------- scratch ----------------------------------------------------
__device__ float g_pj[(size_t)BATCH * NQ * DIMC];

// single-fp16 activations (A-operands for projections)
__device__ __half g_xn16[(size_t)BATCH * NQ * DIMC];
__device__ __half g_cx16[(size_t)BATCH * NCTX * DIMC];
__device__ __half g_ao16[(size_t)BATCH * NQ * INNER];

// attention operands: fp16. Q single; K,V split-2.
__device__ __half g_qh[(size_t)BATCH * HEADS * NQ * DH];
__device__ __half g_kh[(size_t)BATCH * HEADS * MK * DH];
__device__ __half g_kl[(size_t)BATCH * HEADS * MK * DH];
__device__ __half g_vth[(size_t)BATCH * HEADS * DH * MKP];  // [bh][d][key]
__device__ __half g_vtl[(size_t)BATCH * HEADS * DH * MKP];

// transposed/split weights: Wt[n][k], k = 512 (fp16 hi/lo)
__device__ __half g_wqh[512 * 512],  g_wql[512 * 512];
__device__ __half g_wkvh[1024 * 512], g_wkvl[1024 * 512];
__device__ __half g_woh[512 * 512],  g_wol[512 * 512];

// ---------------- helpers -----------------------------------------------------
__device__ __forceinline__ void hsplit(float v, __half* hi, __half* lo) {
    __half h = __float2half(v);
    *hi = h;
    *lo = __float2half(v - __half2float(h));
}
__device__ __forceinline__ uint32_t pack_f16x2(float lo_elem, float hi_elem) {
    uint32_t r;
    asm("cvt.rn.f16x2.f32 %0, %1, %2;" : "=r"(r) : "f"(hi_elem), "f"(lo_elem));
    return r;
}
// fp16 mma
__device__ __forceinline__ void mma16816f(float* d, const uint32_t* a, uint32_t b0, uint32_t b1) {
    asm volatile("mma.sync.aligned.m16n8k16.row.col.f32.f16.f16.f32 "
        "{%0,%1,%2,%3}, {%4,%5,%6,%7}, {%8,%9}, {%0,%1,%2,%3};"
        : "+f"(d[0]), "+f"(d[1]), "+f"(d[2]), "+f"(d[3])
        : "r"(a[0]), "r"(a[1]), "r"(a[2]), "r"(a[3]), "r"(b0), "r"(b1));
}
__device__ __forceinline__ void ldsm_x4(uint32_t* r, uint32_t addr) {
    asm volatile("ldmatrix.sync.aligned.m8n8.x4.shared.b16 {%0,%1,%2,%3}, [%4];"
        : "=r"(r[0]), "=r"(r[1]), "=r"(r[2]), "=r"(r[3]) : "r"(addr));
}
__device__ __forceinline__ void cp16(uint32_t dst, const void* src) {
    asm volatile("cp.async.cg.shared.global [%0], [%1], 16;"
        :: "r"(dst), "l"(src) : "memory");
}
__device__ __forceinline__ void cp16z(uint32_t dst, const void* src, int ok) {
    int sz = ok ? 16 : 0;
    asm volatile("cp.async.cg.shared.global [%0], [%1], 16, %2;"
        :: "r"(dst), "l"(src), "r"(sz) : "memory");
}
#define CP_COMMIT() asm volatile("cp.async.commit_group;" ::: "memory")
#define CP_WAIT0()  asm volatile("cp.async.wait_group 0;" ::: "memory")

// ---------------- layernorm --------------------------------------------------
// WHICH==0: reads inp, writes single fp16 to g_xn16
// WHICH==1: reads g_pj, writes fp32 outp
template <int WHICH>
__global__ void __launch_bounds__(128) ln_kernel(const float* __restrict__ inp,
                                                 const float* __restrict__ g,
                                                 float* __restrict__ outp)
{
    const float* in = (WHICH == 0) ? inp : g_pj;
    int row = blockIdx.x;
    int tid = threadIdx.x;
    const float* rptr = in + (size_t)row * DIMC;

    float4 v = reinterpret_cast<const float4*>(rptr)[tid];
    float s  = v.x + v.y + v.z + v.w;
    float ss = v.x * v.x + v.y * v.y + v.z * v.z + v.w * v.w;
    #pragma unroll
    for (int o = 16; o > 0; o >>= 1) {
        s  += __shfl_down_sync(0xffffffffu, s,  o);
        ss += __shfl_down_sync(0xffffffffu, ss, o);
    }
    __shared__ float sb[8];
    int wid = tid >> 5, lane = tid & 31;
    if (lane == 0) { sb[wid] = s; sb[4 + wid] = ss; }
    __syncthreads();
    float S  = sb[0] + sb[1] + sb[2] + sb[3];
    float SS = sb[4] + sb[5] + sb[6] + sb[7];
    float mean = S * (1.0f / DIMC);
    float var  = SS * (1.0f / DIMC) - mean * mean;
    float rstd = rsqrtf(var + 1e-5f);
    float4 gv = reinterpret_cast<const float4*>(g)[tid];
    float o0 = (v.x - mean) * rstd * gv.x;
    float o1 = (v.y - mean) * rstd * gv.y;
    float o2 = (v.z - mean) * rstd * gv.z;
    float o3 = (v.w - mean) * rstd * gv.w;
    if (WHICH == 0) {
        uint2 pk;
        pk.x = pack_f16x2(o0, o1);
        pk.y = pack_f16x2(o2, o3);
        *(uint2*)(g_xn16 + (size_t)row * DIMC + tid * 4) = pk;
    } else {
        float4 o4 = make_float4(o0, o1, o2, o3);
        reinterpret_cast<float4*>(outp + (size_t)row * DIMC)[tid] = o4;
    }
}

// ---------------- context convert (fp32 -> fp16 single) ----------------------
__global__ void __launch_bounds__(256) csplit_kernel(const float* __restrict__ src)
{
    size_t i4 = ((size_t)blockIdx.x * 256 + threadIdx.x);
    float4 v = reinterpret_cast<const float4*>(src)[i4];
    uint2 pk;
    pk.x = pack_f16x2(v.x, v.y);
    pk.y = pack_f16x2(v.z, v.w);
    *(uint2*)(g_cx16 + i4 * 4) = pk;
}

// ---------------- null kv fill -----------------------------------------------
__global__ void null_fill_kernel(const float* __restrict__ null_kv)
{
    int bh = blockIdx.x;
    int d  = threadIdx.x;
    size_t kidx = (size_t)bh * MK * DH + d;
    hsplit(null_kv[d] * SQSCALE, &g_kh[kidx], &g_kl[kidx]);
    size_t vidx = ((size_t)bh * DH + d) * MKP + 0;
    hsplit(null_kv[DH + d], &g_vth[vidx], &g_vtl[vidx]);
}

// ---------------- weight transpose + split: Wt[n][k] (fp16 hi/lo) ------------
__global__ void __launch_bounds__(256) wsplit_kernel(const float* __restrict__ W,
                                                     __half* __restrict__ Th,
                                                     __half* __restrict__ Tl,
                                                     int N)
{
    __shared__ float s[64][65];
    int tid = threadIdx.x;
    int n0 = blockIdx.x * 64;
    int k0 = blockIdx.y * 64;
    #pragma unroll
    for (int i = 0; i < 16; i++) {
        int idx = tid + i * 256;
        int k = idx >> 6, n = idx & 63;
        s[k][n] = W[(size_t)(k0 + k) * N + n0 + n];
    }
    __syncthreads();
    #pragma unroll
    for (int i = 0; i < 16; i++) {
        int idx = tid + i * 256;
        int n = idx >> 6, k = idx & 63;
        size_t o = (size_t)(n0 + n) * 512 + k0 + k;
        hsplit(s[k][n], &Th[o], &Tl[o]);
    }
}

// ---------------- tensor-core projection GEMM: fp16 2-term, cp.async 2-buffer
// buffer parts: 0=A(single) 1=Bh 2=Bl, each 9216B; BUFSZ 27648, x2 = 55296B.
#define PBUF 27648
template <int MODE>
__global__ void __launch_bounds__(128) proj_mma_kernel(const __half* __restrict__ A16,
                                                       const __half* __restrict__ Wth,
                                                       const __half* __restrict__ Wtl)
{
    extern __shared__ char smc[];
    uint32_t sbase = (uint32_t)__cvta_generic_to_shared(smc);

    int tid  = threadIdx.x;
    int wid  = tid >> 5;
    int lane = tid & 31;
    int g    = lane >> 2;
    int qoff = (lane & 3) << 1;
    int row0 = blockIdx.y * 64;
    int col0 = blockIdx.x * 64;

    int lm = lane >> 3, li = lane & 7;
    uint32_t aoff = (uint32_t)(((wid * 16 + (lm & 1) * 8 + li) * SPIT + (lm >> 1) * 8) * 2);
    uint32_t boff = (uint32_t)((((lm >> 1) * 8 + li) * SPIT + (lm & 1) * 8) * 2);

    auto stage = [&](int k0, int buf) {
        #pragma unroll
        for (int i = 0; i < 12; i++) {
            int idx = tid + i * 128;          // 0..1535
            int part = idx >> 9;              // 0=A 1=Bh 2=Bl
            int rem = idx & 511;
            int r = rem >> 3, cc = (rem & 7) << 3;
            uint32_t dst = sbase + (uint32_t)(buf * PBUF + part * 9216 + (r * SPIT + cc) * 2);
            const __half* src;
            if (part == 0)      src = A16 + (size_t)(row0 + r) * 512 + k0 + cc;
            else if (part == 1) src = Wth + (size_t)(col0 + r) * 512 + k0 + cc;
            else                src = Wtl + (size_t)(col0 + r) * 512 + k0 + cc;
            cp16(dst, src);
        }
    };

    stage(0, 0);
    CP_COMMIT();

    float oacc[8][4] = {};

    for (int kc = 0; kc < 8; kc++) {
        CP_WAIT0();
        __syncthreads();
        if (kc + 1 < 8) { stage((kc + 1) << 6, (kc + 1) & 1); CP_COMMIT(); }

        uint32_t uA  = sbase + (uint32_t)((kc & 1) * PBUF);
        uint32_t uBh = uA + 9216;
        uint32_t uBl = uA + 18432;

        uint32_t af[4][4];
        #pragma unroll
        for (int kt = 0; kt < 4; kt++)
            ldsm_x4(af[kt], uA + (uint32_t)(kt * 32) + aoff);

        #pragma unroll
        for (int kt = 0; kt < 4; kt++) {
            #pragma unroll
            for (int ntp = 0; ntp < 4; ntp++) {
                uint32_t off = (uint32_t)(ntp * 16 * SPIT * 2 + kt * 32) + boff;
                uint32_t bhf[4], blf[4];
                ldsm_x4(bhf, uBh + off);
                ldsm_x4(blf, uBl + off);
                mma16816f(oacc[2 * ntp],     af[kt], bhf[0], bhf[1]);
                mma16816f(oacc[2 * ntp + 1], af[kt], bhf[2], bhf[3]);
                mma16816f(oacc[2 * ntp],     af[kt], blf[0], blf[1]);
                mma16816f(oacc[2 * ntp + 1], af[kt], blf[2], blf[3]);
            }
        }
    }

    #pragma unroll
    for (int nt = 0; nt < 8; nt++) {
        #pragma unroll
        for (int half = 0; half < 2; half++) {
            int row = row0 + wid * 16 + g + half * 8;
            float v0 = oacc[nt][half * 2 + 0];
            float v1 = oacc[nt][half * 2 + 1];
            int c = col0 + nt * 8 + qoff;
            if (MODE == 0) {
                int b = row >> 12, n = row & 4095;
                int h = c >> 6, dd = c & 63;
                size_t idx = (((size_t)(b * HEADS + h)) * NQ + n) * DH + dd;
                *(uint32_t*)(g_qh + idx) = pack_f16x2(v0 * SQSCALE, v1 * SQSCALE);
            } else if (MODE == 1) {
                int b = row >> 12, mr = row & 4095;
                if (c < 512) {
                    int h = c >> 6, dd = c & 63;
                    size_t idx = (((size_t)(b * HEADS + h)) * MK + mr + 1) * DH + dd;
                    hsplit(v0 * SQSCALE, &g_kh[idx],     &g_kl[idx]);
                    hsplit(v1 * SQSCALE, &g_kh[idx + 1], &g_kl[idx + 1]);
                } else {
                    int c2 = c - 512;
                    int h = c2 >> 6, dd = c2 & 63;
                    size_t idx = (((size_t)(b * HEADS + h)) * DH + dd) * MKP + (mr + 1);
                    hsplit(v0, &g_vth[idx],       &g_vtl[idx]);
                    hsplit(v1, &g_vth[idx + MKP], &g_vtl[idx + MKP]);
                }
            } else {
                *(float2*)(g_pj + (size_t)row * 512 + c) = make_float2(v0, v1);
            }
        }
    }
}

// ---------------- FA2 attention: fp16 2-term, 2 Q-subtiles, 128 threads -------
#define BUFSZ   36864
#define OFF_BM  73728
#define ATTN_SMEM 74272
#define NCH     65

__global__ void __launch_bounds__(128) attn_mma_kernel(const int* __restrict__ mask)
{
    extern __shared__ char smc[];
    const int tid  = threadIdx.x;
    const int wid  = tid >> 5;          // 0..3
    const int lane = tid & 31;
    const int g    = lane >> 2;
    const int qoff = (lane & 3) << 1;
    const int bh = blockIdx.y;
    const int b = bh >> 3, h = bh & 7;
    const int n0 = blockIdx.x << 7;     // 128 q-rows per CTA (2 subtiles of 64)

    uint32_t sbase = (uint32_t)__cvta_generic_to_shared(smc);
    uint32_t* bmap = (uint32_t*)(smc + OFF_BM);

    for (int w = tid; w < 130; w += 128) {
        uint32_t wv = 0;
        int jb = w * 32;
        #pragma unroll 8
        for (int i = 0; i < 32; i++) {
            int j = jb + i;
            int ok = (j == 0) ? 1 : ((j < MK) ? (mask[b * NCTX + j - 1] != 0) : 0);
            wv |= (uint32_t)ok << i;
        }
        bmap[w] = wv;
    }

    // Q fragments (fp16 single) for both subtiles
    uint32_t qf[2][4][4];
    #pragma unroll
    for (int t = 0; t < 2; t++) {
        const __half* q0 = g_qh + ((size_t)bh * NQ + n0 + t * 64 + wid * 16 + g) * DH;
        #pragma unroll
        for (int kt = 0; kt < 4; kt++) {
            int d0 = kt * 16 + qoff;
            qf[t][kt][0] = *(const uint32_t*)(q0 + d0);
            qf[t][kt][1] = *(const uint32_t*)(q0 + 8 * DH + d0);
            qf[t][kt][2] = *(const uint32_t*)(q0 + d0 + 8);
            qf[t][kt][3] = *(const uint32_t*)(q0 + 8 * DH + d0 + 8);
        }
    }

    const int lm = lane >> 3, li = lane & 7;
    const uint32_t boff = (uint32_t)((((lm >> 1) * 8 + li) * SPIT + (lm & 1) * 8) * 2);

    auto stage = [&](int c0s, int buf) {
        #pragma unroll
        for (int i = 0; i < 16; i++) {
            int idx = tid + i * 128;          // 0..2047
            int part = idx >> 9;              // 0=Kh 1=Kl 2=Vh 3=Vl
            int rem = idx & 511;
            int r = rem >> 3, cc = (rem & 7) << 3;
            uint32_t dst = sbase + (uint32_t)(buf * BUFSZ + part * 9216 + (r * SPIT + cc) * 2);
            if (part < 2) {
                int j = c0s + r;
                const __half* ks = ((part & 1) ? g_kl : g_kh)
                    + ((size_t)bh * MK + min(j, MK - 1)) * DH + cc;
                cp16z(dst, ks, j < MK);
            } else {
                const __half* vs = ((part & 1) ? g_vtl : g_vth)
                    + ((size_t)bh * DH + r) * MKP + c0s + cc;
                cp16(dst, vs);
            }
        }
    };

    stage(0, 0);
    CP_COMMIT();

    float oacc[2][8][4] = {};
    float sums[2][2] = {};

    for (int ch = 0; ch < NCH; ch++) {
        int c0 = ch << 6;
        CP_WAIT0();
        __syncthreads();
        if (ch + 1 < NCH) { stage((ch + 1) << 6, (ch + 1) & 1); CP_COMMIT(); }

        uint32_t uKh = sbase + (uint32_t)((ch & 1) * BUFSZ);
        uint32_t uKl = uKh + 9216;
        uint32_t uVh = uKh + 18432;
        uint32_t uVl = uKh + 27648;

        #pragma unroll
        for (int t = 0; t < 2; t++) {
            float sacc[8][4] = {};
            #pragma unroll
            for (int kt = 0; kt < 4; kt++) {
                #pragma unroll
                for (int ntp = 0; ntp < 4; ntp++) {
                    uint32_t off = (uint32_t)(ntp * 16 * SPIT * 2 + kt * 32) + boff;
                    uint32_t bhf[4], blf[4];
                    ldsm_x4(bhf, uKh + off);
                    ldsm_x4(blf, uKl + off);
                    mma16816f(sacc[2 * ntp],     qf[t][kt], bhf[0], bhf[1]);
                    mma16816f(sacc[2 * ntp + 1], qf[t][kt], bhf[2], bhf[3]);
                    mma16816f(sacc[2 * ntp],     qf[t][kt], blf[0], blf[1]);
                    mma16816f(sacc[2 * ntp + 1], qf[t][kt], blf[2], blf[3]);
                }
            }

            uint32_t pf[4][4];
            #pragma unroll
            for (int nt = 0; nt < 8; nt++) {
                int j0 = c0 + nt * 8 + qoff;
                uint32_t wb = bmap[j0 >> 5];
                int bi = j0 & 31;
                float m0 = (float)((wb >> bi) & 1u);
                float m1 = (float)((wb >> (bi + 1)) & 1u);
                float p0 = m0 * __expf(fminf(sacc[nt][0], 10.0f));
                float p1 = m1 * __expf(fminf(sacc[nt][1], 10.0f));
                float p2 = m0 * __expf(fminf(sacc[nt][2], 10.0f));
                float p3 = m1 * __expf(fminf(sacc[nt][3], 10.0f));
                float r0 = __half2float(__float2half(p0));
                float r1 = __half2float(__float2half(p1));
                float r2 = __half2float(__float2half(p2));
                float r3 = __half2float(__float2half(p3));
                sums[t][0] += r0 + r1;
                sums[t][1] += r2 + r3;
                int kt = nt >> 1, hf = (nt & 1) << 1;
                pf[kt][hf + 0] = pack_f16x2(r0, r1);
                pf[kt][hf + 1] = pack_f16x2(r2, r3);
            }

            #pragma unroll
            for (int kt = 0; kt < 4; kt++) {
                #pragma unroll
                for (int ntp = 0; ntp < 4; ntp++) {
                    uint32_t off = (uint32_t)(ntp * 16 * SPIT * 2 + kt * 32) + boff;
                    uint32_t vhf[4], vlf[4];
                    ldsm_x4(vhf, uVh + off);
                    ldsm_x4(vlf, uVl + off);
                    mma16816f(oacc[t][2 * ntp],     pf[kt], vhf[0], vhf[1]);
                    mma16816f(oacc[t][2 * ntp + 1], pf[kt], vhf[2], vhf[3]);
                    mma16816f(oacc[t][2 * ntp],     pf[kt], vlf[0], vlf[1]);
                    mma16816f(oacc[t][2 * ntp + 1], pf[kt], vlf[2], vlf[3]);
                }
            }
        }
    }

    #pragma unroll
    for (int t = 0; t < 2; t++) {
        float s0 = sums[t][0], s1 = sums[t][1];
        s0 += __shfl_xor_sync(0xffffffffu, s0, 1);
        s0 += __shfl_xor_sync(0xffffffffu, s0, 2);
        s1 += __shfl_xor_sync(0xffffffffu, s1, 1);
        s1 += __shfl_xor_sync(0xffffffffu, s1, 2);
        float inv0 = 1.0f / s0;
        float inv1 = 1.0f / s1;

        size_t base0 = ((size_t)(b * NQ) + n0 + t * 64 + wid * 16 + g) * INNER + h * DH;
        size_t base1 = base0 + 8 * INNER;
        #pragma unroll
        for (int nt = 0; nt < 8; nt++) {
            int c = nt * 8 + qoff;
            *(uint32_t*)(g_ao16 + base0 + c) = pack_f16x2(oacc[t][nt][0] * inv0, oacc[t][nt][1] * inv0);
            *(uint32_t*)(g_ao16 + base1 + c) = pack_f16x2(oacc[t][nt][2] * inv1, oacc[t][nt][3] * inv1);
        }
    }
}

// ---------------- launch ------------------------------------------------------
extern "C" void kernel_launch(void* const* d_in, const int* in_sizes, int n_in,
                              void* d_out, int out_size)
{
    const float* x       = (const float*)d_in[0];
    const float* context = (const float*)d_in[1];
    const int*   mask    = (const int*)  d_in[2];
    const float* g_x     = (const float*)d_in[3];
    const float* null_kv = (const float*)d_in[4];
    const float* Wq      = (const float*)d_in[5];
    const float* Wkv     = (const float*)d_in[6];
    const float* Wo      = (const float*)d_in[7];
    const float* g_outp  = (const float*)d_in[8];
    float* out = (float*)d_out;
    (void)in_sizes; (void)n_in; (void)out_size;

    __half *wqh, *wql, *wkvh, *wkvl, *woh, *wol;
    __half *xn16, *cx16, *ao16;
    cudaGetSymbolAddress((void**)&wqh,  g_wqh);
    cudaGetSymbolAddress((void**)&wql,  g_wql);
    cudaGetSymbolAddress((void**)&wkvh, g_wkvh);
    cudaGetSymbolAddress((void**)&wkvl, g_wkvl);
    cudaGetSymbolAddress((void**)&woh,  g_woh);
    cudaGetSymbolAddress((void**)&wol,  g_wol);
    cudaGetSymbolAddress((void**)&xn16, g_xn16);
    cudaGetSymbolAddress((void**)&cx16, g_cx16);
    cudaGetSymbolAddress((void**)&ao16, g_ao16);

    wsplit_kernel<<<dim3(8, 8),  256>>>(Wq,  wqh,  wql,  512);
    wsplit_kernel<<<dim3(16, 8), 256>>>(Wkv, wkvh, wkvl, 1024);
    wsplit_kernel<<<dim3(8, 8),  256>>>(Wo,  woh,  wol,  512);

    csplit_kernel<<<(BATCH * NCTX * DIMC) / 1024, 256>>>(context);
    ln_kernel<0><<<BATCH * NQ, 128>>>(x, g_x, nullptr);

    cudaFuncSetAttribute(proj_mma_kernel<0>, cudaFuncAttributeMaxDynamicSharedMemorySize, 2 * PBUF);
    cudaFuncSetAttribute(proj_mma_kernel<1>, cudaFuncAttributeMaxDynamicSharedMemorySize, 2 * PBUF);
    cudaFuncSetAttribute(proj_mma_kernel<2>, cudaFuncAttributeMaxDynamicSharedMemorySize, 2 * PBUF);

    proj_mma_kernel<0><<<dim3(8, 128),  128, 2 * PBUF>>>(xn16, wqh, wql);
    proj_mma_kernel<1><<<dim3(16, 128), 128, 2 * PBUF>>>(cx16, wkvh, wkvl);
    null_fill_kernel<<<BATCH * HEADS, DH>>>(null_kv);

    cudaFuncSetAttribute(attn_mma_kernel, cudaFuncAttributeMaxDynamicSharedMemorySize, ATTN_SMEM);
    attn_mma_kernel<<<dim3(NQ / 128, BATCH * HEADS), 128, ATTN_SMEM>>>(mask);

    proj_mma_kernel<2><<<dim3(8, 128), 128, 2 * PBUF>>>(ao16, woh, wol);
    ln_kernel<1><<<BATCH * NQ, 128>>>(nullptr, g_outp, out);
}

// round 13
// speedup vs baseline: 2.0150x; 1.4564x over previous
#include <cuda_runtime.h>
#include <cuda_bf16.h>
#include <cuda_fp16.h>
#include <math.h>
#include <stdint.h>

// ---------------- problem constants ----------------
#define BATCH   2
#define NQ      4096
#define NCTX    4096
#define DIMC    512
#define HEADS   8
#define DH      64
#define INNER   512
#define MK      4097         // keys incl. null
#define MKP     4160         // padded V^T stride (covers 65*64 tail, zeros in pad)
#define SQSCALE 0.35355339059327373f   // sqrt(64^-0.5)
#define SPIT    72           // smem pitch (16-bit elems) = 144B

// ---------------- scratch ----------------------------------------------------
__device__ float g_pj[(size_t)BATCH * NQ * DIMC];

// single-fp16 activations (A-operands for projections)
__device__ __half g_xn16[(size_t)BATCH * NQ * DIMC];
__device__ __half g_cx16[(size_t)BATCH * NCTX * DIMC];
__device__ __half g_ao16[(size_t)BATCH * NQ * INNER];

// attention operands: all single fp16 now.
__device__ __half g_qh[(size_t)BATCH * HEADS * NQ * DH];
__device__ __half g_kh[(size_t)BATCH * HEADS * MK * DH];
__device__ __half g_vth[(size_t)BATCH * HEADS * DH * MKP];  // [bh][d][key]

// transposed/split weights: Wt[n][k], k = 512 (fp16 hi/lo — weights stay split)
__device__ __half g_wqh[512 * 512],  g_wql[512 * 512];
__device__ __half g_wkvh[1024 * 512], g_wkvl[1024 * 512];
__device__ __half g_woh[512 * 512],  g_wol[512 * 512];

// ---------------- helpers -----------------------------------------------------
__device__ __forceinline__ void hsplit(float v, __half* hi, __half* lo) {
    __half h = __float2half(v);
    *hi = h;
    *lo = __float2half(v - __half2float(h));
}
__device__ __forceinline__ uint32_t pack_f16x2(float lo_elem, float hi_elem) {
    uint32_t r;
    asm("cvt.rn.f16x2.f32 %0, %1, %2;" : "=r"(r) : "f"(hi_elem), "f"(lo_elem));
    return r;
}
// fp16 mma
__device__ __forceinline__ void mma16816f(float* d, const uint32_t* a, uint32_t b0, uint32_t b1) {
    asm volatile("mma.sync.aligned.m16n8k16.row.col.f32.f16.f16.f32 "
        "{%0,%1,%2,%3}, {%4,%5,%6,%7}, {%8,%9}, {%0,%1,%2,%3};"
        : "+f"(d[0]), "+f"(d[1]), "+f"(d[2]), "+f"(d[3])
        : "r"(a[0]), "r"(a[1]), "r"(a[2]), "r"(a[3]), "r"(b0), "r"(b1));
}
__device__ __forceinline__ void ldsm_x4(uint32_t* r, uint32_t addr) {
    asm volatile("ldmatrix.sync.aligned.m8n8.x4.shared.b16 {%0,%1,%2,%3}, [%4];"
        : "=r"(r[0]), "=r"(r[1]), "=r"(r[2]), "=r"(r[3]) : "r"(addr));
}
__device__ __forceinline__ void cp16(uint32_t dst, const void* src) {
    asm volatile("cp.async.cg.shared.global [%0], [%1], 16;"
        :: "r"(dst), "l"(src) : "memory");
}
__device__ __forceinline__ void cp16z(uint32_t dst, const void* src, int ok) {
    int sz = ok ? 16 : 0;
    asm volatile("cp.async.cg.shared.global [%0], [%1], 16, %2;"
        :: "r"(dst), "l"(src), "r"(sz) : "memory");
}
#define CP_COMMIT() asm volatile("cp.async.commit_group;" ::: "memory")
#define CP_WAIT0()  asm volatile("cp.async.wait_group 0;" ::: "memory")

// ---------------- layernorm --------------------------------------------------
template <int WHICH>
__global__ void __launch_bounds__(128) ln_kernel(const float* __restrict__ inp,
                                                 const float* __restrict__ g,
                                                 float* __restrict__ outp)
{
    const float* in = (WHICH == 0) ? inp : g_pj;
    int row = blockIdx.x;
    int tid = threadIdx.x;
    const float* rptr = in + (size_t)row * DIMC;

    float4 v = reinterpret_cast<const float4*>(rptr)[tid];
    float s  = v.x + v.y + v.z + v.w;
    float ss = v.x * v.x + v.y * v.y + v.z * v.z + v.w * v.w;
    #pragma unroll
    for (int o = 16; o > 0; o >>= 1) {
        s  += __shfl_down_sync(0xffffffffu, s,  o);
        ss += __shfl_down_sync(0xffffffffu, ss, o);
    }
    __shared__ float sb[8];
    int wid = tid >> 5, lane = tid & 31;
    if (lane == 0) { sb[wid] = s; sb[4 + wid] = ss; }
    __syncthreads();
    float S  = sb[0] + sb[1] + sb[2] + sb[3];
    float SS = sb[4] + sb[5] + sb[6] + sb[7];
    float mean = S * (1.0f / DIMC);
    float var  = SS * (1.0f / DIMC) - mean * mean;
    float rstd = rsqrtf(var + 1e-5f);
    float4 gv = reinterpret_cast<const float4*>(g)[tid];
    float o0 = (v.x - mean) * rstd * gv.x;
    float o1 = (v.y - mean) * rstd * gv.y;
    float o2 = (v.z - mean) * rstd * gv.z;
    float o3 = (v.w - mean) * rstd * gv.w;
    if (WHICH == 0) {
        uint2 pk;
        pk.x = pack_f16x2(o0, o1);
        pk.y = pack_f16x2(o2, o3);
        *(uint2*)(g_xn16 + (size_t)row * DIMC + tid * 4) = pk;
    } else {
        float4 o4 = make_float4(o0, o1, o2, o3);
        reinterpret_cast<float4*>(outp + (size_t)row * DIMC)[tid] = o4;
    }
}

// ---------------- context convert (fp32 -> fp16 single) ----------------------
__global__ void __launch_bounds__(256) csplit_kernel(const float* __restrict__ src)
{
    size_t i4 = ((size_t)blockIdx.x * 256 + threadIdx.x);
    float4 v = reinterpret_cast<const float4*>(src)[i4];
    uint2 pk;
    pk.x = pack_f16x2(v.x, v.y);
    pk.y = pack_f16x2(v.z, v.w);
    *(uint2*)(g_cx16 + i4 * 4) = pk;
}

// ---------------- null kv fill -----------------------------------------------
__global__ void null_fill_kernel(const float* __restrict__ null_kv)
{
    int bh = blockIdx.x;
    int d  = threadIdx.x;
    g_kh[(size_t)bh * MK * DH + d] = __float2half(null_kv[d] * SQSCALE);
    g_vth[((size_t)bh * DH + d) * MKP + 0] = __float2half(null_kv[DH + d]);
}

// ---------------- weight transpose + split: Wt[n][k] (fp16 hi/lo) ------------
__global__ void __launch_bounds__(256) wsplit_kernel(const float* __restrict__ W,
                                                     __half* __restrict__ Th,
                                                     __half* __restrict__ Tl,
                                                     int N)
{
    __shared__ float s[64][65];
    int tid = threadIdx.x;
    int n0 = blockIdx.x * 64;
    int k0 = blockIdx.y * 64;
    #pragma unroll
    for (int i = 0; i < 16; i++) {
        int idx = tid + i * 256;
        int k = idx >> 6, n = idx & 63;
        s[k][n] = W[(size_t)(k0 + k) * N + n0 + n];
    }
    __syncthreads();
    #pragma unroll
    for (int i = 0; i < 16; i++) {
        int idx = tid + i * 256;
        int n = idx >> 6, k = idx & 63;
        size_t o = (size_t)(n0 + n) * 512 + k0 + k;
        hsplit(s[k][n], &Th[o], &Tl[o]);
    }
}

// ---------------- tensor-core projection GEMM: fp16 2-term, cp.async 2-buffer
#define PBUF 27648
template <int MODE>
__global__ void __launch_bounds__(128) proj_mma_kernel(const __half* __restrict__ A16,
                                                       const __half* __restrict__ Wth,
                                                       const __half* __restrict__ Wtl)
{
    extern __shared__ char smc[];
    uint32_t sbase = (uint32_t)__cvta_generic_to_shared(smc);

    int tid  = threadIdx.x;
    int wid  = tid >> 5;
    int lane = tid & 31;
    int g    = lane >> 2;
    int qoff = (lane & 3) << 1;
    int row0 = blockIdx.y * 64;
    int col0 = blockIdx.x * 64;

    int lm = lane >> 3, li = lane & 7;
    uint32_t aoff = (uint32_t)(((wid * 16 + (lm & 1) * 8 + li) * SPIT + (lm >> 1) * 8) * 2);
    uint32_t boff = (uint32_t)((((lm >> 1) * 8 + li) * SPIT + (lm & 1) * 8) * 2);

    auto stage = [&](int k0, int buf) {
        #pragma unroll
        for (int i = 0; i < 12; i++) {
            int idx = tid + i * 128;          // 0..1535
            int part = idx >> 9;              // 0=A 1=Bh 2=Bl
            int rem = idx & 511;
            int r = rem >> 3, cc = (rem & 7) << 3;
            uint32_t dst = sbase + (uint32_t)(buf * PBUF + part * 9216 + (r * SPIT + cc) * 2);
            const __half* src;
            if (part == 0)      src = A16 + (size_t)(row0 + r) * 512 + k0 + cc;
            else if (part == 1) src = Wth + (size_t)(col0 + r) * 512 + k0 + cc;
            else                src = Wtl + (size_t)(col0 + r) * 512 + k0 + cc;
            cp16(dst, src);
        }
    };

    stage(0, 0);
    CP_COMMIT();

    float oacc[8][4] = {};

    for (int kc = 0; kc < 8; kc++) {
        CP_WAIT0();
        __syncthreads();
        if (kc + 1 < 8) { stage((kc + 1) << 6, (kc + 1) & 1); CP_COMMIT(); }

        uint32_t uA  = sbase + (uint32_t)((kc & 1) * PBUF);
        uint32_t uBh = uA + 9216;
        uint32_t uBl = uA + 18432;

        uint32_t af[4][4];
        #pragma unroll
        for (int kt = 0; kt < 4; kt++)
            ldsm_x4(af[kt], uA + (uint32_t)(kt * 32) + aoff);

        #pragma unroll
        for (int kt = 0; kt < 4; kt++) {
            #pragma unroll
            for (int ntp = 0; ntp < 4; ntp++) {
                uint32_t off = (uint32_t)(ntp * 16 * SPIT * 2 + kt * 32) + boff;
                uint32_t bhf[4], blf[4];
                ldsm_x4(bhf, uBh + off);
                ldsm_x4(blf, uBl + off);
                mma16816f(oacc[2 * ntp],     af[kt], bhf[0], bhf[1]);
                mma16816f(oacc[2 * ntp + 1], af[kt], bhf[2], bhf[3]);
                mma16816f(oacc[2 * ntp],     af[kt], blf[0], blf[1]);
                mma16816f(oacc[2 * ntp + 1], af[kt], blf[2], blf[3]);
            }
        }
    }

    #pragma unroll
    for (int nt = 0; nt < 8; nt++) {
        #pragma unroll
        for (int half = 0; half < 2; half++) {
            int row = row0 + wid * 16 + g + half * 8;
            float v0 = oacc[nt][half * 2 + 0];
            float v1 = oacc[nt][half * 2 + 1];
            int c = col0 + nt * 8 + qoff;
            if (MODE == 0) {
                int b = row >> 12, n = row & 4095;
                int h = c >> 6, dd = c & 63;
                size_t idx = (((size_t)(b * HEADS + h)) * NQ + n) * DH + dd;
                *(uint32_t*)(g_qh + idx) = pack_f16x2(v0 * SQSCALE, v1 * SQSCALE);
            } else if (MODE == 1) {
                int b = row >> 12, mr = row & 4095;
                if (c < 512) {
                    int h = c >> 6, dd = c & 63;
                    size_t idx = (((size_t)(b * HEADS + h)) * MK + mr + 1) * DH + dd;
                    *(uint32_t*)(g_kh + idx) = pack_f16x2(v0 * SQSCALE, v1 * SQSCALE);
                } else {
                    int c2 = c - 512;
                    int h = c2 >> 6, dd = c2 & 63;
                    size_t idx = (((size_t)(b * HEADS + h)) * DH + dd) * MKP + (mr + 1);
                    g_vth[idx]       = __float2half(v0);
                    g_vth[idx + MKP] = __float2half(v1);
                }
            } else {
                *(float2*)(g_pj + (size_t)row * 512 + c) = make_float2(v0, v1);
            }
        }
    }
}

// ---------------- FA2 attention: fp16 single K/V, 2 Q-subtiles, 128 threads ---
// buffer parts: K(0) V(9216); BUFSZ=18432, x2; bitmap at 36864.
#define BUFSZ   18432
#define OFF_BM  36864
#define ATTN_SMEM 37408
#define NCH     65

__global__ void __launch_bounds__(128) attn_mma_kernel(const int* __restrict__ mask)
{
    extern __shared__ char smc[];
    const int tid  = threadIdx.x;
    const int wid  = tid >> 5;          // 0..3
    const int lane = tid & 31;
    const int g    = lane >> 2;
    const int qoff = (lane & 3) << 1;
    const int bh = blockIdx.y;
    const int b = bh >> 3, h = bh & 7;
    const int n0 = blockIdx.x << 7;     // 128 q-rows per CTA (2 subtiles of 64)

    uint32_t sbase = (uint32_t)__cvta_generic_to_shared(smc);
    uint32_t* bmap = (uint32_t*)(smc + OFF_BM);

    for (int w = tid; w < 130; w += 128) {
        uint32_t wv = 0;
        int jb = w * 32;
        #pragma unroll 8
        for (int i = 0; i < 32; i++) {
            int j = jb + i;
            int ok = (j == 0) ? 1 : ((j < MK) ? (mask[b * NCTX + j - 1] != 0) : 0);
            wv |= (uint32_t)ok << i;
        }
        bmap[w] = wv;
    }

    // Q fragments (fp16 single) for both subtiles
    uint32_t qf[2][4][4];
    #pragma unroll
    for (int t = 0; t < 2; t++) {
        const __half* q0 = g_qh + ((size_t)bh * NQ + n0 + t * 64 + wid * 16 + g) * DH;
        #pragma unroll
        for (int kt = 0; kt < 4; kt++) {
            int d0 = kt * 16 + qoff;
            qf[t][kt][0] = *(const uint32_t*)(q0 + d0);
            qf[t][kt][1] = *(const uint32_t*)(q0 + 8 * DH + d0);
            qf[t][kt][2] = *(const uint32_t*)(q0 + d0 + 8);
            qf[t][kt][3] = *(const uint32_t*)(q0 + 8 * DH + d0 + 8);
        }
    }

    const int lm = lane >> 3, li = lane & 7;
    const uint32_t boff = (uint32_t)((((lm >> 1) * 8 + li) * SPIT + (lm & 1) * 8) * 2);

    auto stage = [&](int c0s, int buf) {
        #pragma unroll
        for (int i = 0; i < 8; i++) {
            int idx = tid + i * 128;          // 0..1023
            int part = idx >> 9;              // 0=K 1=V
            int rem = idx & 511;
            int r = rem >> 3, cc = (rem & 7) << 3;
            uint32_t dst = sbase + (uint32_t)(buf * BUFSZ + part * 9216 + (r * SPIT + cc) * 2);
            if (part == 0) {
                int j = c0s + r;
                const __half* ks = g_kh + ((size_t)bh * MK + min(j, MK - 1)) * DH + cc;
                cp16z(dst, ks, j < MK);
            } else {
                const __half* vs = g_vth + ((size_t)bh * DH + r) * MKP + c0s + cc;
                cp16(dst, vs);
            }
        }
    };

    stage(0, 0);
    CP_COMMIT();

    float oacc[2][8][4] = {};
    float sums[2][2] = {};

    for (int ch = 0; ch < NCH; ch++) {
        int c0 = ch << 6;
        CP_WAIT0();
        __syncthreads();
        if (ch + 1 < NCH) { stage((ch + 1) << 6, (ch + 1) & 1); CP_COMMIT(); }

        uint32_t uK = sbase + (uint32_t)((ch & 1) * BUFSZ);
        uint32_t uV = uK + 9216;

        #pragma unroll
        for (int t = 0; t < 2; t++) {
            float sacc[8][4] = {};
            #pragma unroll
            for (int kt = 0; kt < 4; kt++) {
                #pragma unroll
                for (int ntp = 0; ntp < 4; ntp++) {
                    uint32_t off = (uint32_t)(ntp * 16 * SPIT * 2 + kt * 32) + boff;
                    uint32_t bf[4];
                    ldsm_x4(bf, uK + off);
                    mma16816f(sacc[2 * ntp],     qf[t][kt], bf[0], bf[1]);
                    mma16816f(sacc[2 * ntp + 1], qf[t][kt], bf[2], bf[3]);
                }
            }

            uint32_t pf[4][4];
            #pragma unroll
            for (int nt = 0; nt < 8; nt++) {
                int j0 = c0 + nt * 8 + qoff;
                uint32_t wb = bmap[j0 >> 5];
                int bi = j0 & 31;
                float m0 = (float)((wb >> bi) & 1u);
                float m1 = (float)((wb >> (bi + 1)) & 1u);
                float p0 = m0 * __expf(fminf(sacc[nt][0], 10.0f));
                float p1 = m1 * __expf(fminf(sacc[nt][1], 10.0f));
                float p2 = m0 * __expf(fminf(sacc[nt][2], 10.0f));
                float p3 = m1 * __expf(fminf(sacc[nt][3], 10.0f));
                float r0 = __half2float(__float2half(p0));
                float r1 = __half2float(__float2half(p1));
                float r2 = __half2float(__float2half(p2));
                float r3 = __half2float(__float2half(p3));
                sums[t][0] += r0 + r1;
                sums[t][1] += r2 + r3;
                int kt = nt >> 1, hf = (nt & 1) << 1;
                pf[kt][hf + 0] = pack_f16x2(r0, r1);
                pf[kt][hf + 1] = pack_f16x2(r2, r3);
            }

            #pragma unroll
            for (int kt = 0; kt < 4; kt++) {
                #pragma unroll
                for (int ntp = 0; ntp < 4; ntp++) {
                    uint32_t off = (uint32_t)(ntp * 16 * SPIT * 2 + kt * 32) + boff;
                    uint32_t vf[4];
                    ldsm_x4(vf, uV + off);
                    mma16816f(oacc[t][2 * ntp],     pf[kt], vf[0], vf[1]);
                    mma16816f(oacc[t][2 * ntp + 1], pf[kt], vf[2], vf[3]);
                }
            }
        }
    }

    #pragma unroll
    for (int t = 0; t < 2; t++) {
        float s0 = sums[t][0], s1 = sums[t][1];
        s0 += __shfl_xor_sync(0xffffffffu, s0, 1);
        s0 += __shfl_xor_sync(0xffffffffu, s0, 2);
        s1 += __shfl_xor_sync(0xffffffffu, s1, 1);
        s1 += __shfl_xor_sync(0xffffffffu, s1, 2);
        float inv0 = 1.0f / s0;
        float inv1 = 1.0f / s1;

        size_t base0 = ((size_t)(b * NQ) + n0 + t * 64 + wid * 16 + g) * INNER + h * DH;
        size_t base1 = base0 + 8 * INNER;
        #pragma unroll
        for (int nt = 0; nt < 8; nt++) {
            int c = nt * 8 + qoff;
            *(uint32_t*)(g_ao16 + base0 + c) = pack_f16x2(oacc[t][nt][0] * inv0, oacc[t][nt][1] * inv0);
            *(uint32_t*)(g_ao16 + base1 + c) = pack_f16x2(oacc[t][nt][2] * inv1, oacc[t][nt][3] * inv1);
        }
    }
}

// ---------------- launch ------------------------------------------------------
extern "C" void kernel_launch(void* const* d_in, const int* in_sizes, int n_in,
                              void* d_out, int out_size)
{
    const float* x       = (const float*)d_in[0];
    const float* context = (const float*)d_in[1];
    const int*   mask    = (const int*)  d_in[2];
    const float* g_x     = (const float*)d_in[3];
    const float* null_kv = (const float*)d_in[4];
    const float* Wq      = (const float*)d_in[5];
    const float* Wkv     = (const float*)d_in[6];
    const float* Wo      = (const float*)d_in[7];
    const float* g_outp  = (const float*)d_in[8];
    float* out = (float*)d_out;
    (void)in_sizes; (void)n_in; (void)out_size;

    __half *wqh, *wql, *wkvh, *wkvl, *woh, *wol;
    __half *xn16, *cx16, *ao16;
    cudaGetSymbolAddress((void**)&wqh,  g_wqh);
    cudaGetSymbolAddress((void**)&wql,  g_wql);
    cudaGetSymbolAddress((void**)&wkvh, g_wkvh);
    cudaGetSymbolAddress((void**)&wkvl, g_wkvl);
    cudaGetSymbolAddress((void**)&woh,  g_woh);
    cudaGetSymbolAddress((void**)&wol,  g_wol);
    cudaGetSymbolAddress((void**)&xn16, g_xn16);
    cudaGetSymbolAddress((void**)&cx16, g_cx16);
    cudaGetSymbolAddress((void**)&ao16, g_ao16);

    wsplit_kernel<<<dim3(8, 8),  256>>>(Wq,  wqh,  wql,  512);
    wsplit_kernel<<<dim3(16, 8), 256>>>(Wkv, wkvh, wkvl, 1024);
    wsplit_kernel<<<dim3(8, 8),  256>>>(Wo,  woh,  wol,  512);

    csplit_kernel<<<(BATCH * NCTX * DIMC) / 1024, 256>>>(context);
    ln_kernel<0><<<BATCH * NQ, 128>>>(x, g_x, nullptr);

    cudaFuncSetAttribute(proj_mma_kernel<0>, cudaFuncAttributeMaxDynamicSharedMemorySize, 2 * PBUF);
    cudaFuncSetAttribute(proj_mma_kernel<1>, cudaFuncAttributeMaxDynamicSharedMemorySize, 2 * PBUF);
    cudaFuncSetAttribute(proj_mma_kernel<2>, cudaFuncAttributeMaxDynamicSharedMemorySize, 2 * PBUF);

    proj_mma_kernel<0><<<dim3(8, 128),  128, 2 * PBUF>>>(xn16, wqh, wql);
    proj_mma_kernel<1><<<dim3(16, 128), 128, 2 * PBUF>>>(cx16, wkvh, wkvl);
    null_fill_kernel<<<BATCH * HEADS, DH>>>(null_kv);

    cudaFuncSetAttribute(attn_mma_kernel, cudaFuncAttributeMaxDynamicSharedMemorySize, ATTN_SMEM);
    attn_mma_kernel<<<dim3(NQ / 128, BATCH * HEADS), 128, ATTN_SMEM>>>(mask);

    proj_mma_kernel<2><<<dim3(8, 128), 128, 2 * PBUF>>>(ao16, woh, wol);
    ln_kernel<1><<<BATCH * NQ, 128>>>(nullptr, g_outp, out);
}

// round 14
// speedup vs baseline: 2.2092x; 1.0964x over previous
#include <cuda_runtime.h>
#include <cuda_bf16.h>
#include <cuda_fp16.h>
#include <math.h>
#include <stdint.h>

// ---------------- problem constants ----------------
#define BATCH   2
#define NQ      4096
#define NCTX    4096
#define DIMC    512
#define HEADS   8
#define DH      64
#define INNER   512
#define MK      4097         // keys incl. null
#define MKP     4160         // padded V^T stride (covers 65*64 tail, zeros in pad)
#define SQSCALE 0.35355339059327373f   // sqrt(64^-0.5)
#define SPIT    72           // smem pitch (16-bit elems) = 144B

// ---------------- scratch ----------------------------------------------------
__device__ float g_pj[(size_t)BATCH * NQ * DIMC];

// single-fp16 activations (A-operands for projections)
__device__ __half g_xn16[(size_t)BATCH * NQ * DIMC];
__device__ __half g_cx16[(size_t)BATCH * NCTX * DIMC];
__device__ __half g_ao16[(size_t)BATCH * NQ * INNER];

// attention operands: all single fp16.
__device__ __half g_qh[(size_t)BATCH * HEADS * NQ * DH];
__device__ __half g_kh[(size_t)BATCH * HEADS * MK * DH];
__device__ __half g_vth[(size_t)BATCH * HEADS * DH * MKP];  // [bh][d][key]

// transposed weights: Wt[n][k], k = 512 (single fp16)
__device__ __half g_wq16[512 * 512];
__device__ __half g_wkv16[1024 * 512];
__device__ __half g_wo16[512 * 512];

// ---------------- helpers -----------------------------------------------------
__device__ __forceinline__ uint32_t pack_f16x2(float lo_elem, float hi_elem) {
    uint32_t r;
    asm("cvt.rn.f16x2.f32 %0, %1, %2;" : "=r"(r) : "f"(hi_elem), "f"(lo_elem));
    return r;
}
// fp16 mma
__device__ __forceinline__ void mma16816f(float* d, const uint32_t* a, uint32_t b0, uint32_t b1) {
    asm volatile("mma.sync.aligned.m16n8k16.row.col.f32.f16.f16.f32 "
        "{%0,%1,%2,%3}, {%4,%5,%6,%7}, {%8,%9}, {%0,%1,%2,%3};"
        : "+f"(d[0]), "+f"(d[1]), "+f"(d[2]), "+f"(d[3])
        : "r"(a[0]), "r"(a[1]), "r"(a[2]), "r"(a[3]), "r"(b0), "r"(b1));
}
__device__ __forceinline__ void ldsm_x4(uint32_t* r, uint32_t addr) {
    asm volatile("ldmatrix.sync.aligned.m8n8.x4.shared.b16 {%0,%1,%2,%3}, [%4];"
        : "=r"(r[0]), "=r"(r[1]), "=r"(r[2]), "=r"(r[3]) : "r"(addr));
}
__device__ __forceinline__ void cp16(uint32_t dst, const void* src) {
    asm volatile("cp.async.cg.shared.global [%0], [%1], 16;"
        :: "r"(dst), "l"(src) : "memory");
}
__device__ __forceinline__ void cp16z(uint32_t dst, const void* src, int ok) {
    int sz = ok ? 16 : 0;
    asm volatile("cp.async.cg.shared.global [%0], [%1], 16, %2;"
        :: "r"(dst), "l"(src), "r"(sz) : "memory");
}
#define CP_COMMIT() asm volatile("cp.async.commit_group;" ::: "memory")
#define CP_WAIT0()  asm volatile("cp.async.wait_group 0;" ::: "memory")

// ---------------- layernorm --------------------------------------------------
template <int WHICH>
__global__ void __launch_bounds__(128) ln_kernel(const float* __restrict__ inp,
                                                 const float* __restrict__ g,
                                                 float* __restrict__ outp)
{
    const float* in = (WHICH == 0) ? inp : g_pj;
    int row = blockIdx.x;
    int tid = threadIdx.x;
    const float* rptr = in + (size_t)row * DIMC;

    float4 v = reinterpret_cast<const float4*>(rptr)[tid];
    float s  = v.x + v.y + v.z + v.w;
    float ss = v.x * v.x + v.y * v.y + v.z * v.z + v.w * v.w;
    #pragma unroll
    for (int o = 16; o > 0; o >>= 1) {
        s  += __shfl_down_sync(0xffffffffu, s,  o);
        ss += __shfl_down_sync(0xffffffffu, ss, o);
    }
    __shared__ float sb[8];
    int wid = tid >> 5, lane = tid & 31;
    if (lane == 0) { sb[wid] = s; sb[4 + wid] = ss; }
    __syncthreads();
    float S  = sb[0] + sb[1] + sb[2] + sb[3];
    float SS = sb[4] + sb[5] + sb[6] + sb[7];
    float mean = S * (1.0f / DIMC);
    float var  = SS * (1.0f / DIMC) - mean * mean;
    float rstd = rsqrtf(var + 1e-5f);
    float4 gv = reinterpret_cast<const float4*>(g)[tid];
    float o0 = (v.x - mean) * rstd * gv.x;
    float o1 = (v.y - mean) * rstd * gv.y;
    float o2 = (v.z - mean) * rstd * gv.z;
    float o3 = (v.w - mean) * rstd * gv.w;
    if (WHICH == 0) {
        uint2 pk;
        pk.x = pack_f16x2(o0, o1);
        pk.y = pack_f16x2(o2, o3);
        *(uint2*)(g_xn16 + (size_t)row * DIMC + tid * 4) = pk;
    } else {
        float4 o4 = make_float4(o0, o1, o2, o3);
        reinterpret_cast<float4*>(outp + (size_t)row * DIMC)[tid] = o4;
    }
}

// ---------------- context convert (fp32 -> fp16 single) ----------------------
__global__ void __launch_bounds__(256) csplit_kernel(const float* __restrict__ src)
{
    size_t i4 = ((size_t)blockIdx.x * 256 + threadIdx.x);
    float4 v = reinterpret_cast<const float4*>(src)[i4];
    uint2 pk;
    pk.x = pack_f16x2(v.x, v.y);
    pk.y = pack_f16x2(v.z, v.w);
    *(uint2*)(g_cx16 + i4 * 4) = pk;
}

// ---------------- null kv fill -----------------------------------------------
__global__ void null_fill_kernel(const float* __restrict__ null_kv)
{
    int bh = blockIdx.x;
    int d  = threadIdx.x;
    g_kh[(size_t)bh * MK * DH + d] = __float2half(null_kv[d] * SQSCALE);
    g_vth[((size_t)bh * DH + d) * MKP + 0] = __float2half(null_kv[DH + d]);
}

// ---------------- weight transpose + convert: Wt[n][k] single fp16 -----------
__global__ void __launch_bounds__(256) wconv_kernel(const float* __restrict__ W,
                                                    __half* __restrict__ T,
                                                    int N)
{
    __shared__ float s[64][65];
    int tid = threadIdx.x;
    int n0 = blockIdx.x * 64;
    int k0 = blockIdx.y * 64;
    #pragma unroll
    for (int i = 0; i < 16; i++) {
        int idx = tid + i * 256;
        int k = idx >> 6, n = idx & 63;
        s[k][n] = W[(size_t)(k0 + k) * N + n0 + n];
    }
    __syncthreads();
    #pragma unroll
    for (int i = 0; i < 8; i++) {
        int idx = tid + i * 256;         // 2048 pair-slots
        int n = idx >> 5, k2 = (idx & 31) << 1;
        size_t o = (size_t)(n0 + n) * 512 + k0 + k2;
        *(uint32_t*)(T + o) = pack_f16x2(s[k2][n], s[k2 + 1][n]);
    }
}

// ---------------- tensor-core projection GEMM: fp16 single, cp.async 2-buffer
// buffer parts: 0=A 1=B, each 9216B; PBUF 18432, x2 = 36864B dyn smem.
#define PBUF 18432
template <int MODE>
__global__ void __launch_bounds__(128) proj_mma_kernel(const __half* __restrict__ A16,
                                                       const __half* __restrict__ Wt)
{
    extern __shared__ char smc[];
    uint32_t sbase = (uint32_t)__cvta_generic_to_shared(smc);

    int tid  = threadIdx.x;
    int wid  = tid >> 5;
    int lane = tid & 31;
    int g    = lane >> 2;
    int qoff = (lane & 3) << 1;
    int row0 = blockIdx.y * 64;
    int col0 = blockIdx.x * 64;

    int lm = lane >> 3, li = lane & 7;
    uint32_t aoff = (uint32_t)(((wid * 16 + (lm & 1) * 8 + li) * SPIT + (lm >> 1) * 8) * 2);
    uint32_t boff = (uint32_t)((((lm >> 1) * 8 + li) * SPIT + (lm & 1) * 8) * 2);

    auto stage = [&](int k0, int buf) {
        #pragma unroll
        for (int i = 0; i < 8; i++) {
            int idx = tid + i * 128;          // 0..1023
            int part = idx >> 9;              // 0=A 1=B
            int rem = idx & 511;
            int r = rem >> 3, cc = (rem & 7) << 3;
            uint32_t dst = sbase + (uint32_t)(buf * PBUF + part * 9216 + (r * SPIT + cc) * 2);
            const __half* src = (part == 0)
                ? A16 + (size_t)(row0 + r) * 512 + k0 + cc
                : Wt  + (size_t)(col0 + r) * 512 + k0 + cc;
            cp16(dst, src);
        }
    };

    stage(0, 0);
    CP_COMMIT();

    float oacc[8][4] = {};

    for (int kc = 0; kc < 8; kc++) {
        CP_WAIT0();
        __syncthreads();
        if (kc + 1 < 8) { stage((kc + 1) << 6, (kc + 1) & 1); CP_COMMIT(); }

        uint32_t uA = sbase + (uint32_t)((kc & 1) * PBUF);
        uint32_t uB = uA + 9216;

        uint32_t af[4][4];
        #pragma unroll
        for (int kt = 0; kt < 4; kt++)
            ldsm_x4(af[kt], uA + (uint32_t)(kt * 32) + aoff);

        #pragma unroll
        for (int kt = 0; kt < 4; kt++) {
            #pragma unroll
            for (int ntp = 0; ntp < 4; ntp++) {
                uint32_t off = (uint32_t)(ntp * 16 * SPIT * 2 + kt * 32) + boff;
                uint32_t bf[4];
                ldsm_x4(bf, uB + off);
                mma16816f(oacc[2 * ntp],     af[kt], bf[0], bf[1]);
                mma16816f(oacc[2 * ntp + 1], af[kt], bf[2], bf[3]);
            }
        }
    }

    #pragma unroll
    for (int nt = 0; nt < 8; nt++) {
        #pragma unroll
        for (int half = 0; half < 2; half++) {
            int row = row0 + wid * 16 + g + half * 8;
            float v0 = oacc[nt][half * 2 + 0];
            float v1 = oacc[nt][half * 2 + 1];
            int c = col0 + nt * 8 + qoff;
            if (MODE == 0) {
                int b = row >> 12, n = row & 4095;
                int h = c >> 6, dd = c & 63;
                size_t idx = (((size_t)(b * HEADS + h)) * NQ + n) * DH + dd;
                *(uint32_t*)(g_qh + idx) = pack_f16x2(v0 * SQSCALE, v1 * SQSCALE);
            } else if (MODE == 1) {
                int b = row >> 12, mr = row & 4095;
                if (c < 512) {
                    int h = c >> 6, dd = c & 63;
                    size_t idx = (((size_t)(b * HEADS + h)) * MK + mr + 1) * DH + dd;
                    *(uint32_t*)(g_kh + idx) = pack_f16x2(v0 * SQSCALE, v1 * SQSCALE);
                } else {
                    int c2 = c - 512;
                    int h = c2 >> 6, dd = c2 & 63;
                    size_t idx = (((size_t)(b * HEADS + h)) * DH + dd) * MKP + (mr + 1);
                    g_vth[idx]       = __float2half(v0);
                    g_vth[idx + MKP] = __float2half(v1);
                }
            } else {
                *(float2*)(g_pj + (size_t)row * 512 + c) = make_float2(v0, v1);
            }
        }
    }
}

// ---------------- FA2 attention: fp16 single K/V, 2 Q-subtiles, 128 threads ---
#define BUFSZ   18432
#define OFF_BM  36864
#define ATTN_SMEM 37408
#define NCH     65

__global__ void __launch_bounds__(128) attn_mma_kernel(const int* __restrict__ mask)
{
    extern __shared__ char smc[];
    const int tid  = threadIdx.x;
    const int wid  = tid >> 5;          // 0..3
    const int lane = tid & 31;
    const int g    = lane >> 2;
    const int qoff = (lane & 3) << 1;
    const int bh = blockIdx.y;
    const int b = bh >> 3, h = bh & 7;
    const int n0 = blockIdx.x << 7;     // 128 q-rows per CTA (2 subtiles of 64)

    uint32_t sbase = (uint32_t)__cvta_generic_to_shared(smc);
    uint32_t* bmap = (uint32_t*)(smc + OFF_BM);

    for (int w = tid; w < 130; w += 128) {
        uint32_t wv = 0;
        int jb = w * 32;
        #pragma unroll 8
        for (int i = 0; i < 32; i++) {
            int j = jb + i;
            int ok = (j == 0) ? 1 : ((j < MK) ? (mask[b * NCTX + j - 1] != 0) : 0);
            wv |= (uint32_t)ok << i;
        }
        bmap[w] = wv;
    }

    // Q fragments (fp16 single) for both subtiles
    uint32_t qf[2][4][4];
    #pragma unroll
    for (int t = 0; t < 2; t++) {
        const __half* q0 = g_qh + ((size_t)bh * NQ + n0 + t * 64 + wid * 16 + g) * DH;
        #pragma unroll
        for (int kt = 0; kt < 4; kt++) {
            int d0 = kt * 16 + qoff;
            qf[t][kt][0] = *(const uint32_t*)(q0 + d0);
            qf[t][kt][1] = *(const uint32_t*)(q0 + 8 * DH + d0);
            qf[t][kt][2] = *(const uint32_t*)(q0 + d0 + 8);
            qf[t][kt][3] = *(const uint32_t*)(q0 + 8 * DH + d0 + 8);
        }
    }

    const int lm = lane >> 3, li = lane & 7;
    const uint32_t boff = (uint32_t)((((lm >> 1) * 8 + li) * SPIT + (lm & 1) * 8) * 2);

    auto stage = [&](int c0s, int buf) {
        #pragma unroll
        for (int i = 0; i < 8; i++) {
            int idx = tid + i * 128;          // 0..1023
            int part = idx >> 9;              // 0=K 1=V
            int rem = idx & 511;
            int r = rem >> 3, cc = (rem & 7) << 3;
            uint32_t dst = sbase + (uint32_t)(buf * BUFSZ + part * 9216 + (r * SPIT + cc) * 2);
            if (part == 0) {
                int j = c0s + r;
                const __half* ks = g_kh + ((size_t)bh * MK + min(j, MK - 1)) * DH + cc;
                cp16z(dst, ks, j < MK);
            } else {
                const __half* vs = g_vth + ((size_t)bh * DH + r) * MKP + c0s + cc;
                cp16(dst, vs);
            }
        }
    };

    stage(0, 0);
    CP_COMMIT();

    float oacc[2][8][4] = {};
    float sums[2][2] = {};

    for (int ch = 0; ch < NCH; ch++) {
        int c0 = ch << 6;
        CP_WAIT0();
        __syncthreads();
        if (ch + 1 < NCH) { stage((ch + 1) << 6, (ch + 1) & 1); CP_COMMIT(); }

        uint32_t uK = sbase + (uint32_t)((ch & 1) * BUFSZ);
        uint32_t uV = uK + 9216;

        #pragma unroll
        for (int t = 0; t < 2; t++) {
            float sacc[8][4] = {};
            #pragma unroll
            for (int kt = 0; kt < 4; kt++) {
                #pragma unroll
                for (int ntp = 0; ntp < 4; ntp++) {
                    uint32_t off = (uint32_t)(ntp * 16 * SPIT * 2 + kt * 32) + boff;
                    uint32_t bf[4];
                    ldsm_x4(bf, uK + off);
                    mma16816f(sacc[2 * ntp],     qf[t][kt], bf[0], bf[1]);
                    mma16816f(sacc[2 * ntp + 1], qf[t][kt], bf[2], bf[3]);
                }
            }

            uint32_t pf[4][4];
            #pragma unroll
            for (int nt = 0; nt < 8; nt++) {
                int j0 = c0 + nt * 8 + qoff;
                uint32_t wb = bmap[j0 >> 5];
                int bi = j0 & 31;
                float m0 = (float)((wb >> bi) & 1u);
                float m1 = (float)((wb >> (bi + 1)) & 1u);
                float p0 = m0 * __expf(fminf(sacc[nt][0], 10.0f));
                float p1 = m1 * __expf(fminf(sacc[nt][1], 10.0f));
                float p2 = m0 * __expf(fminf(sacc[nt][2], 10.0f));
                float p3 = m1 * __expf(fminf(sacc[nt][3], 10.0f));
                float r0 = __half2float(__float2half(p0));
                float r1 = __half2float(__float2half(p1));
                float r2 = __half2float(__float2half(p2));
                float r3 = __half2float(__float2half(p3));
                sums[t][0] += r0 + r1;
                sums[t][1] += r2 + r3;
                int kt = nt >> 1, hf = (nt & 1) << 1;
                pf[kt][hf + 0] = pack_f16x2(r0, r1);
                pf[kt][hf + 1] = pack_f16x2(r2, r3);
            }

            #pragma unroll
            for (int kt = 0; kt < 4; kt++) {
                #pragma unroll
                for (int ntp = 0; ntp < 4; ntp++) {
                    uint32_t off = (uint32_t)(ntp * 16 * SPIT * 2 + kt * 32) + boff;
                    uint32_t vf[4];
                    ldsm_x4(vf, uV + off);
                    mma16816f(oacc[t][2 * ntp],     pf[kt], vf[0], vf[1]);
                    mma16816f(oacc[t][2 * ntp + 1], pf[kt], vf[2], vf[3]);
                }
            }
        }
    }

    #pragma unroll
    for (int t = 0; t < 2; t++) {
        float s0 = sums[t][0], s1 = sums[t][1];
        s0 += __shfl_xor_sync(0xffffffffu, s0, 1);
        s0 += __shfl_xor_sync(0xffffffffu, s0, 2);
        s1 += __shfl_xor_sync(0xffffffffu, s1, 1);
        s1 += __shfl_xor_sync(0xffffffffu, s1, 2);
        float inv0 = 1.0f / s0;
        float inv1 = 1.0f / s1;

        size_t base0 = ((size_t)(b * NQ) + n0 + t * 64 + wid * 16 + g) * INNER + h * DH;
        size_t base1 = base0 + 8 * INNER;
        #pragma unroll
        for (int nt = 0; nt < 8; nt++) {
            int c = nt * 8 + qoff;
            *(uint32_t*)(g_ao16 + base0 + c) = pack_f16x2(oacc[t][nt][0] * inv0, oacc[t][nt][1] * inv0);
            *(uint32_t*)(g_ao16 + base1 + c) = pack_f16x2(oacc[t][nt][2] * inv1, oacc[t][nt][3] * inv1);
        }
    }
}

// ---------------- launch ------------------------------------------------------
extern "C" void kernel_launch(void* const* d_in, const int* in_sizes, int n_in,
                              void* d_out, int out_size)
{
    const float* x       = (const float*)d_in[0];
    const float* context = (const float*)d_in[1];
    const int*   mask    = (const int*)  d_in[2];
    const float* g_x     = (const float*)d_in[3];
    const float* null_kv = (const float*)d_in[4];
    const float* Wq      = (const float*)d_in[5];
    const float* Wkv     = (const float*)d_in[6];
    const float* Wo      = (const float*)d_in[7];
    const float* g_outp  = (const float*)d_in[8];
    float* out = (float*)d_out;
    (void)in_sizes; (void)n_in; (void)out_size;

    __half *wq16, *wkv16, *wo16, *xn16, *cx16, *ao16;
    cudaGetSymbolAddress((void**)&wq16,  g_wq16);
    cudaGetSymbolAddress((void**)&wkv16, g_wkv16);
    cudaGetSymbolAddress((void**)&wo16,  g_wo16);
    cudaGetSymbolAddress((void**)&xn16,  g_xn16);
    cudaGetSymbolAddress((void**)&cx16,  g_cx16);
    cudaGetSymbolAddress((void**)&ao16,  g_ao16);

    wconv_kernel<<<dim3(8, 8),  256>>>(Wq,  wq16,  512);
    wconv_kernel<<<dim3(16, 8), 256>>>(Wkv, wkv16, 1024);
    wconv_kernel<<<dim3(8, 8),  256>>>(Wo,  wo16,  512);

    csplit_kernel<<<(BATCH * NCTX * DIMC) / 1024, 256>>>(context);
    ln_kernel<0><<<BATCH * NQ, 128>>>(x, g_x, nullptr);

    cudaFuncSetAttribute(proj_mma_kernel<0>, cudaFuncAttributeMaxDynamicSharedMemorySize, 2 * PBUF);
    cudaFuncSetAttribute(proj_mma_kernel<1>, cudaFuncAttributeMaxDynamicSharedMemorySize, 2 * PBUF);
    cudaFuncSetAttribute(proj_mma_kernel<2>, cudaFuncAttributeMaxDynamicSharedMemorySize, 2 * PBUF);

    proj_mma_kernel<0><<<dim3(8, 128),  128, 2 * PBUF>>>(xn16, wq16);
    proj_mma_kernel<1><<<dim3(16, 128), 128, 2 * PBUF>>>(cx16, wkv16);
    null_fill_kernel<<<BATCH * HEADS, DH>>>(null_kv);

    cudaFuncSetAttribute(attn_mma_kernel, cudaFuncAttributeMaxDynamicSharedMemorySize, ATTN_SMEM);
    attn_mma_kernel<<<dim3(NQ / 128, BATCH * HEADS), 128, ATTN_SMEM>>>(mask);

    proj_mma_kernel<2><<<dim3(8, 128), 128, 2 * PBUF>>>(ao16, wo16);
    ln_kernel<1><<<BATCH * NQ, 128>>>(nullptr, g_outp, out);
}

// round 15
// speedup vs baseline: 2.4254x; 1.0979x over previous
#include <cuda_runtime.h>
#include <cuda_bf16.h>
#include <cuda_fp16.h>
#include <math.h>
#include <stdint.h>

// ---------------- problem constants ----------------
#define BATCH   2
#define NQ      4096
#define NCTX    4096
#define DIMC    512
#define HEADS   8
#define DH      64
#define INNER   512
#define MK      4097         // keys incl. null
#define MKP     4160         // padded V^T stride
#define SQSCALE 0.35355339059327373f     // sqrt(64^-0.5)
#define QSCALE2 0.5100696616388476f      // SQSCALE * log2(e)
#define CLAMP2  14.426950408889634f      // 10 * log2(e)
#define SPIT    72           // smem pitch (16-bit elems) = 144B

// ---------------- scratch ----------------------------------------------------
__device__ float g_pj[(size_t)BATCH * NQ * DIMC];

__device__ __half g_xn16[(size_t)BATCH * NQ * DIMC];
__device__ __half g_cx16[(size_t)BATCH * NCTX * DIMC];
__device__ __half g_ao16[(size_t)BATCH * NQ * INNER];

__device__ __half g_qh[(size_t)BATCH * HEADS * NQ * DH];    // pre-scaled by QSCALE2
__device__ __half g_kh[(size_t)BATCH * HEADS * MK * DH];    // pre-scaled by SQSCALE
__device__ __half g_vth[(size_t)BATCH * HEADS * DH * MKP];  // [bh][d][key]

__device__ __half g_wq16[512 * 512];
__device__ __half g_wkv16[1024 * 512];
__device__ __half g_wo16[512 * 512];

// ---------------- helpers -----------------------------------------------------
__device__ __forceinline__ uint32_t pack_f16x2(float lo_elem, float hi_elem) {
    uint32_t r;
    asm("cvt.rn.f16x2.f32 %0, %1, %2;" : "=r"(r) : "f"(hi_elem), "f"(lo_elem));
    return r;
}
__device__ __forceinline__ float ex2f(float x) {
    float r;
    asm("ex2.approx.f32 %0, %1;" : "=f"(r) : "f"(x));
    return r;
}
__device__ __forceinline__ void mma16816f(float* d, const uint32_t* a, uint32_t b0, uint32_t b1) {
    asm volatile("mma.sync.aligned.m16n8k16.row.col.f32.f16.f16.f32 "
        "{%0,%1,%2,%3}, {%4,%5,%6,%7}, {%8,%9}, {%0,%1,%2,%3};"
        : "+f"(d[0]), "+f"(d[1]), "+f"(d[2]), "+f"(d[3])
        : "r"(a[0]), "r"(a[1]), "r"(a[2]), "r"(a[3]), "r"(b0), "r"(b1));
}
__device__ __forceinline__ void ldsm_x4(uint32_t* r, uint32_t addr) {
    asm volatile("ldmatrix.sync.aligned.m8n8.x4.shared.b16 {%0,%1,%2,%3}, [%4];"
        : "=r"(r[0]), "=r"(r[1]), "=r"(r[2]), "=r"(r[3]) : "r"(addr));
}
__device__ __forceinline__ void cp16(uint32_t dst, const void* src) {
    asm volatile("cp.async.cg.shared.global [%0], [%1], 16;"
        :: "r"(dst), "l"(src) : "memory");
}
__device__ __forceinline__ void cp16z(uint32_t dst, const void* src, int ok) {
    int sz = ok ? 16 : 0;
    asm volatile("cp.async.cg.shared.global [%0], [%1], 16, %2;"
        :: "r"(dst), "l"(src), "r"(sz) : "memory");
}
#define CP_COMMIT() asm volatile("cp.async.commit_group;" ::: "memory")
#define CP_WAIT0()  asm volatile("cp.async.wait_group 0;" ::: "memory")

// ---------------- layernorm --------------------------------------------------
template <int WHICH>
__global__ void __launch_bounds__(128) ln_kernel(const float* __restrict__ inp,
                                                 const float* __restrict__ g,
                                                 float* __restrict__ outp)
{
    const float* in = (WHICH == 0) ? inp : g_pj;
    int row = blockIdx.x;
    int tid = threadIdx.x;
    const float* rptr = in + (size_t)row * DIMC;

    float4 v = reinterpret_cast<const float4*>(rptr)[tid];
    float s  = v.x + v.y + v.z + v.w;
    float ss = v.x * v.x + v.y * v.y + v.z * v.z + v.w * v.w;
    #pragma unroll
    for (int o = 16; o > 0; o >>= 1) {
        s  += __shfl_down_sync(0xffffffffu, s,  o);
        ss += __shfl_down_sync(0xffffffffu, ss, o);
    }
    __shared__ float sb[8];
    int wid = tid >> 5, lane = tid & 31;
    if (lane == 0) { sb[wid] = s; sb[4 + wid] = ss; }
    __syncthreads();
    float S  = sb[0] + sb[1] + sb[2] + sb[3];
    float SS = sb[4] + sb[5] + sb[6] + sb[7];
    float mean = S * (1.0f / DIMC);
    float var  = SS * (1.0f / DIMC) - mean * mean;
    float rstd = rsqrtf(var + 1e-5f);
    float4 gv = reinterpret_cast<const float4*>(g)[tid];
    float o0 = (v.x - mean) * rstd * gv.x;
    float o1 = (v.y - mean) * rstd * gv.y;
    float o2 = (v.z - mean) * rstd * gv.z;
    float o3 = (v.w - mean) * rstd * gv.w;
    if (WHICH == 0) {
        uint2 pk;
        pk.x = pack_f16x2(o0, o1);
        pk.y = pack_f16x2(o2, o3);
        *(uint2*)(g_xn16 + (size_t)row * DIMC + tid * 4) = pk;
    } else {
        float4 o4 = make_float4(o0, o1, o2, o3);
        reinterpret_cast<float4*>(outp + (size_t)row * DIMC)[tid] = o4;
    }
}

// ---------------- context convert --------------------------------------------
__global__ void __launch_bounds__(256) csplit_kernel(const float* __restrict__ src)
{
    size_t i4 = ((size_t)blockIdx.x * 256 + threadIdx.x);
    float4 v = reinterpret_cast<const float4*>(src)[i4];
    uint2 pk;
    pk.x = pack_f16x2(v.x, v.y);
    pk.y = pack_f16x2(v.z, v.w);
    *(uint2*)(g_cx16 + i4 * 4) = pk;
}

// ---------------- weight transpose + convert (all 3 weights, one launch) -----
__global__ void __launch_bounds__(256) wconv_all_kernel(const float* __restrict__ Wq,
                                                        const float* __restrict__ Wkv,
                                                        const float* __restrict__ Wo)
{
    __shared__ float s[64][65];
    int bx = blockIdx.x;
    const float* W; __half* T; int N;
    if (bx < 8)       { W = Wq;  T = g_wq16;  N = 512; }
    else if (bx < 24) { W = Wkv; T = g_wkv16; N = 1024; bx -= 8; }
    else              { W = Wo;  T = g_wo16;  N = 512; bx -= 24; }

    int tid = threadIdx.x;
    int n0 = bx * 64;
    int k0 = blockIdx.y * 64;
    #pragma unroll
    for (int i = 0; i < 16; i++) {
        int idx = tid + i * 256;
        int k = idx >> 6, n = idx & 63;
        s[k][n] = W[(size_t)(k0 + k) * N + n0 + n];
    }
    __syncthreads();
    #pragma unroll
    for (int i = 0; i < 8; i++) {
        int idx = tid + i * 256;
        int n = idx >> 5, k2 = (idx & 31) << 1;
        size_t o = (size_t)(n0 + n) * 512 + k0 + k2;
        *(uint32_t*)(T + o) = pack_f16x2(s[k2][n], s[k2 + 1][n]);
    }
}

// ---------------- projection GEMM core: 128 rows x 64 cols, shared B ldsm ----
// smem parts per buffer: A0(0) A1(9216) B(18432); PBUF 27648, x2 = 55296.
#define PBUF 27648

// MODE 0: Q epilogue (scaled QSCALE2); MODE 1: K/V epilogue; MODE 2: g_pj.
template <int MODE>
__device__ __forceinline__ void proj_body(const __half* __restrict__ A16,
                                          const __half* __restrict__ Wt,
                                          int row0, int col0, char* smc)
{
    uint32_t sbase = (uint32_t)__cvta_generic_to_shared(smc);
    int tid  = threadIdx.x;
    int wid  = tid >> 5;
    int lane = tid & 31;
    int g    = lane >> 2;
    int qoff = (lane & 3) << 1;

    int lm = lane >> 3, li = lane & 7;
    uint32_t aoff = (uint32_t)(((wid * 16 + (lm & 1) * 8 + li) * SPIT + (lm >> 1) * 8) * 2);
    uint32_t boff = (uint32_t)((((lm >> 1) * 8 + li) * SPIT + (lm & 1) * 8) * 2);

    auto stage = [&](int k0, int buf) {
        #pragma unroll
        for (int i = 0; i < 12; i++) {
            int idx = tid + i * 128;          // 0..1535
            int part = idx >> 9;              // 0=A0 1=A1 2=B
            int rem = idx & 511;
            int r = rem >> 3, cc = (rem & 7) << 3;
            uint32_t dst = sbase + (uint32_t)(buf * PBUF + part * 9216 + (r * SPIT + cc) * 2);
            const __half* src;
            if (part == 0)      src = A16 + (size_t)(row0 + r) * 512 + k0 + cc;
            else if (part == 1) src = A16 + (size_t)(row0 + 64 + r) * 512 + k0 + cc;
            else                src = Wt + (size_t)(col0 + r) * 512 + k0 + cc;
            cp16(dst, src);
        }
    };

    stage(0, 0);
    CP_COMMIT();

    float oacc[2][8][4] = {};

    for (int kc = 0; kc < 8; kc++) {
        CP_WAIT0();
        __syncthreads();
        if (kc + 1 < 8) { stage((kc + 1) << 6, (kc + 1) & 1); CP_COMMIT(); }

        uint32_t uA0 = sbase + (uint32_t)((kc & 1) * PBUF);
        uint32_t uA1 = uA0 + 9216;
        uint32_t uB  = uA0 + 18432;

        uint32_t af[2][4][4];
        #pragma unroll
        for (int kt = 0; kt < 4; kt++) {
            ldsm_x4(af[0][kt], uA0 + (uint32_t)(kt * 32) + aoff);
            ldsm_x4(af[1][kt], uA1 + (uint32_t)(kt * 32) + aoff);
        }

        #pragma unroll
        for (int kt = 0; kt < 4; kt++) {
            #pragma unroll
            for (int ntp = 0; ntp < 4; ntp++) {
                uint32_t off = (uint32_t)(ntp * 16 * SPIT * 2 + kt * 32) + boff;
                uint32_t bf[4];
                ldsm_x4(bf, uB + off);
                mma16816f(oacc[0][2 * ntp],     af[0][kt], bf[0], bf[1]);
                mma16816f(oacc[0][2 * ntp + 1], af[0][kt], bf[2], bf[3]);
                mma16816f(oacc[1][2 * ntp],     af[1][kt], bf[0], bf[1]);
                mma16816f(oacc[1][2 * ntp + 1], af[1][kt], bf[2], bf[3]);
            }
        }
    }

    #pragma unroll
    for (int t = 0; t < 2; t++) {
        #pragma unroll
        for (int nt = 0; nt < 8; nt++) {
            #pragma unroll
            for (int half = 0; half < 2; half++) {
                int row = row0 + t * 64 + wid * 16 + g + half * 8;
                float v0 = oacc[t][nt][half * 2 + 0];
                float v1 = oacc[t][nt][half * 2 + 1];
                int c = col0 + nt * 8 + qoff;
                if (MODE == 0) {
                    int b = row >> 12, n = row & 4095;
                    int h = c >> 6, dd = c & 63;
                    size_t idx = (((size_t)(b * HEADS + h)) * NQ + n) * DH + dd;
                    *(uint32_t*)(g_qh + idx) = pack_f16x2(v0 * QSCALE2, v1 * QSCALE2);
                } else if (MODE == 1) {
                    int b = row >> 12, mr = row & 4095;
                    if (c < 512) {
                        int h = c >> 6, dd = c & 63;
                        size_t idx = (((size_t)(b * HEADS + h)) * MK + mr + 1) * DH + dd;
                        *(uint32_t*)(g_kh + idx) = pack_f16x2(v0 * SQSCALE, v1 * SQSCALE);
                    } else {
                        int c2 = c - 512;
                        int h = c2 >> 6, dd = c2 & 63;
                        size_t idx = (((size_t)(b * HEADS + h)) * DH + dd) * MKP + (mr + 1);
                        g_vth[idx]       = __float2half(v0);
                        g_vth[idx + MKP] = __float2half(v1);
                    }
                } else {
                    *(float2*)(g_pj + (size_t)row * 512 + c) = make_float2(v0, v1);
                }
            }
        }
    }
}

// Q + KV projections in one launch; null-kv fill folded into block (0,0).
__global__ void __launch_bounds__(128) proj01_kernel(const float* __restrict__ null_kv)
{
    extern __shared__ char smc[];
    int bx = blockIdx.x;
    int row0 = blockIdx.y * 128;

    if (bx == 0 && blockIdx.y == 0) {
        // null kv: 16 bh x 64 d, threads 0-63 -> K, 64-127 -> V
        int tid = threadIdx.x;
        int d = tid & 63;
        if (tid < 64) {
            __half kv = __float2half(null_kv[d] * SQSCALE);
            #pragma unroll
            for (int bh = 0; bh < 16; bh++)
                g_kh[(size_t)bh * MK * DH + d] = kv;
        } else {
            __half vv = __float2half(null_kv[DH + d]);
            #pragma unroll
            for (int bh = 0; bh < 16; bh++)
                g_vth[((size_t)bh * DH + d) * MKP + 0] = vv;
        }
    }

    if (bx < 8) proj_body<0>(g_xn16, g_wq16, row0, bx * 64, smc);
    else        proj_body<1>(g_cx16, g_wkv16, row0, (bx - 8) * 64, smc);
}

__global__ void __launch_bounds__(128) proj2_kernel()
{
    extern __shared__ char smc[];
    proj_body<2>(g_ao16, g_wo16, blockIdx.y * 128, blockIdx.x * 64, smc);
}

// ---------------- FA2 attention: fp16 single K/V, 2 Q-subtiles, ex2 -----------
#define BUFSZ   18432
#define OFF_BM  36864
#define ATTN_SMEM 37408
#define NCH     65

__global__ void __launch_bounds__(128) attn_mma_kernel(const int* __restrict__ mask)
{
    extern __shared__ char smc[];
    const int tid  = threadIdx.x;
    const int wid  = tid >> 5;
    const int lane = tid & 31;
    const int g    = lane >> 2;
    const int qoff = (lane & 3) << 1;
    const int bh = blockIdx.y;
    const int b = bh >> 3, h = bh & 7;
    const int n0 = blockIdx.x << 7;

    uint32_t sbase = (uint32_t)__cvta_generic_to_shared(smc);
    uint32_t* bmap = (uint32_t*)(smc + OFF_BM);

    for (int w = tid; w < 130; w += 128) {
        uint32_t wv = 0;
        int jb = w * 32;
        #pragma unroll 8
        for (int i = 0; i < 32; i++) {
            int j = jb + i;
            int ok = (j == 0) ? 1 : ((j < MK) ? (mask[b * NCTX + j - 1] != 0) : 0);
            wv |= (uint32_t)ok << i;
        }
        bmap[w] = wv;
    }

    uint32_t qf[2][4][4];
    #pragma unroll
    for (int t = 0; t < 2; t++) {
        const __half* q0 = g_qh + ((size_t)bh * NQ + n0 + t * 64 + wid * 16 + g) * DH;
        #pragma unroll
        for (int kt = 0; kt < 4; kt++) {
            int d0 = kt * 16 + qoff;
            qf[t][kt][0] = *(const uint32_t*)(q0 + d0);
            qf[t][kt][1] = *(const uint32_t*)(q0 + 8 * DH + d0);
            qf[t][kt][2] = *(const uint32_t*)(q0 + d0 + 8);
            qf[t][kt][3] = *(const uint32_t*)(q0 + 8 * DH + d0 + 8);
        }
    }

    const int lm = lane >> 3, li = lane & 7;
    const uint32_t boff = (uint32_t)((((lm >> 1) * 8 + li) * SPIT + (lm & 1) * 8) * 2);

    auto stage = [&](int c0s, int buf) {
        #pragma unroll
        for (int i = 0; i < 8; i++) {
            int idx = tid + i * 128;
            int part = idx >> 9;              // 0=K 1=V
            int rem = idx & 511;
            int r = rem >> 3, cc = (rem & 7) << 3;
            uint32_t dst = sbase + (uint32_t)(buf * BUFSZ + part * 9216 + (r * SPIT + cc) * 2);
            if (part == 0) {
                int j = c0s + r;
                const __half* ks = g_kh + ((size_t)bh * MK + min(j, MK - 1)) * DH + cc;
                cp16z(dst, ks, j < MK);
            } else {
                const __half* vs = g_vth + ((size_t)bh * DH + r) * MKP + c0s + cc;
                cp16(dst, vs);
            }
        }
    };

    stage(0, 0);
    CP_COMMIT();

    float oacc[2][8][4] = {};
    float sums[2][2] = {};

    for (int ch = 0; ch < NCH; ch++) {
        int c0 = ch << 6;
        CP_WAIT0();
        __syncthreads();
        if (ch + 1 < NCH) { stage((ch + 1) << 6, (ch + 1) & 1); CP_COMMIT(); }

        uint32_t uK = sbase + (uint32_t)((ch & 1) * BUFSZ);
        uint32_t uV = uK + 9216;

        #pragma unroll
        for (int t = 0; t < 2; t++) {
            float sacc[8][4] = {};
            #pragma unroll
            for (int kt = 0; kt < 4; kt++) {
                #pragma unroll
                for (int ntp = 0; ntp < 4; ntp++) {
                    uint32_t off = (uint32_t)(ntp * 16 * SPIT * 2 + kt * 32) + boff;
                    uint32_t bf[4];
                    ldsm_x4(bf, uK + off);
                    mma16816f(sacc[2 * ntp],     qf[t][kt], bf[0], bf[1]);
                    mma16816f(sacc[2 * ntp + 1], qf[t][kt], bf[2], bf[3]);
                }
            }

            uint32_t pf[4][4];
            #pragma unroll
            for (int nt = 0; nt < 8; nt++) {
                int j0 = c0 + nt * 8 + qoff;
                uint32_t wb = bmap[j0 >> 5];
                int bi = j0 & 31;
                float m0 = (float)((wb >> bi) & 1u);
                float m1 = (float)((wb >> (bi + 1)) & 1u);
                float p0 = m0 * ex2f(fminf(sacc[nt][0], CLAMP2));
                float p1 = m1 * ex2f(fminf(sacc[nt][1], CLAMP2));
                float p2 = m0 * ex2f(fminf(sacc[nt][2], CLAMP2));
                float p3 = m1 * ex2f(fminf(sacc[nt][3], CLAMP2));
                float r0 = __half2float(__float2half(p0));
                float r1 = __half2float(__float2half(p1));
                float r2 = __half2float(__float2half(p2));
                float r3 = __half2float(__float2half(p3));
                sums[t][0] += r0 + r1;
                sums[t][1] += r2 + r3;
                int kt = nt >> 1, hf = (nt & 1) << 1;
                pf[kt][hf + 0] = pack_f16x2(r0, r1);
                pf[kt][hf + 1] = pack_f16x2(r2, r3);
            }

            #pragma unroll
            for (int kt = 0; kt < 4; kt++) {
                #pragma unroll
                for (int ntp = 0; ntp < 4; ntp++) {
                    uint32_t off = (uint32_t)(ntp * 16 * SPIT * 2 + kt * 32) + boff;
                    uint32_t vf[4];
                    ldsm_x4(vf, uV + off);
                    mma16816f(oacc[t][2 * ntp],     pf[kt], vf[0], vf[1]);
                    mma16816f(oacc[t][2 * ntp + 1], pf[kt], vf[2], vf[3]);
                }
            }
        }
    }

    #pragma unroll
    for (int t = 0; t < 2; t++) {
        float s0 = sums[t][0], s1 = sums[t][1];
        s0 += __shfl_xor_sync(0xffffffffu, s0, 1);
        s0 += __shfl_xor_sync(0xffffffffu, s0, 2);
        s1 += __shfl_xor_sync(0xffffffffu, s1, 1);
        s1 += __shfl_xor_sync(0xffffffffu, s1, 2);
        float inv0 = 1.0f / s0;
        float inv1 = 1.0f / s1;

        size_t base0 = ((size_t)(b * NQ) + n0 + t * 64 + wid * 16 + g) * INNER + h * DH;
        size_t base1 = base0 + 8 * INNER;
        #pragma unroll
        for (int nt = 0; nt < 8; nt++) {
            int c = nt * 8 + qoff;
            *(uint32_t*)(g_ao16 + base0 + c) = pack_f16x2(oacc[t][nt][0] * inv0, oacc[t][nt][1] * inv0);
            *(uint32_t*)(g_ao16 + base1 + c) = pack_f16x2(oacc[t][nt][2] * inv1, oacc[t][nt][3] * inv1);
        }
    }
}

// ---------------- launch ------------------------------------------------------
extern "C" void kernel_launch(void* const* d_in, const int* in_sizes, int n_in,
                              void* d_out, int out_size)
{
    const float* x       = (const float*)d_in[0];
    const float* context = (const float*)d_in[1];
    const int*   mask    = (const int*)  d_in[2];
    const float* g_x     = (const float*)d_in[3];
    const float* null_kv = (const float*)d_in[4];
    const float* Wq      = (const float*)d_in[5];
    const float* Wkv     = (const float*)d_in[6];
    const float* Wo      = (const float*)d_in[7];
    const float* g_outp  = (const float*)d_in[8];
    float* out = (float*)d_out;
    (void)in_sizes; (void)n_in; (void)out_size;

    wconv_all_kernel<<<dim3(32, 8), 256>>>(Wq, Wkv, Wo);
    csplit_kernel<<<(BATCH * NCTX * DIMC) / 1024, 256>>>(context);
    ln_kernel<0><<<BATCH * NQ, 128>>>(x, g_x, nullptr);

    cudaFuncSetAttribute(proj01_kernel, cudaFuncAttributeMaxDynamicSharedMemorySize, 2 * PBUF);
    cudaFuncSetAttribute(proj2_kernel,  cudaFuncAttributeMaxDynamicSharedMemorySize, 2 * PBUF);

    proj01_kernel<<<dim3(24, 64), 128, 2 * PBUF>>>(null_kv);

    cudaFuncSetAttribute(attn_mma_kernel, cudaFuncAttributeMaxDynamicSharedMemorySize, ATTN_SMEM);
    attn_mma_kernel<<<dim3(NQ / 128, BATCH * HEADS), 128, ATTN_SMEM>>>(mask);

    proj2_kernel<<<dim3(8, 64), 128, 2 * PBUF>>>();
    ln_kernel<1><<<BATCH * NQ, 128>>>(nullptr, g_outp, out);
}

// round 16
// speedup vs baseline: 2.5776x; 1.0628x over previous
#include <cuda_runtime.h>
#include <cuda_bf16.h>
#include <cuda_fp16.h>
#include <math.h>
#include <stdint.h>

// ---------------- problem constants ----------------
#define BATCH   2
#define NQ      4096
#define NCTX    4096
#define DIMC    512
#define HEADS   8
#define DH      64
#define INNER   512
#define MK      4097
#define MKP     4160
#define SQSCALE 0.35355339059327373f     // sqrt(64^-0.5)
#define QSCALE2 0.5100696616388476f      // SQSCALE * log2(e)
#define CLAMP2  14.426950408889634f      // 10 * log2(e)
#define SPIT    72                       // smem pitch (16-bit elems) = 144B
#define HONES   0x3C003C00u              // half2 {1.0, 1.0}

// ---------------- scratch ----------------------------------------------------
__device__ float g_pj[(size_t)BATCH * NQ * DIMC];

__device__ __half g_xn16[(size_t)BATCH * NQ * DIMC];
__device__ __half g_cx16[(size_t)BATCH * NCTX * DIMC];
__device__ __half g_ao16[(size_t)BATCH * NQ * INNER];

__device__ __half g_qh[(size_t)BATCH * HEADS * NQ * DH];    // pre-scaled by QSCALE2
__device__ __half g_kh[(size_t)BATCH * HEADS * MK * DH];    // pre-scaled by SQSCALE
__device__ __half g_vth[(size_t)BATCH * HEADS * DH * MKP];  // [bh][d][key]

__device__ __half g_wq16[512 * 512];
__device__ __half g_wkv16[1024 * 512];
__device__ __half g_wo16[512 * 512];

// ---------------- helpers -----------------------------------------------------
__device__ __forceinline__ uint32_t pack_f16x2(float lo_elem, float hi_elem) {
    uint32_t r;
    asm("cvt.rn.f16x2.f32 %0, %1, %2;" : "=r"(r) : "f"(hi_elem), "f"(lo_elem));
    return r;
}
__device__ __forceinline__ float ex2f(float x) {
    float r;
    asm("ex2.approx.f32 %0, %1;" : "=f"(r) : "f"(x));
    return r;
}
__device__ __forceinline__ void mma16816f(float* d, const uint32_t* a, uint32_t b0, uint32_t b1) {
    asm volatile("mma.sync.aligned.m16n8k16.row.col.f32.f16.f16.f32 "
        "{%0,%1,%2,%3}, {%4,%5,%6,%7}, {%8,%9}, {%0,%1,%2,%3};"
        : "+f"(d[0]), "+f"(d[1]), "+f"(d[2]), "+f"(d[3])
        : "r"(a[0]), "r"(a[1]), "r"(a[2]), "r"(a[3]), "r"(b0), "r"(b1));
}
__device__ __forceinline__ void ldsm_x4(uint32_t* r, uint32_t addr) {
    asm volatile("ldmatrix.sync.aligned.m8n8.x4.shared.b16 {%0,%1,%2,%3}, [%4];"
        : "=r"(r[0]), "=r"(r[1]), "=r"(r[2]), "=r"(r[3]) : "r"(addr));
}
__device__ __forceinline__ void cp16(uint32_t dst, const void* src) {
    asm volatile("cp.async.cg.shared.global [%0], [%1], 16;"
        :: "r"(dst), "l"(src) : "memory");
}
__device__ __forceinline__ void cp16z(uint32_t dst, const void* src, int ok) {
    int sz = ok ? 16 : 0;
    asm volatile("cp.async.cg.shared.global [%0], [%1], 16, %2;"
        :: "r"(dst), "l"(src), "r"(sz) : "memory");
}
#define CP_COMMIT() asm volatile("cp.async.commit_group;" ::: "memory")
#define CP_WAIT0()  asm volatile("cp.async.wait_group 0;" ::: "memory")

// ---------------- fused prep: ln0 + csplit + wconv ---------------------------
// blocks [0, 8192): layernorm row
// blocks [8192, 10240): context convert (512 float4 per block)
// blocks [10240, 10496): weight transpose-convert (256 blocks: 32 x 8)
__global__ void __launch_bounds__(128) prep_kernel(const float* __restrict__ x,
                                                   const float* __restrict__ g,
                                                   const float* __restrict__ context,
                                                   const float* __restrict__ Wq,
                                                   const float* __restrict__ Wkv,
                                                   const float* __restrict__ Wo)
{
    __shared__ float s[64][65];
    int bx = blockIdx.x;
    int tid = threadIdx.x;

    if (bx < 8192) {
        // ---- layernorm(x) -> g_xn16 ----
        int row = bx;
        float4 v = reinterpret_cast<const float4*>(x + (size_t)row * DIMC)[tid];
        float sm = v.x + v.y + v.z + v.w;
        float ss = v.x * v.x + v.y * v.y + v.z * v.z + v.w * v.w;
        #pragma unroll
        for (int o = 16; o > 0; o >>= 1) {
            sm += __shfl_down_sync(0xffffffffu, sm, o);
            ss += __shfl_down_sync(0xffffffffu, ss, o);
        }
        int wid = tid >> 5, lane = tid & 31;
        float* sb = &s[0][0];
        if (lane == 0) { sb[wid] = sm; sb[4 + wid] = ss; }
        __syncthreads();
        float S  = sb[0] + sb[1] + sb[2] + sb[3];
        float SS = sb[4] + sb[5] + sb[6] + sb[7];
        float mean = S * (1.0f / DIMC);
        float var  = SS * (1.0f / DIMC) - mean * mean;
        float rstd = rsqrtf(var + 1e-5f);
        float4 gv = reinterpret_cast<const float4*>(g)[tid];
        float o0 = (v.x - mean) * rstd * gv.x;
        float o1 = (v.y - mean) * rstd * gv.y;
        float o2 = (v.z - mean) * rstd * gv.z;
        float o3 = (v.w - mean) * rstd * gv.w;
        uint2 pk;
        pk.x = pack_f16x2(o0, o1);
        pk.y = pack_f16x2(o2, o3);
        *(uint2*)(g_xn16 + (size_t)row * DIMC + tid * 4) = pk;
    } else if (bx < 10240) {
        // ---- context fp32 -> fp16 ----
        size_t base4 = (size_t)(bx - 8192) * 512 + tid;
        #pragma unroll
        for (int j = 0; j < 4; j++) {
            size_t i4 = base4 + j * 128;
            float4 v = reinterpret_cast<const float4*>(context)[i4];
            uint2 pk;
            pk.x = pack_f16x2(v.x, v.y);
            pk.y = pack_f16x2(v.z, v.w);
            *(uint2*)(g_cx16 + i4 * 4) = pk;
        }
    } else {
        // ---- weight transpose + convert ----
        int wb = bx - 10240;                // 0..255
        int wx = wb & 31;                   // 0..31 (column-of-64 index across 3 weights)
        int k0 = (wb >> 5) * 64;            // 0..448
        const float* W; __half* T; int N;
        if (wx < 8)       { W = Wq;  T = g_wq16;  N = 512; }
        else if (wx < 24) { W = Wkv; T = g_wkv16; N = 1024; wx -= 8; }
        else              { W = Wo;  T = g_wo16;  N = 512; wx -= 24; }
        int n0 = wx * 64;
        #pragma unroll
        for (int i = 0; i < 32; i++) {
            int idx = tid + i * 128;
            int k = idx >> 6, n = idx & 63;
            s[k][n] = W[(size_t)(k0 + k) * N + n0 + n];
        }
        __syncthreads();
        #pragma unroll
        for (int i = 0; i < 16; i++) {
            int idx = tid + i * 128;        // 2048 pair-slots
            int n = idx >> 5, k2 = (idx & 31) << 1;
            size_t o = (size_t)(n0 + n) * 512 + k0 + k2;
            *(uint32_t*)(T + o) = pack_f16x2(s[k2][n], s[k2 + 1][n]);
        }
    }
}

// ---------------- final layernorm --------------------------------------------
__global__ void __launch_bounds__(128) ln1_kernel(const float* __restrict__ g,
                                                  float* __restrict__ outp)
{
    int row = blockIdx.x;
    int tid = threadIdx.x;
    float4 v = reinterpret_cast<const float4*>(g_pj + (size_t)row * DIMC)[tid];
    float sm = v.x + v.y + v.z + v.w;
    float ss = v.x * v.x + v.y * v.y + v.z * v.z + v.w * v.w;
    #pragma unroll
    for (int o = 16; o > 0; o >>= 1) {
        sm += __shfl_down_sync(0xffffffffu, sm, o);
        ss += __shfl_down_sync(0xffffffffu, ss, o);
    }
    __shared__ float sb[8];
    int wid = tid >> 5, lane = tid & 31;
    if (lane == 0) { sb[wid] = sm; sb[4 + wid] = ss; }
    __syncthreads();
    float S  = sb[0] + sb[1] + sb[2] + sb[3];
    float SS = sb[4] + sb[5] + sb[6] + sb[7];
    float mean = S * (1.0f / DIMC);
    float var  = SS * (1.0f / DIMC) - mean * mean;
    float rstd = rsqrtf(var + 1e-5f);
    float4 gv = reinterpret_cast<const float4*>(g)[tid];
    float4 o4;
    o4.x = (v.x - mean) * rstd * gv.x;
    o4.y = (v.y - mean) * rstd * gv.y;
    o4.z = (v.z - mean) * rstd * gv.z;
    o4.w = (v.w - mean) * rstd * gv.w;
    reinterpret_cast<float4*>(outp + (size_t)row * DIMC)[tid] = o4;
}

// ---------------- projection GEMM core: 128 rows x 64 cols, shared B ldsm ----
#define PBUF 27648
template <int MODE>
__device__ __forceinline__ void proj_body(const __half* __restrict__ A16,
                                          const __half* __restrict__ Wt,
                                          int row0, int col0, char* smc)
{
    uint32_t sbase = (uint32_t)__cvta_generic_to_shared(smc);
    int tid  = threadIdx.x;
    int wid  = tid >> 5;
    int lane = tid & 31;
    int g    = lane >> 2;
    int qoff = (lane & 3) << 1;

    int lm = lane >> 3, li = lane & 7;
    uint32_t aoff = (uint32_t)(((wid * 16 + (lm & 1) * 8 + li) * SPIT + (lm >> 1) * 8) * 2);
    uint32_t boff = (uint32_t)((((lm >> 1) * 8 + li) * SPIT + (lm & 1) * 8) * 2);

    auto stage = [&](int k0, int buf) {
        #pragma unroll
        for (int i = 0; i < 12; i++) {
            int idx = tid + i * 128;
            int part = idx >> 9;              // 0=A0 1=A1 2=B
            int rem = idx & 511;
            int r = rem >> 3, cc = (rem & 7) << 3;
            uint32_t dst = sbase + (uint32_t)(buf * PBUF + part * 9216 + (r * SPIT + cc) * 2);
            const __half* src;
            if (part == 0)      src = A16 + (size_t)(row0 + r) * 512 + k0 + cc;
            else if (part == 1) src = A16 + (size_t)(row0 + 64 + r) * 512 + k0 + cc;
            else                src = Wt + (size_t)(col0 + r) * 512 + k0 + cc;
            cp16(dst, src);
        }
    };

    stage(0, 0);
    CP_COMMIT();

    float oacc[2][8][4] = {};

    for (int kc = 0; kc < 8; kc++) {
        CP_WAIT0();
        __syncthreads();
        if (kc + 1 < 8) { stage((kc + 1) << 6, (kc + 1) & 1); CP_COMMIT(); }

        uint32_t uA0 = sbase + (uint32_t)((kc & 1) * PBUF);
        uint32_t uA1 = uA0 + 9216;
        uint32_t uB  = uA0 + 18432;

        uint32_t af[2][4][4];
        #pragma unroll
        for (int kt = 0; kt < 4; kt++) {
            ldsm_x4(af[0][kt], uA0 + (uint32_t)(kt * 32) + aoff);
            ldsm_x4(af[1][kt], uA1 + (uint32_t)(kt * 32) + aoff);
        }

        #pragma unroll
        for (int kt = 0; kt < 4; kt++) {
            #pragma unroll
            for (int ntp = 0; ntp < 4; ntp++) {
                uint32_t off = (uint32_t)(ntp * 16 * SPIT * 2 + kt * 32) + boff;
                uint32_t bf[4];
                ldsm_x4(bf, uB + off);
                mma16816f(oacc[0][2 * ntp],     af[0][kt], bf[0], bf[1]);
                mma16816f(oacc[0][2 * ntp + 1], af[0][kt], bf[2], bf[3]);
                mma16816f(oacc[1][2 * ntp],     af[1][kt], bf[0], bf[1]);
                mma16816f(oacc[1][2 * ntp + 1], af[1][kt], bf[2], bf[3]);
            }
        }
    }

    #pragma unroll
    for (int t = 0; t < 2; t++) {
        #pragma unroll
        for (int nt = 0; nt < 8; nt++) {
            #pragma unroll
            for (int half = 0; half < 2; half++) {
                int row = row0 + t * 64 + wid * 16 + g + half * 8;
                float v0 = oacc[t][nt][half * 2 + 0];
                float v1 = oacc[t][nt][half * 2 + 1];
                int c = col0 + nt * 8 + qoff;
                if (MODE == 0) {
                    int b = row >> 12, n = row & 4095;
                    int h = c >> 6, dd = c & 63;
                    size_t idx = (((size_t)(b * HEADS + h)) * NQ + n) * DH + dd;
                    *(uint32_t*)(g_qh + idx) = pack_f16x2(v0 * QSCALE2, v1 * QSCALE2);
                } else if (MODE == 1) {
                    int b = row >> 12, mr = row & 4095;
                    if (c < 512) {
                        int h = c >> 6, dd = c & 63;
                        size_t idx = (((size_t)(b * HEADS + h)) * MK + mr + 1) * DH + dd;
                        *(uint32_t*)(g_kh + idx) = pack_f16x2(v0 * SQSCALE, v1 * SQSCALE);
                    } else {
                        int c2 = c - 512;
                        int h = c2 >> 6, dd = c2 & 63;
                        size_t idx = (((size_t)(b * HEADS + h)) * DH + dd) * MKP + (mr + 1);
                        g_vth[idx]       = __float2half(v0);
                        g_vth[idx + MKP] = __float2half(v1);
                    }
                } else {
                    *(float2*)(g_pj + (size_t)row * 512 + c) = make_float2(v0, v1);
                }
            }
        }
    }
}

__global__ void __launch_bounds__(128) proj01_kernel(const float* __restrict__ null_kv)
{
    extern __shared__ char smc[];
    int bx = blockIdx.x;
    int row0 = blockIdx.y * 128;

    if (bx == 0 && blockIdx.y == 0) {
        int tid = threadIdx.x;
        int d = tid & 63;
        if (tid < 64) {
            __half kv = __float2half(null_kv[d] * SQSCALE);
            #pragma unroll
            for (int bh = 0; bh < 16; bh++)
                g_kh[(size_t)bh * MK * DH + d] = kv;
        } else {
            __half vv = __float2half(null_kv[DH + d]);
            #pragma unroll
            for (int bh = 0; bh < 16; bh++)
                g_vth[((size_t)bh * DH + d) * MKP + 0] = vv;
        }
    }

    if (bx < 8) proj_body<0>(g_xn16, g_wq16, row0, bx * 64, smc);
    else        proj_body<1>(g_cx16, g_wkv16, row0, (bx - 8) * 64, smc);
}

__global__ void __launch_bounds__(128) proj2_kernel()
{
    extern __shared__ char smc[];
    proj_body<2>(g_ao16, g_wo16, blockIdx.y * 128, blockIdx.x * 64, smc);
}

// ---------------- FA2 attention: streamlined softmax + MMA row-sums -----------
#define BUFSZ   18432
#define OFF_BM  36864
#define ATTN_SMEM 37408
#define NCH     65

__global__ void __launch_bounds__(128) attn_mma_kernel(const int* __restrict__ mask)
{
    extern __shared__ char smc[];
    const int tid  = threadIdx.x;
    const int wid  = tid >> 5;
    const int lane = tid & 31;
    const int g    = lane >> 2;
    const int qoff = (lane & 3) << 1;
    const int bh = blockIdx.y;
    const int b = bh >> 3, h = bh & 7;
    const int n0 = blockIdx.x << 7;

    uint32_t sbase = (uint32_t)__cvta_generic_to_shared(smc);
    uint32_t* bmap = (uint32_t*)(smc + OFF_BM);

    for (int w = tid; w < 130; w += 128) {
        uint32_t wv = 0;
        int jb = w * 32;
        #pragma unroll 8
        for (int i = 0; i < 32; i++) {
            int j = jb + i;
            int ok = (j == 0) ? 1 : ((j < MK) ? (mask[b * NCTX + j - 1] != 0) : 0);
            wv |= (uint32_t)ok << i;
        }
        bmap[w] = wv;
    }

    uint32_t qf[2][4][4];
    #pragma unroll
    for (int t = 0; t < 2; t++) {
        const __half* q0 = g_qh + ((size_t)bh * NQ + n0 + t * 64 + wid * 16 + g) * DH;
        #pragma unroll
        for (int kt = 0; kt < 4; kt++) {
            int d0 = kt * 16 + qoff;
            qf[t][kt][0] = *(const uint32_t*)(q0 + d0);
            qf[t][kt][1] = *(const uint32_t*)(q0 + 8 * DH + d0);
            qf[t][kt][2] = *(const uint32_t*)(q0 + d0 + 8);
            qf[t][kt][3] = *(const uint32_t*)(q0 + 8 * DH + d0 + 8);
        }
    }

    const int lm = lane >> 3, li = lane & 7;
    const uint32_t boff = (uint32_t)((((lm >> 1) * 8 + li) * SPIT + (lm & 1) * 8) * 2);

    auto stage = [&](int c0s, int buf) {
        #pragma unroll
        for (int i = 0; i < 8; i++) {
            int idx = tid + i * 128;
            int part = idx >> 9;
            int rem = idx & 511;
            int r = rem >> 3, cc = (rem & 7) << 3;
            uint32_t dst = sbase + (uint32_t)(buf * BUFSZ + part * 9216 + (r * SPIT + cc) * 2);
            if (part == 0) {
                int j = c0s + r;
                const __half* ks = g_kh + ((size_t)bh * MK + min(j, MK - 1)) * DH + cc;
                cp16z(dst, ks, j < MK);
            } else {
                const __half* vs = g_vth + ((size_t)bh * DH + r) * MKP + c0s + cc;
                cp16(dst, vs);
            }
        }
    };

    stage(0, 0);
    CP_COMMIT();

    float oacc[2][8][4] = {};
    float ssum[2][4] = {};   // MMA-of-ones row-sum accumulators

    for (int ch = 0; ch < NCH; ch++) {
        int c0 = ch << 6;
        CP_WAIT0();
        __syncthreads();
        if (ch + 1 < NCH) { stage((ch + 1) << 6, (ch + 1) & 1); CP_COMMIT(); }

        uint32_t uK = sbase + (uint32_t)((ch & 1) * BUFSZ);
        uint32_t uV = uK + 9216;

        #pragma unroll
        for (int t = 0; t < 2; t++) {
            float sacc[8][4] = {};
            #pragma unroll
            for (int kt = 0; kt < 4; kt++) {
                #pragma unroll
                for (int ntp = 0; ntp < 4; ntp++) {
                    uint32_t off = (uint32_t)(ntp * 16 * SPIT * 2 + kt * 32) + boff;
                    uint32_t bf[4];
                    ldsm_x4(bf, uK + off);
                    mma16816f(sacc[2 * ntp],     qf[t][kt], bf[0], bf[1]);
                    mma16816f(sacc[2 * ntp + 1], qf[t][kt], bf[2], bf[3]);
                }
            }

            // softmax: clamp, ex2, mask, pack fp16 (no round-trip, no scalar sums)
            uint32_t pf[4][4];
            #pragma unroll
            for (int nt = 0; nt < 8; nt++) {
                int j0 = c0 + nt * 8 + qoff;
                uint32_t wb = bmap[j0 >> 5];
                int bi = j0 & 31;
                float m0 = (float)((wb >> bi) & 1u);
                float m1 = (float)((wb >> (bi + 1)) & 1u);
                float p0 = m0 * ex2f(fminf(sacc[nt][0], CLAMP2));
                float p1 = m1 * ex2f(fminf(sacc[nt][1], CLAMP2));
                float p2 = m0 * ex2f(fminf(sacc[nt][2], CLAMP2));
                float p3 = m1 * ex2f(fminf(sacc[nt][3], CLAMP2));
                int kt = nt >> 1, hf = (nt & 1) << 1;
                pf[kt][hf + 0] = pack_f16x2(p0, p1);
                pf[kt][hf + 1] = pack_f16x2(p2, p3);
            }

            // row sums via MMA against all-ones B (accumulates across chunks)
            #pragma unroll
            for (int kt = 0; kt < 4; kt++)
                mma16816f(ssum[t], pf[kt], HONES, HONES);

            #pragma unroll
            for (int kt = 0; kt < 4; kt++) {
                #pragma unroll
                for (int ntp = 0; ntp < 4; ntp++) {
                    uint32_t off = (uint32_t)(ntp * 16 * SPIT * 2 + kt * 32) + boff;
                    uint32_t vf[4];
                    ldsm_x4(vf, uV + off);
                    mma16816f(oacc[t][2 * ntp],     pf[kt], vf[0], vf[1]);
                    mma16816f(oacc[t][2 * ntp + 1], pf[kt], vf[2], vf[3]);
                }
            }
        }
    }

    #pragma unroll
    for (int t = 0; t < 2; t++) {
        float inv0 = 1.0f / ssum[t][0];   // row g sum (all cols identical)
        float inv1 = 1.0f / ssum[t][2];   // row g+8 sum

        size_t base0 = ((size_t)(b * NQ) + n0 + t * 64 + wid * 16 + g) * INNER + h * DH;
        size_t base1 = base0 + 8 * INNER;
        #pragma unroll
        for (int nt = 0; nt < 8; nt++) {
            int c = nt * 8 + qoff;
            *(uint32_t*)(g_ao16 + base0 + c) = pack_f16x2(oacc[t][nt][0] * inv0, oacc[t][nt][1] * inv0);
            *(uint32_t*)(g_ao16 + base1 + c) = pack_f16x2(oacc[t][nt][2] * inv1, oacc[t][nt][3] * inv1);
        }
    }
}

// ---------------- launch ------------------------------------------------------
extern "C" void kernel_launch(void* const* d_in, const int* in_sizes, int n_in,
                              void* d_out, int out_size)
{
    const float* x       = (const float*)d_in[0];
    const float* context = (const float*)d_in[1];
    const int*   mask    = (const int*)  d_in[2];
    const float* g_x     = (const float*)d_in[3];
    const float* null_kv = (const float*)d_in[4];
    const float* Wq      = (const float*)d_in[5];
    const float* Wkv     = (const float*)d_in[6];
    const float* Wo      = (const float*)d_in[7];
    const float* g_outp  = (const float*)d_in[8];
    float* out = (float*)d_out;
    (void)in_sizes; (void)n_in; (void)out_size;

    prep_kernel<<<10496, 128>>>(x, g_x, context, Wq, Wkv, Wo);

    cudaFuncSetAttribute(proj01_kernel, cudaFuncAttributeMaxDynamicSharedMemorySize, 2 * PBUF);
    cudaFuncSetAttribute(proj2_kernel,  cudaFuncAttributeMaxDynamicSharedMemorySize, 2 * PBUF);

    proj01_kernel<<<dim3(24, 64), 128, 2 * PBUF>>>(null_kv);

    cudaFuncSetAttribute(attn_mma_kernel, cudaFuncAttributeMaxDynamicSharedMemorySize, ATTN_SMEM);
    attn_mma_kernel<<<dim3(NQ / 128, BATCH * HEADS), 128, ATTN_SMEM>>>(mask);

    proj2_kernel<<<dim3(8, 64), 128, 2 * PBUF>>>();
    ln1_kernel<<<BATCH * NQ, 128>>>(g_outp, out);
}

// round 17
// speedup vs baseline: 2.6329x; 1.0215x over previous
#include <cuda_runtime.h>
#include <cuda_bf16.h>
#include <cuda_fp16.h>
#include <math.h>
#include <stdint.h>

// ---------------- problem constants ----------------
#define BATCH   2
#define NQ      4096
#define NCTX    4096
#define DIMC    512
#define HEADS   8
#define DH      64
#define INNER   512
#define MK      4097
#define MKP     4160
#define SQSCALE 0.35355339059327373f     // sqrt(64^-0.5)
#define QSCALE2 0.5100696616388476f      // SQSCALE * log2(e)
#define CLAMP2  14.426950408889634f      // 10 * log2(e)
#define SPIT    72                       // smem pitch (16-bit elems) = 144B

// ---------------- scratch ----------------------------------------------------
__device__ float g_pj[(size_t)BATCH * NQ * DIMC];

__device__ __half g_xn16[(size_t)BATCH * NQ * DIMC];
__device__ __half g_cx16[(size_t)BATCH * NCTX * DIMC];
__device__ __half g_ao16[(size_t)BATCH * NQ * INNER];

__device__ __half g_qh[(size_t)BATCH * HEADS * NQ * DH];    // pre-scaled by QSCALE2
__device__ __half g_kh[(size_t)BATCH * HEADS * MK * DH];    // pre-scaled by SQSCALE
__device__ __half g_vth[(size_t)BATCH * HEADS * DH * MKP];  // [bh][d][key], mask-folded

__device__ __half g_wq16[512 * 512];
__device__ __half g_wkv16[1024 * 512];
__device__ __half g_wo16[512 * 512];

// ---------------- helpers -----------------------------------------------------
__device__ __forceinline__ uint32_t pack_f16x2(float lo_elem, float hi_elem) {
    uint32_t r;
    asm("cvt.rn.f16x2.f32 %0, %1, %2;" : "=r"(r) : "f"(hi_elem), "f"(lo_elem));
    return r;
}
__device__ __forceinline__ float ex2f(float x) {
    float r;
    asm("ex2.approx.f32 %0, %1;" : "=f"(r) : "f"(x));
    return r;
}
__device__ __forceinline__ void mma16816f(float* d, const uint32_t* a, uint32_t b0, uint32_t b1) {
    asm volatile("mma.sync.aligned.m16n8k16.row.col.f32.f16.f16.f32 "
        "{%0,%1,%2,%3}, {%4,%5,%6,%7}, {%8,%9}, {%0,%1,%2,%3};"
        : "+f"(d[0]), "+f"(d[1]), "+f"(d[2]), "+f"(d[3])
        : "r"(a[0]), "r"(a[1]), "r"(a[2]), "r"(a[3]), "r"(b0), "r"(b1));
}
__device__ __forceinline__ void ldsm_x4(uint32_t* r, uint32_t addr) {
    asm volatile("ldmatrix.sync.aligned.m8n8.x4.shared.b16 {%0,%1,%2,%3}, [%4];"
        : "=r"(r[0]), "=r"(r[1]), "=r"(r[2]), "=r"(r[3]) : "r"(addr));
}
__device__ __forceinline__ void cp16(uint32_t dst, const void* src) {
    asm volatile("cp.async.cg.shared.global [%0], [%1], 16;"
        :: "r"(dst), "l"(src) : "memory");
}
__device__ __forceinline__ void cp16z(uint32_t dst, const void* src, int ok) {
    int sz = ok ? 16 : 0;
    asm volatile("cp.async.cg.shared.global [%0], [%1], 16, %2;"
        :: "r"(dst), "l"(src), "r"(sz) : "memory");
}
#define CP_COMMIT() asm volatile("cp.async.commit_group;" ::: "memory")
#define CP_WAIT0()  asm volatile("cp.async.wait_group 0;" ::: "memory")

// ---------------- fused prep: ln0 + csplit + wconv ---------------------------
__global__ void __launch_bounds__(128) prep_kernel(const float* __restrict__ x,
                                                   const float* __restrict__ g,
                                                   const float* __restrict__ context,
                                                   const float* __restrict__ Wq,
                                                   const float* __restrict__ Wkv,
                                                   const float* __restrict__ Wo)
{
    __shared__ float s[64][65];
    int bx = blockIdx.x;
    int tid = threadIdx.x;

    if (bx < 8192) {
        int row = bx;
        float4 v = reinterpret_cast<const float4*>(x + (size_t)row * DIMC)[tid];
        float sm = v.x + v.y + v.z + v.w;
        float ss = v.x * v.x + v.y * v.y + v.z * v.z + v.w * v.w;
        #pragma unroll
        for (int o = 16; o > 0; o >>= 1) {
            sm += __shfl_down_sync(0xffffffffu, sm, o);
            ss += __shfl_down_sync(0xffffffffu, ss, o);
        }
        int wid = tid >> 5, lane = tid & 31;
        float* sb = &s[0][0];
        if (lane == 0) { sb[wid] = sm; sb[4 + wid] = ss; }
        __syncthreads();
        float S  = sb[0] + sb[1] + sb[2] + sb[3];
        float SS = sb[4] + sb[5] + sb[6] + sb[7];
        float mean = S * (1.0f / DIMC);
        float var  = SS * (1.0f / DIMC) - mean * mean;
        float rstd = rsqrtf(var + 1e-5f);
        float4 gv = reinterpret_cast<const float4*>(g)[tid];
        float o0 = (v.x - mean) * rstd * gv.x;
        float o1 = (v.y - mean) * rstd * gv.y;
        float o2 = (v.z - mean) * rstd * gv.z;
        float o3 = (v.w - mean) * rstd * gv.w;
        uint2 pk;
        pk.x = pack_f16x2(o0, o1);
        pk.y = pack_f16x2(o2, o3);
        *(uint2*)(g_xn16 + (size_t)row * DIMC + tid * 4) = pk;
    } else if (bx < 10240) {
        size_t base4 = (size_t)(bx - 8192) * 512 + tid;
        #pragma unroll
        for (int j = 0; j < 4; j++) {
            size_t i4 = base4 + j * 128;
            float4 v = reinterpret_cast<const float4*>(context)[i4];
            uint2 pk;
            pk.x = pack_f16x2(v.x, v.y);
            pk.y = pack_f16x2(v.z, v.w);
            *(uint2*)(g_cx16 + i4 * 4) = pk;
        }
    } else {
        int wb = bx - 10240;
        int wx = wb & 31;
        int k0 = (wb >> 5) * 64;
        const float* W; __half* T; int N;
        if (wx < 8)       { W = Wq;  T = g_wq16;  N = 512; }
        else if (wx < 24) { W = Wkv; T = g_wkv16; N = 1024; wx -= 8; }
        else              { W = Wo;  T = g_wo16;  N = 512; wx -= 24; }
        int n0 = wx * 64;
        #pragma unroll
        for (int i = 0; i < 32; i++) {
            int idx = tid + i * 128;
            int k = idx >> 6, n = idx & 63;
            s[k][n] = W[(size_t)(k0 + k) * N + n0 + n];
        }
        __syncthreads();
        #pragma unroll
        for (int i = 0; i < 16; i++) {
            int idx = tid + i * 128;
            int n = idx >> 5, k2 = (idx & 31) << 1;
            size_t o = (size_t)(n0 + n) * 512 + k0 + k2;
            *(uint32_t*)(T + o) = pack_f16x2(s[k2][n], s[k2 + 1][n]);
        }
    }
}

// ---------------- final layernorm --------------------------------------------
__global__ void __launch_bounds__(128) ln1_kernel(const float* __restrict__ g,
                                                  float* __restrict__ outp)
{
    int row = blockIdx.x;
    int tid = threadIdx.x;
    float4 v = reinterpret_cast<const float4*>(g_pj + (size_t)row * DIMC)[tid];
    float sm = v.x + v.y + v.z + v.w;
    float ss = v.x * v.x + v.y * v.y + v.z * v.z + v.w * v.w;
    #pragma unroll
    for (int o = 16; o > 0; o >>= 1) {
        sm += __shfl_down_sync(0xffffffffu, sm, o);
        ss += __shfl_down_sync(0xffffffffu, ss, o);
    }
    __shared__ float sb[8];
    int wid = tid >> 5, lane = tid & 31;
    if (lane == 0) { sb[wid] = sm; sb[4 + wid] = ss; }
    __syncthreads();
    float S  = sb[0] + sb[1] + sb[2] + sb[3];
    float SS = sb[4] + sb[5] + sb[6] + sb[7];
    float mean = S * (1.0f / DIMC);
    float var  = SS * (1.0f / DIMC) - mean * mean;
    float rstd = rsqrtf(var + 1e-5f);
    float4 gv = reinterpret_cast<const float4*>(g)[tid];
    float4 o4;
    o4.x = (v.x - mean) * rstd * gv.x;
    o4.y = (v.y - mean) * rstd * gv.y;
    o4.z = (v.z - mean) * rstd * gv.z;
    o4.w = (v.w - mean) * rstd * gv.w;
    reinterpret_cast<float4*>(outp + (size_t)row * DIMC)[tid] = o4;
}

// ---------------- projection GEMM core ---------------------------------------
#define PBUF 27648
template <int MODE>
__device__ __forceinline__ void proj_body(const __half* __restrict__ A16,
                                          const __half* __restrict__ Wt,
                                          const int* __restrict__ mask,
                                          int row0, int col0, char* smc)
{
    uint32_t sbase = (uint32_t)__cvta_generic_to_shared(smc);
    int tid  = threadIdx.x;
    int wid  = tid >> 5;
    int lane = tid & 31;
    int g    = lane >> 2;
    int qoff = (lane & 3) << 1;

    int lm = lane >> 3, li = lane & 7;
    uint32_t aoff = (uint32_t)(((wid * 16 + (lm & 1) * 8 + li) * SPIT + (lm >> 1) * 8) * 2);
    uint32_t boff = (uint32_t)((((lm >> 1) * 8 + li) * SPIT + (lm & 1) * 8) * 2);

    auto stage = [&](int k0, int buf) {
        #pragma unroll
        for (int i = 0; i < 12; i++) {
            int idx = tid + i * 128;
            int part = idx >> 9;
            int rem = idx & 511;
            int r = rem >> 3, cc = (rem & 7) << 3;
            uint32_t dst = sbase + (uint32_t)(buf * PBUF + part * 9216 + (r * SPIT + cc) * 2);
            const __half* src;
            if (part == 0)      src = A16 + (size_t)(row0 + r) * 512 + k0 + cc;
            else if (part == 1) src = A16 + (size_t)(row0 + 64 + r) * 512 + k0 + cc;
            else                src = Wt + (size_t)(col0 + r) * 512 + k0 + cc;
            cp16(dst, src);
        }
    };

    stage(0, 0);
    CP_COMMIT();

    float oacc[2][8][4] = {};

    for (int kc = 0; kc < 8; kc++) {
        CP_WAIT0();
        __syncthreads();
        if (kc + 1 < 8) { stage((kc + 1) << 6, (kc + 1) & 1); CP_COMMIT(); }

        uint32_t uA0 = sbase + (uint32_t)((kc & 1) * PBUF);
        uint32_t uA1 = uA0 + 9216;
        uint32_t uB  = uA0 + 18432;

        uint32_t af[2][4][4];
        #pragma unroll
        for (int kt = 0; kt < 4; kt++) {
            ldsm_x4(af[0][kt], uA0 + (uint32_t)(kt * 32) + aoff);
            ldsm_x4(af[1][kt], uA1 + (uint32_t)(kt * 32) + aoff);
        }

        #pragma unroll
        for (int kt = 0; kt < 4; kt++) {
            #pragma unroll
            for (int ntp = 0; ntp < 4; ntp++) {
                uint32_t off = (uint32_t)(ntp * 16 * SPIT * 2 + kt * 32) + boff;
                uint32_t bf[4];
                ldsm_x4(bf, uB + off);
                mma16816f(oacc[0][2 * ntp],     af[0][kt], bf[0], bf[1]);
                mma16816f(oacc[0][2 * ntp + 1], af[0][kt], bf[2], bf[3]);
                mma16816f(oacc[1][2 * ntp],     af[1][kt], bf[0], bf[1]);
                mma16816f(oacc[1][2 * ntp + 1], af[1][kt], bf[2], bf[3]);
            }
        }
    }

    // V-CTA mask values (one per row-subtile/half), MODE 1 + V columns only
    float vm[2][2] = {{1.0f, 1.0f}, {1.0f, 1.0f}};
    if (MODE == 1 && col0 >= 512) {
        #pragma unroll
        for (int t = 0; t < 2; t++)
            #pragma unroll
            for (int half = 0; half < 2; half++) {
                int row = row0 + t * 64 + wid * 16 + g + half * 8;
                int b = row >> 12, mr = row & 4095;
                vm[t][half] = (mask[b * NCTX + mr] != 0) ? 1.0f : 0.0f;
            }
    }

    #pragma unroll
    for (int t = 0; t < 2; t++) {
        #pragma unroll
        for (int nt = 0; nt < 8; nt++) {
            #pragma unroll
            for (int half = 0; half < 2; half++) {
                int row = row0 + t * 64 + wid * 16 + g + half * 8;
                float v0 = oacc[t][nt][half * 2 + 0];
                float v1 = oacc[t][nt][half * 2 + 1];
                int c = col0 + nt * 8 + qoff;
                if (MODE == 0) {
                    int b = row >> 12, n = row & 4095;
                    int h = c >> 6, dd = c & 63;
                    size_t idx = (((size_t)(b * HEADS + h)) * NQ + n) * DH + dd;
                    *(uint32_t*)(g_qh + idx) = pack_f16x2(v0 * QSCALE2, v1 * QSCALE2);
                } else if (MODE == 1) {
                    int b = row >> 12, mr = row & 4095;
                    if (c < 512) {
                        int h = c >> 6, dd = c & 63;
                        size_t idx = (((size_t)(b * HEADS + h)) * MK + mr + 1) * DH + dd;
                        *(uint32_t*)(g_kh + idx) = pack_f16x2(v0 * SQSCALE, v1 * SQSCALE);
                    } else {
                        int c2 = c - 512;
                        int h = c2 >> 6, dd = c2 & 63;
                        size_t idx = (((size_t)(b * HEADS + h)) * DH + dd) * MKP + (mr + 1);
                        float m = vm[t][half];
                        g_vth[idx]       = __float2half(v0 * m);
                        g_vth[idx + MKP] = __float2half(v1 * m);
                    }
                } else {
                    *(float2*)(g_pj + (size_t)row * 512 + c) = make_float2(v0, v1);
                }
            }
        }
    }
}

__global__ void __launch_bounds__(128) proj01_kernel(const float* __restrict__ null_kv,
                                                     const int* __restrict__ mask)
{
    extern __shared__ char smc[];
    int bx = blockIdx.x;
    int row0 = blockIdx.y * 128;

    if (bx == 0 && blockIdx.y == 0) {
        int tid = threadIdx.x;
        int d = tid & 63;
        if (tid < 64) {
            __half kv = __float2half(null_kv[d] * SQSCALE);
            #pragma unroll
            for (int bh = 0; bh < 16; bh++)
                g_kh[(size_t)bh * MK * DH + d] = kv;
        } else {
            __half vv = __float2half(null_kv[DH + d]);
            #pragma unroll
            for (int bh = 0; bh < 16; bh++)
                g_vth[((size_t)bh * DH + d) * MKP + 0] = vv;
        }
    }

    if (bx < 8) proj_body<0>(g_xn16, g_wq16, mask, row0, bx * 64, smc);
    else        proj_body<1>(g_cx16, g_wkv16, mask, row0, (bx - 8) * 64, smc);
}

__global__ void __launch_bounds__(128) proj2_kernel()
{
    extern __shared__ char smc[];
    proj_body<2>(g_ao16, g_wo16, nullptr, blockIdx.y * 128, blockIdx.x * 64, smc);
}

// ---------------- FA2 attention: mask-free softmax, mask-B row sums -----------
#define BUFSZ   18432
#define OFF_BM  36864
#define ATTN_SMEM 37408
#define NCH     65

__global__ void __launch_bounds__(128) attn_mma_kernel(const int* __restrict__ mask)
{
    extern __shared__ char smc[];
    const int tid  = threadIdx.x;
    const int wid  = tid >> 5;
    const int lane = tid & 31;
    const int g    = lane >> 2;
    const int qoff = (lane & 3) << 1;
    const int bh = blockIdx.y;
    const int b = bh >> 3, h = bh & 7;
    const int n0 = blockIdx.x << 7;

    uint32_t sbase = (uint32_t)__cvta_generic_to_shared(smc);
    uint32_t* bmap = (uint32_t*)(smc + OFF_BM);

    for (int w = tid; w < 130; w += 128) {
        uint32_t wv = 0;
        int jb = w * 32;
        #pragma unroll 8
        for (int i = 0; i < 32; i++) {
            int j = jb + i;
            int ok = (j == 0) ? 1 : ((j < MK) ? (mask[b * NCTX + j - 1] != 0) : 0);
            wv |= (uint32_t)ok << i;
        }
        bmap[w] = wv;
    }

    uint32_t qf[2][4][4];
    #pragma unroll
    for (int t = 0; t < 2; t++) {
        const __half* q0 = g_qh + ((size_t)bh * NQ + n0 + t * 64 + wid * 16 + g) * DH;
        #pragma unroll
        for (int kt = 0; kt < 4; kt++) {
            int d0 = kt * 16 + qoff;
            qf[t][kt][0] = *(const uint32_t*)(q0 + d0);
            qf[t][kt][1] = *(const uint32_t*)(q0 + 8 * DH + d0);
            qf[t][kt][2] = *(const uint32_t*)(q0 + d0 + 8);
            qf[t][kt][3] = *(const uint32_t*)(q0 + 8 * DH + d0 + 8);
        }
    }

    const int lm = lane >> 3, li = lane & 7;
    const uint32_t boff = (uint32_t)((((lm >> 1) * 8 + li) * SPIT + (lm & 1) * 8) * 2);

    auto stage = [&](int c0s, int buf) {
        #pragma unroll
        for (int i = 0; i < 8; i++) {
            int idx = tid + i * 128;
            int part = idx >> 9;
            int rem = idx & 511;
            int r = rem >> 3, cc = (rem & 7) << 3;
            uint32_t dst = sbase + (uint32_t)(buf * BUFSZ + part * 9216 + (r * SPIT + cc) * 2);
            if (part == 0) {
                int j = c0s + r;
                const __half* ks = g_kh + ((size_t)bh * MK + min(j, MK - 1)) * DH + cc;
                cp16z(dst, ks, j < MK);
            } else {
                const __half* vs = g_vth + ((size_t)bh * DH + r) * MKP + c0s + cc;
                cp16(dst, vs);
            }
        }
    };

    stage(0, 0);
    CP_COMMIT();

    float oacc[2][8][4] = {};
    float ssum[2][4] = {};

    for (int ch = 0; ch < NCH; ch++) {
        int c0 = ch << 6;
        CP_WAIT0();
        __syncthreads();
        if (ch + 1 < NCH) { stage((ch + 1) << 6, (ch + 1) & 1); CP_COMMIT(); }

        uint32_t uK = sbase + (uint32_t)((ch & 1) * BUFSZ);
        uint32_t uV = uK + 9216;

        // mask B-fragments for this chunk (k = (lane&3)*2 + {0,1}, +8 for b1)
        uint32_t mb[4][2];
        #pragma unroll
        for (int kt = 0; kt < 4; kt++) {
            int jb = c0 + kt * 16 + qoff;
            uint32_t wb = bmap[jb >> 5];
            int bi = jb & 31;
            uint32_t m0 = (wb >> bi) & 1u;
            uint32_t m1 = (wb >> (bi + 1)) & 1u;
            uint32_t m8 = (wb >> (bi + 8)) & 1u;
            uint32_t m9 = (wb >> (bi + 9)) & 1u;
            mb[kt][0] = m0 * 0x3C00u | ((m1 * 0x3C00u) << 16);
            mb[kt][1] = m8 * 0x3C00u | ((m9 * 0x3C00u) << 16);
        }

        #pragma unroll
        for (int t = 0; t < 2; t++) {
            float sacc[8][4] = {};
            #pragma unroll
            for (int kt = 0; kt < 4; kt++) {
                #pragma unroll
                for (int ntp = 0; ntp < 4; ntp++) {
                    uint32_t off = (uint32_t)(ntp * 16 * SPIT * 2 + kt * 32) + boff;
                    uint32_t bf[4];
                    ldsm_x4(bf, uK + off);
                    mma16816f(sacc[2 * ntp],     qf[t][kt], bf[0], bf[1]);
                    mma16816f(sacc[2 * ntp + 1], qf[t][kt], bf[2], bf[3]);
                }
            }

            // softmax: clamp -> ex2 -> pack (mask handled by V-zero + mask-B sums)
            uint32_t pf[4][4];
            #pragma unroll
            for (int nt = 0; nt < 8; nt++) {
                float p0 = ex2f(fminf(sacc[nt][0], CLAMP2));
                float p1 = ex2f(fminf(sacc[nt][1], CLAMP2));
                float p2 = ex2f(fminf(sacc[nt][2], CLAMP2));
                float p3 = ex2f(fminf(sacc[nt][3], CLAMP2));
                int kt = nt >> 1, hf = (nt & 1) << 1;
                pf[kt][hf + 0] = pack_f16x2(p0, p1);
                pf[kt][hf + 1] = pack_f16x2(p2, p3);
            }

            // masked row sums via MMA (accumulates across chunks)
            #pragma unroll
            for (int kt = 0; kt < 4; kt++)
                mma16816f(ssum[t], pf[kt], mb[kt][0], mb[kt][1]);

            #pragma unroll
            for (int kt = 0; kt < 4; kt++) {
                #pragma unroll
                for (int ntp = 0; ntp < 4; ntp++) {
                    uint32_t off = (uint32_t)(ntp * 16 * SPIT * 2 + kt * 32) + boff;
                    uint32_t vf[4];
                    ldsm_x4(vf, uV + off);
                    mma16816f(oacc[t][2 * ntp],     pf[kt], vf[0], vf[1]);
                    mma16816f(oacc[t][2 * ntp + 1], pf[kt], vf[2], vf[3]);
                }
            }
        }
    }

    #pragma unroll
    for (int t = 0; t < 2; t++) {
        float inv0 = 1.0f / ssum[t][0];
        float inv1 = 1.0f / ssum[t][2];

        size_t base0 = ((size_t)(b * NQ) + n0 + t * 64 + wid * 16 + g) * INNER + h * DH;
        size_t base1 = base0 + 8 * INNER;
        #pragma unroll
        for (int nt = 0; nt < 8; nt++) {
            int c = nt * 8 + qoff;
            *(uint32_t*)(g_ao16 + base0 + c) = pack_f16x2(oacc[t][nt][0] * inv0, oacc[t][nt][1] * inv0);
            *(uint32_t*)(g_ao16 + base1 + c) = pack_f16x2(oacc[t][nt][2] * inv1, oacc[t][nt][3] * inv1);
        }
    }
}

// ---------------- launch ------------------------------------------------------
extern "C" void kernel_launch(void* const* d_in, const int* in_sizes, int n_in,
                              void* d_out, int out_size)
{
    const float* x       = (const float*)d_in[0];
    const float* context = (const float*)d_in[1];
    const int*   mask    = (const int*)  d_in[2];
    const float* g_x     = (const float*)d_in[3];
    const float* null_kv = (const float*)d_in[4];
    const float* Wq      = (const float*)d_in[5];
    const float* Wkv     = (const float*)d_in[6];
    const float* Wo      = (const float*)d_in[7];
    const float* g_outp  = (const float*)d_in[8];
    float* out = (float*)d_out;
    (void)in_sizes; (void)n_in; (void)out_size;

    prep_kernel<<<10496, 128>>>(x, g_x, context, Wq, Wkv, Wo);

    cudaFuncSetAttribute(proj01_kernel, cudaFuncAttributeMaxDynamicSharedMemorySize, 2 * PBUF);
    cudaFuncSetAttribute(proj2_kernel,  cudaFuncAttributeMaxDynamicSharedMemorySize, 2 * PBUF);

    proj01_kernel<<<dim3(24, 64), 128, 2 * PBUF>>>(null_kv, mask);

    cudaFuncSetAttribute(attn_mma_kernel, cudaFuncAttributeMaxDynamicSharedMemorySize, ATTN_SMEM);
    attn_mma_kernel<<<dim3(NQ / 128, BATCH * HEADS), 128, ATTN_SMEM>>>(mask);

    proj2_kernel<<<dim3(8, 64), 128, 2 * PBUF>>>();
    ln1_kernel<<<BATCH * NQ, 128>>>(g_outp, out);
}